// round 2
// baseline (speedup 1.0000x reference)
#include <cuda_runtime.h>
#include <cuda_bf16.h>
#include <math.h>

#define BB      8
#define NPTS    4096
#define NS      1024
#define NP      32
#define DM      128
#define NH      4
#define DH      32
#define MLPH    256
#define GK      130
#define FFH     512
#define LN_EPS  1e-5f
#define SQROWS  (BB*NS)
#define GFROWS  (BB*NPTS)

__device__ float g_gfeat[GFROWS * DM];
__device__ float g_cent [BB * NS * 2];
__device__ int   g_knn  [BB * NS * NP];
__device__ int   g_kcnt [BB * NS];
__device__ float g_local[SQROWS * DM];
__device__ float g_x    [SQROWS * DM];
__device__ float g_x2   [SQROWS * DM];
__device__ float g_q    [SQROWS * DM];
__device__ float g_att  [SQROWS * DM];
__device__ float g_tmp  [SQROWS * DM];
__device__ float g_kv   [GFROWS * 256];
__device__ float g_ff   [SQROWS * FFH];

__device__ __forceinline__ float gelu_exact(float x) {
    return 0.5f * x * (1.0f + erff(x * 0.70710678118654752440f));
}

// ---------- 1) fourier features + 26->128 projection ----------
__global__ __launch_bounds__(128) void gfeat_kernel(
    const float* __restrict__ pts, const float* __restrict__ fw, const float* __restrict__ fb)
{
    __shared__ float fsh[128 * 26];
    const int t = threadIdx.x;
    const int base = blockIdx.x * 128;
    float wreg[26];
    #pragma unroll
    for (int j = 0; j < 26; j++) wreg[j] = fw[t * 26 + j];

    const float FREQ[6] = {3.14159265358979323846f, 6.28318530717958647693f,
        12.5663706143591729539f, 25.1327412287183459077f,
        50.2654824574366918154f, 100.530964914873383631f};
    {
        float x = pts[(size_t)(base + t) * 2 + 0];
        float y = pts[(size_t)(base + t) * 2 + 1];
        fsh[t * 26 + 0] = x; fsh[t * 26 + 1] = y;
        #pragma unroll
        for (int k = 0; k < 6; k++) {
            float sx, cx, sy, cy;
            sincosf(FREQ[k] * x, &sx, &cx);
            sincosf(FREQ[k] * y, &sy, &cy);
            fsh[t*26 + 2 + 4*k + 0] = sx; fsh[t*26 + 2 + 4*k + 1] = sy;
            fsh[t*26 + 2 + 4*k + 2] = cx; fsh[t*26 + 2 + 4*k + 3] = cy;
        }
    }
    float bb = fb[t];
    __syncthreads();
    for (int p = 0; p < 128; p++) {
        float acc = bb;
        #pragma unroll
        for (int j = 0; j < 26; j++) acc += fsh[p * 26 + j] * wreg[j];
        g_gfeat[(size_t)(base + p) * DM + t] = acc;
    }
}

// ---------- 2) farthest point sampling ----------
__global__ __launch_bounds__(512) void fps_kernel(const float* __restrict__ pts)
{
    const int b = blockIdx.x, tid = threadIdx.x;
    const int lane = tid & 31, wid = tid >> 5;
    float px[8], py[8], dd[8];
    #pragma unroll
    for (int j = 0; j < 8; j++) {
        int p = tid + j * 512;
        px[j] = pts[((size_t)b * NPTS + p) * 2 + 0];
        py[j] = pts[((size_t)b * NPTS + p) * 2 + 1];
        dd[j] = INFINITY;
    }
    __shared__ float rv[16]; __shared__ int ri[16];
    __shared__ float rx[16], ry[16];
    __shared__ float sbx, sby;
    float lastx = pts[(size_t)b * NPTS * 2 + 0];
    float lasty = pts[(size_t)b * NPTS * 2 + 1];
    if (tid == 0) {
        g_cent[(size_t)b * NS * 2 + 0] = lastx;
        g_cent[(size_t)b * NS * 2 + 1] = lasty;
    }
    for (int it = 1; it < NS; it++) {
        float bv = -1.0f; int bi = 0x7fffffff; float bx = 0.f, by = 0.f;
        #pragma unroll
        for (int j = 0; j < 8; j++) {
            float dx = __fsub_rn(px[j], lastx);
            float dy = __fsub_rn(py[j], lasty);
            float d2 = __fadd_rn(__fmul_rn(dx, dx), __fmul_rn(dy, dy));
            dd[j] = fminf(dd[j], d2);
            if (dd[j] > bv) { bv = dd[j]; bi = tid + j * 512; bx = px[j]; by = py[j]; }
        }
        #pragma unroll
        for (int off = 16; off > 0; off >>= 1) {
            float ov = __shfl_down_sync(0xffffffffu, bv, off);
            int   oi = __shfl_down_sync(0xffffffffu, bi, off);
            float ox = __shfl_down_sync(0xffffffffu, bx, off);
            float oy = __shfl_down_sync(0xffffffffu, by, off);
            if (ov > bv || (ov == bv && oi < bi)) { bv = ov; bi = oi; bx = ox; by = oy; }
        }
        if (lane == 0) { rv[wid] = bv; ri[wid] = bi; rx[wid] = bx; ry[wid] = by; }
        __syncthreads();
        if (tid < 32) {
            if (tid < 16) { bv = rv[tid]; bi = ri[tid]; bx = rx[tid]; by = ry[tid]; }
            else          { bv = -1.0f; bi = 0x7fffffff; bx = 0.f; by = 0.f; }
            #pragma unroll
            for (int off = 8; off > 0; off >>= 1) {
                float ov = __shfl_down_sync(0xffffffffu, bv, off);
                int   oi = __shfl_down_sync(0xffffffffu, bi, off);
                float ox = __shfl_down_sync(0xffffffffu, bx, off);
                float oy = __shfl_down_sync(0xffffffffu, by, off);
                if (ov > bv || (ov == bv && oi < bi)) { bv = ov; bi = oi; bx = ox; by = oy; }
            }
            if (tid == 0) {
                g_cent[((size_t)b * NS + it) * 2 + 0] = bx;
                g_cent[((size_t)b * NS + it) * 2 + 1] = by;
                sbx = bx; sby = by;
            }
        }
        __syncthreads();
        lastx = sbx; lasty = sby;
    }
}

// ---------- 3) ball query (warp per centroid) ----------
__global__ __launch_bounds__(256) void bq_kernel(const float* __restrict__ pts)
{
    __shared__ int sknn[8][NP];
    const int gwid = (blockIdx.x * blockDim.x + threadIdx.x) >> 5;
    const int lane = threadIdx.x & 31, wl = threadIdx.x >> 5;
    if (gwid >= BB * NS) return;
    const int b = gwid >> 10;
    const float cx = g_cent[gwid * 2 + 0];
    const float cy = g_cent[gwid * 2 + 1];
    const float R2 = 0.01f;
    int cnt = 0;
    for (int c = 0; c < NPTS / 32 && cnt < NP; c++) {
        int p = c * 32 + lane;
        float dx = __fsub_rn(cx, pts[((size_t)b * NPTS + p) * 2 + 0]);
        float dy = __fsub_rn(cy, pts[((size_t)b * NPTS + p) * 2 + 1]);
        float d2 = __fadd_rn(__fmul_rn(dx, dx), __fmul_rn(dy, dy));
        bool in = d2 < R2;
        unsigned m = __ballot_sync(0xffffffffu, in);
        int before = __popc(m & ((1u << lane) - 1u));
        if (in && cnt + before < NP) sknn[wl][cnt + before] = p;
        cnt += __popc(m);
    }
    __syncwarp();
    int cc = min(cnt, NP);
    g_knn[gwid * NP + lane] = (lane < cc) ? sknn[wl][lane] : sknn[wl][0];
    if (lane == 0) g_kcnt[gwid] = cc;
}

// ---------- 4) grouped MLP (block per group) ----------
__device__ __forceinline__ void ln_gelu_256(float* h, const float* __restrict__ g,
                                            const float* __restrict__ be, int tid)
{
    const int w = tid >> 5, lane = tid & 31;
    for (int rr = 0; rr < 8; rr++) {
        int r = w * 8 + rr;
        float x[8];
        #pragma unroll
        for (int i = 0; i < 8; i++) x[i] = h[r * 256 + lane + i * 32];
        float s = 0.f;
        #pragma unroll
        for (int i = 0; i < 8; i++) s += x[i];
        #pragma unroll
        for (int o = 16; o > 0; o >>= 1) s += __shfl_xor_sync(0xffffffffu, s, o);
        float mu = s * (1.0f / 256.0f);
        float q = 0.f;
        #pragma unroll
        for (int i = 0; i < 8; i++) { float d = x[i] - mu; q += d * d; }
        #pragma unroll
        for (int o = 16; o > 0; o >>= 1) q += __shfl_xor_sync(0xffffffffu, q, o);
        float inv = rsqrtf(q * (1.0f / 256.0f) + LN_EPS);
        #pragma unroll
        for (int i = 0; i < 8; i++) {
            int c = lane + i * 32;
            h[r * 256 + c] = gelu_exact((x[i] - mu) * inv * g[c] + be[c]);
        }
    }
}

__global__ __launch_bounds__(128) void gmlp_kernel(
    const float* __restrict__ pts,
    const float* __restrict__ w1, const float* __restrict__ b1,
    const float* __restrict__ lg1, const float* __restrict__ lb1,
    const float* __restrict__ w2, const float* __restrict__ b2,
    const float* __restrict__ lg2, const float* __restrict__ lb2,
    const float* __restrict__ w3, const float* __restrict__ b3)
{
    __shared__ float sm[32 * 256];     // gin (32x130) aliases h (32x256)
    float* gin = sm;
    float* h = sm;
    __shared__ int idxs[NP];
    __shared__ int scnt;
    const int gid = blockIdx.x;
    const int b = gid >> 10;
    const int tid = threadIdx.x;

    if (tid < NP) idxs[tid] = g_knn[gid * NP + tid];
    if (tid == 0) scnt = g_kcnt[gid];
    __syncthreads();
    for (int r = 0; r < NP; r++)
        gin[r * GK + tid] = g_gfeat[((size_t)b * NPTS + idxs[r]) * DM + tid];
    if (tid < 2) {
        float cc = g_cent[gid * 2 + tid];
        for (int r = 0; r < NP; r++)
            gin[r * GK + 128 + tid] = __fsub_rn(pts[((size_t)b * NPTS + idxs[r]) * 2 + tid], cc);
    }
    __syncthreads();

    float a0[32], a1[32];
    // layer 1: 130 -> 256
    #pragma unroll
    for (int r = 0; r < 32; r++) { a0[r] = 0.f; a1[r] = 0.f; }
    {
        const float* wr0 = w1 + (size_t)tid * GK;
        const float* wr1 = w1 + (size_t)(tid + 128) * GK;
        for (int k = 0; k < GK; k++) {
            float wa = __ldg(wr0 + k), wb = __ldg(wr1 + k);
            #pragma unroll
            for (int r = 0; r < 32; r++) {
                float gv = gin[r * GK + k];
                a0[r] += gv * wa; a1[r] += gv * wb;
            }
        }
    }
    __syncthreads();  // gin dead; h aliases it
    {
        float bb0 = b1[tid], bb1 = b1[tid + 128];
        #pragma unroll
        for (int r = 0; r < 32; r++) {
            h[r * 256 + tid] = a0[r] + bb0;
            h[r * 256 + tid + 128] = a1[r] + bb1;
        }
    }
    __syncthreads();
    ln_gelu_256(h, lg1, lb1, tid);
    __syncthreads();

    // layer 2: 256 -> 256
    #pragma unroll
    for (int r = 0; r < 32; r++) { a0[r] = 0.f; a1[r] = 0.f; }
    {
        const float* wr0 = w2 + (size_t)tid * 256;
        const float* wr1 = w2 + (size_t)(tid + 128) * 256;
        for (int k = 0; k < 256; k++) {
            float wa = __ldg(wr0 + k), wb = __ldg(wr1 + k);
            #pragma unroll
            for (int r = 0; r < 32; r++) {
                float gv = h[r * 256 + k];
                a0[r] += gv * wa; a1[r] += gv * wb;
            }
        }
    }
    __syncthreads();
    {
        float bb0 = b2[tid], bb1 = b2[tid + 128];
        #pragma unroll
        for (int r = 0; r < 32; r++) {
            h[r * 256 + tid] = a0[r] + bb0;
            h[r * 256 + tid + 128] = a1[r] + bb1;
        }
    }
    __syncthreads();
    ln_gelu_256(h, lg2, lb2, tid);
    __syncthreads();

    // layer 3: 256 -> 128, masked max over rows
    #pragma unroll
    for (int r = 0; r < 32; r++) a0[r] = 0.f;
    {
        const float* wr = w3 + (size_t)tid * 256;
        for (int k = 0; k < 256; k++) {
            float wv = __ldg(wr + k);
            #pragma unroll
            for (int r = 0; r < 32; r++) a0[r] += h[r * 256 + k] * wv;
        }
    }
    {
        float bb = b3[tid];
        int cnt = scnt;
        float mx = a0[0] + bb;
        #pragma unroll
        for (int r = 1; r < 32; r++) if (r < cnt) mx = fmaxf(mx, a0[r] + bb);
        g_local[(size_t)gid * DM + tid] = mx;
    }
}

// ---------- 5) tiled SGEMM: C[M,Nc] = A[M,K] @ W[Nc,K]^T + bias ----------
template<int EPI>  // 0 none, 1 gelu
__global__ __launch_bounds__(256) void gemm_kernel(
    const float* __restrict__ A, const float* __restrict__ W,
    const float* __restrict__ bias, float* __restrict__ C,
    int M, int Nc, int K)
{
    __shared__ float As[64 * 17];
    __shared__ float Ws[16 * 68];
    const int tid = threadIdx.x;
    const int tx = tid & 15, ty = tid >> 4;
    const int m0 = blockIdx.y * 64, n0 = blockIdx.x * 64;
    const int lk = tid & 15, lm = tid >> 4;
    float acc[4][4];
    #pragma unroll
    for (int r = 0; r < 4; r++)
        #pragma unroll
        for (int c = 0; c < 4; c++) acc[r][c] = 0.f;

    for (int k0 = 0; k0 < K; k0 += 16) {
        #pragma unroll
        for (int i = 0; i < 4; i++) {
            int m = lm + i * 16;
            As[m * 17 + lk] = A[(size_t)(m0 + m) * K + k0 + lk];
            Ws[lk * 68 + m] = W[(size_t)(n0 + m) * K + k0 + lk];
        }
        __syncthreads();
        #pragma unroll
        for (int k = 0; k < 16; k++) {
            float av[4], wv[4];
            #pragma unroll
            for (int r = 0; r < 4; r++) av[r] = As[(ty * 4 + r) * 17 + k];
            #pragma unroll
            for (int c = 0; c < 4; c++) wv[c] = Ws[k * 68 + tx * 4 + c];
            #pragma unroll
            for (int r = 0; r < 4; r++)
                #pragma unroll
                for (int c = 0; c < 4; c++) acc[r][c] += av[r] * wv[c];
        }
        __syncthreads();
    }
    #pragma unroll
    for (int c = 0; c < 4; c++) {
        int n = n0 + tx * 4 + c;
        float bn = bias[n];
        #pragma unroll
        for (int r = 0; r < 4; r++) {
            float v = acc[r][c] + bn;
            if (EPI == 1) v = gelu_exact(v);
            C[(size_t)(m0 + ty * 4 + r) * Nc + n] = v;
        }
    }
}

// ---------- 6) fused flash attention (fp32) ----------
__global__ __launch_bounds__(128) void flash_kernel(
    const float* __restrict__ Q, const float* __restrict__ KV,
    float* __restrict__ Out, int Sq, int Skv)
{
    __shared__ float Qs[16 * 33];
    __shared__ float Ks[64 * 33];
    __shared__ float Vs[64 * 33];
    __shared__ float Ps[16 * 65];
    const int b = blockIdx.z, h = blockIdx.y, q0 = blockIdx.x * 16;
    const int tid = threadIdx.x;
    const int qr = tid >> 3, dg = tid & 7;
    const int d0 = dg * 4, kb = dg * 8;
    const float scale = 0.17677669529663687f;

    #pragma unroll
    for (int i = 0; i < 4; i++) {
        int e = tid * 4 + i;
        int q = e >> 5, d = e & 31;
        Qs[q * 33 + d] = Q[((size_t)(b * Sq + q0 + q)) * DM + h * DH + d];
    }
    float O[4] = {0.f, 0.f, 0.f, 0.f};
    float mreg = -INFINITY, lreg = 0.f;

    for (int kv0 = 0; kv0 < Skv; kv0 += 64) {
        #pragma unroll
        for (int i = 0; i < 16; i++) {
            int idx = tid + i * 128;
            int r = idx >> 5, d = idx & 31;
            size_t grow = (size_t)(b * Skv + kv0 + r) * 256;
            Ks[r * 33 + d] = KV[grow + h * DH + d];
            Vs[r * 33 + d] = KV[grow + 128 + h * DH + d];
        }
        __syncthreads();
        float s[8];
        #pragma unroll
        for (int j = 0; j < 8; j++) s[j] = 0.f;
        #pragma unroll
        for (int d = 0; d < 32; d++) {
            float qv = Qs[qr * 33 + d];
            #pragma unroll
            for (int j = 0; j < 8; j++) s[j] += Ks[(kb + j) * 33 + d] * qv;
        }
        float rmax = -INFINITY;
        #pragma unroll
        for (int j = 0; j < 8; j++) { s[j] *= scale; rmax = fmaxf(rmax, s[j]); }
        #pragma unroll
        for (int o = 1; o < 8; o <<= 1) rmax = fmaxf(rmax, __shfl_xor_sync(0xffffffffu, rmax, o));
        float mnew = fmaxf(mreg, rmax);
        float corr = expf(mreg - mnew);
        float psum = 0.f;
        #pragma unroll
        for (int j = 0; j < 8; j++) {
            float p = expf(s[j] - mnew);
            Ps[qr * 65 + kb + j] = p;
            psum += p;
        }
        #pragma unroll
        for (int o = 1; o < 8; o <<= 1) psum += __shfl_xor_sync(0xffffffffu, psum, o);
        lreg = lreg * corr + psum;
        mreg = mnew;
        #pragma unroll
        for (int c = 0; c < 4; c++) O[c] *= corr;
        __syncthreads();
        for (int k = 0; k < 64; k++) {
            float pv = Ps[qr * 65 + k];
            #pragma unroll
            for (int c = 0; c < 4; c++) O[c] += pv * Vs[k * 33 + d0 + c];
        }
        __syncthreads();
    }
    float inv = 1.0f / lreg;
    #pragma unroll
    for (int c = 0; c < 4; c++)
        Out[((size_t)(b * Sq + q0 + qr)) * DM + h * DH + d0 + c] = O[c] * inv;
}

// ---------- 7) residual add + layernorm (width 128) ----------
__global__ __launch_bounds__(128) void ln_res_kernel(
    float* __restrict__ out, const float* __restrict__ a, const float* __restrict__ res,
    const float* __restrict__ g, const float* __restrict__ be)
{
    __shared__ float sh1[4], sh2[4];
    const int row = blockIdx.x, t = threadIdx.x;
    const int w = t >> 5, lane = t & 31;
    float x = a[(size_t)row * DM + t] + res[(size_t)row * DM + t];
    float s = x;
    #pragma unroll
    for (int o = 16; o > 0; o >>= 1) s += __shfl_xor_sync(0xffffffffu, s, o);
    if (lane == 0) sh1[w] = s;
    __syncthreads();
    float mu = (sh1[0] + sh1[1] + sh1[2] + sh1[3]) * (1.0f / 128.0f);
    float d = x - mu;
    float q = d * d;
    #pragma unroll
    for (int o = 16; o > 0; o >>= 1) q += __shfl_xor_sync(0xffffffffu, q, o);
    if (lane == 0) sh2[w] = q;
    __syncthreads();
    float var = (sh2[0] + sh2[1] + sh2[2] + sh2[3]) * (1.0f / 128.0f);
    out[(size_t)row * DM + t] = d * rsqrtf(var + LN_EPS) * g[t] + be[t];
}

// ---------- host ----------
extern "C" void kernel_launch(void* const* d_in, const int* in_sizes, int n_in,
                              void* d_out, int out_size)
{
    (void)in_sizes; (void)n_in; (void)out_size;
    const float* pts     = (const float*)d_in[0];
    const float* feat_w  = (const float*)d_in[2];
    const float* feat_b  = (const float*)d_in[3];
    const float* mlp_w1  = (const float*)d_in[4];
    const float* mlp_b1  = (const float*)d_in[5];
    const float* mlp_g1  = (const float*)d_in[6];
    const float* mlp_be1 = (const float*)d_in[7];
    const float* mlp_w2  = (const float*)d_in[8];
    const float* mlp_b2  = (const float*)d_in[9];
    const float* mlp_g2  = (const float*)d_in[10];
    const float* mlp_be2 = (const float*)d_in[11];
    const float* mlp_w3  = (const float*)d_in[12];
    const float* mlp_b3  = (const float*)d_in[13];
    const float* blk_in_w = (const float*)d_in[14];
    const float* blk_in_b = (const float*)d_in[15];
    const float* blk_ow   = (const float*)d_in[16];
    const float* blk_ob   = (const float*)d_in[17];
    const float* blk_g1   = (const float*)d_in[18];
    const float* blk_be1  = (const float*)d_in[19];
    const float* blk_g2   = (const float*)d_in[20];
    const float* blk_be2  = (const float*)d_in[21];
    const float* blk_f1w  = (const float*)d_in[22];
    const float* blk_f1b  = (const float*)d_in[23];
    const float* blk_f2w  = (const float*)d_in[24];
    const float* blk_f2b  = (const float*)d_in[25];
    const float* k_w = (const float*)d_in[26];
    const float* k_b = (const float*)d_in[27];
    const float* v_w = (const float*)d_in[28];
    const float* v_b = (const float*)d_in[29];
    float* out = (float*)d_out;

    float *gfeatp, *centp, *localp, *xp, *x2p, *qp, *attp, *tmpp, *kvp, *ffp;
    cudaGetSymbolAddress((void**)&gfeatp, g_gfeat);
    cudaGetSymbolAddress((void**)&centp,  g_cent);
    cudaGetSymbolAddress((void**)&localp, g_local);
    cudaGetSymbolAddress((void**)&xp,     g_x);
    cudaGetSymbolAddress((void**)&x2p,    g_x2);
    cudaGetSymbolAddress((void**)&qp,     g_q);
    cudaGetSymbolAddress((void**)&attp,   g_att);
    cudaGetSymbolAddress((void**)&tmpp,   g_tmp);
    cudaGetSymbolAddress((void**)&kvp,    g_kv);
    cudaGetSymbolAddress((void**)&ffp,    g_ff);

    gfeat_kernel<<<GFROWS / 128, 128>>>(pts, feat_w, feat_b);
    fps_kernel<<<BB, 512>>>(pts);
    bq_kernel<<<(BB * NS) / 8, 256>>>(pts);
    gmlp_kernel<<<BB * NS, 128>>>(pts, mlp_w1, mlp_b1, mlp_g1, mlp_be1,
                                  mlp_w2, mlp_b2, mlp_g2, mlp_be2, mlp_w3, mlp_b3);

    for (int i = 0; i < 4; i++) {
        const float* xcur = (i == 0) ? localp : xp;
        const float* kvsrc = (i < 2) ? gfeatp : xcur;
        int Skv = (i < 2) ? NPTS : NS;
        int Mkv = BB * Skv;
        const float* wq = blk_in_w + (size_t)i * 384 * 128;
        const float* bq = blk_in_b + (size_t)i * 384;

        gemm_kernel<0><<<dim3(2, SQROWS / 64), 256>>>(xcur, wq, bq, qp, SQROWS, 128, 128);
        gemm_kernel<0><<<dim3(4, Mkv / 64), 256>>>(kvsrc, wq + 128 * 128, bq + 128, kvp, Mkv, 256, 128);
        flash_kernel<<<dim3(NS / 16, NH, BB), 128>>>(qp, kvp, attp, NS, Skv);
        gemm_kernel<0><<<dim3(2, SQROWS / 64), 256>>>(attp, blk_ow + (size_t)i * 128 * 128,
                                                      blk_ob + (size_t)i * 128, tmpp, SQROWS, 128, 128);
        ln_res_kernel<<<SQROWS, 128>>>(x2p, tmpp, xcur, blk_g1 + (size_t)i * 128, blk_be1 + (size_t)i * 128);
        gemm_kernel<1><<<dim3(8, SQROWS / 64), 256>>>(x2p, blk_f1w + (size_t)i * 512 * 128,
                                                      blk_f1b + (size_t)i * 512, ffp, SQROWS, 512, 128);
        gemm_kernel<0><<<dim3(2, SQROWS / 64), 256>>>(ffp, blk_f2w + (size_t)i * 128 * 512,
                                                      blk_f2b + (size_t)i * 128, tmpp, SQROWS, 128, 512);
        ln_res_kernel<<<SQROWS, 128>>>(xp, tmpp, x2p, blk_g2 + (size_t)i * 128, blk_be2 + (size_t)i * 128);
    }

    gemm_kernel<0><<<dim3(2, SQROWS / 64), 256>>>(xp, k_w, k_b, out, SQROWS, 128, 128);
    gemm_kernel<0><<<dim3(2, SQROWS / 64), 256>>>(xp, v_w, v_b, out + (size_t)SQROWS * 128, SQROWS, 128, 128);
}

// round 3
// speedup vs baseline: 1.4455x; 1.4455x over previous
#include <cuda_runtime.h>
#include <cuda_bf16.h>
#include <math.h>

#define BB      8
#define NPTS    4096
#define NS      1024
#define NP      32
#define DM      128
#define NH      4
#define DH      32
#define MLPH    256
#define GK      130
#define FFH     512
#define LN_EPS  1e-5f
#define SQROWS  (BB*NS)
#define GFROWS  (BB*NPTS)

// tensor-core gmlp geometry
#define SA  138     // stride of sA (64 x 138), data cols 0..135
#define SWS 138     // stride of sW (128 x 138)
#define SH  258     // stride of sH (64 x 258), data cols 0..255
#define SMEM_TC ((64*SA + 128*SWS + 64*SH) * 4)

__device__ float g_gfeat[GFROWS * DM];
__device__ float g_cent [BB * NS * 2];
__device__ int   g_knn  [BB * NS * NP];
__device__ int   g_kcnt [BB * NS];
__device__ float g_local[SQROWS * DM];
__device__ float g_x    [SQROWS * DM];
__device__ float g_x2   [SQROWS * DM];
__device__ float g_q    [SQROWS * DM];
__device__ float g_att  [SQROWS * DM];
__device__ float g_tmp  [SQROWS * DM];
__device__ float g_kv   [GFROWS * 256];
__device__ float g_ff   [SQROWS * FFH];

__device__ __forceinline__ float gelu_exact(float x) {
    return 0.5f * x * (1.0f + erff(x * 0.70710678118654752440f));
}

__device__ __forceinline__ float tf32r(float x) {
    unsigned u;
    asm("cvt.rna.tf32.f32 %0, %1;" : "=r"(u) : "f"(x));
    return __uint_as_float(u);
}

__device__ __forceinline__ void mma_tf32(float* c, unsigned a0, unsigned a1,
                                         unsigned a2, unsigned a3,
                                         unsigned b0, unsigned b1) {
    asm volatile(
        "mma.sync.aligned.m16n8k8.row.col.f32.tf32.tf32.f32 "
        "{%0,%1,%2,%3},{%4,%5,%6,%7},{%8,%9},{%0,%1,%2,%3};"
        : "+f"(c[0]), "+f"(c[1]), "+f"(c[2]), "+f"(c[3])
        : "r"(a0), "r"(a1), "r"(a2), "r"(a3), "r"(b0), "r"(b1));
}

// ---------- 1) fourier features + 26->128 projection ----------
__global__ __launch_bounds__(128) void gfeat_kernel(
    const float* __restrict__ pts, const float* __restrict__ fw, const float* __restrict__ fb)
{
    __shared__ float fsh[128 * 26];
    const int t = threadIdx.x;
    const int base = blockIdx.x * 128;
    float wreg[26];
    #pragma unroll
    for (int j = 0; j < 26; j++) wreg[j] = fw[t * 26 + j];

    const float FREQ[6] = {3.14159265358979323846f, 6.28318530717958647693f,
        12.5663706143591729539f, 25.1327412287183459077f,
        50.2654824574366918154f, 100.530964914873383631f};
    {
        float x = pts[(size_t)(base + t) * 2 + 0];
        float y = pts[(size_t)(base + t) * 2 + 1];
        fsh[t * 26 + 0] = x; fsh[t * 26 + 1] = y;
        #pragma unroll
        for (int k = 0; k < 6; k++) {
            float sx, cx, sy, cy;
            sincosf(FREQ[k] * x, &sx, &cx);
            sincosf(FREQ[k] * y, &sy, &cy);
            fsh[t*26 + 2 + 4*k + 0] = sx; fsh[t*26 + 2 + 4*k + 1] = sy;
            fsh[t*26 + 2 + 4*k + 2] = cx; fsh[t*26 + 2 + 4*k + 3] = cy;
        }
    }
    float bb = fb[t];
    __syncthreads();
    for (int p = 0; p < 128; p++) {
        float acc = bb;
        #pragma unroll
        for (int j = 0; j < 26; j++) acc += fsh[p * 26 + j] * wreg[j];
        g_gfeat[(size_t)(base + p) * DM + t] = acc;
    }
}

// ---------- 2) farthest point sampling ----------
__global__ __launch_bounds__(512) void fps_kernel(const float* __restrict__ pts)
{
    const int b = blockIdx.x, tid = threadIdx.x;
    const int lane = tid & 31, wid = tid >> 5;
    float px[8], py[8], dd[8];
    #pragma unroll
    for (int j = 0; j < 8; j++) {
        int p = tid + j * 512;
        px[j] = pts[((size_t)b * NPTS + p) * 2 + 0];
        py[j] = pts[((size_t)b * NPTS + p) * 2 + 1];
        dd[j] = INFINITY;
    }
    __shared__ float rv[16]; __shared__ int ri[16];
    __shared__ float rx[16], ry[16];
    __shared__ float sbx, sby;
    float lastx = pts[(size_t)b * NPTS * 2 + 0];
    float lasty = pts[(size_t)b * NPTS * 2 + 1];
    if (tid == 0) {
        g_cent[(size_t)b * NS * 2 + 0] = lastx;
        g_cent[(size_t)b * NS * 2 + 1] = lasty;
    }
    for (int it = 1; it < NS; it++) {
        float bv = -1.0f; int bi = 0x7fffffff; float bx = 0.f, by = 0.f;
        #pragma unroll
        for (int j = 0; j < 8; j++) {
            float dx = __fsub_rn(px[j], lastx);
            float dy = __fsub_rn(py[j], lasty);
            float d2 = __fadd_rn(__fmul_rn(dx, dx), __fmul_rn(dy, dy));
            dd[j] = fminf(dd[j], d2);
            if (dd[j] > bv) { bv = dd[j]; bi = tid + j * 512; bx = px[j]; by = py[j]; }
        }
        #pragma unroll
        for (int off = 16; off > 0; off >>= 1) {
            float ov = __shfl_down_sync(0xffffffffu, bv, off);
            int   oi = __shfl_down_sync(0xffffffffu, bi, off);
            float ox = __shfl_down_sync(0xffffffffu, bx, off);
            float oy = __shfl_down_sync(0xffffffffu, by, off);
            if (ov > bv || (ov == bv && oi < bi)) { bv = ov; bi = oi; bx = ox; by = oy; }
        }
        if (lane == 0) { rv[wid] = bv; ri[wid] = bi; rx[wid] = bx; ry[wid] = by; }
        __syncthreads();
        if (tid < 32) {
            if (tid < 16) { bv = rv[tid]; bi = ri[tid]; bx = rx[tid]; by = ry[tid]; }
            else          { bv = -1.0f; bi = 0x7fffffff; bx = 0.f; by = 0.f; }
            #pragma unroll
            for (int off = 8; off > 0; off >>= 1) {
                float ov = __shfl_down_sync(0xffffffffu, bv, off);
                int   oi = __shfl_down_sync(0xffffffffu, bi, off);
                float ox = __shfl_down_sync(0xffffffffu, bx, off);
                float oy = __shfl_down_sync(0xffffffffu, by, off);
                if (ov > bv || (ov == bv && oi < bi)) { bv = ov; bi = oi; bx = ox; by = oy; }
            }
            if (tid == 0) {
                g_cent[((size_t)b * NS + it) * 2 + 0] = bx;
                g_cent[((size_t)b * NS + it) * 2 + 1] = by;
                sbx = bx; sby = by;
            }
        }
        __syncthreads();
        lastx = sbx; lasty = sby;
    }
}

// ---------- 3) ball query (warp per centroid) ----------
__global__ __launch_bounds__(256) void bq_kernel(const float* __restrict__ pts)
{
    __shared__ int sknn[8][NP];
    const int gwid = (blockIdx.x * blockDim.x + threadIdx.x) >> 5;
    const int lane = threadIdx.x & 31, wl = threadIdx.x >> 5;
    if (gwid >= BB * NS) return;
    const int b = gwid >> 10;
    const float cx = g_cent[gwid * 2 + 0];
    const float cy = g_cent[gwid * 2 + 1];
    const float R2 = 0.01f;
    int cnt = 0;
    for (int c = 0; c < NPTS / 32 && cnt < NP; c++) {
        int p = c * 32 + lane;
        float dx = __fsub_rn(cx, pts[((size_t)b * NPTS + p) * 2 + 0]);
        float dy = __fsub_rn(cy, pts[((size_t)b * NPTS + p) * 2 + 1]);
        float d2 = __fadd_rn(__fmul_rn(dx, dx), __fmul_rn(dy, dy));
        bool in = d2 < R2;
        unsigned m = __ballot_sync(0xffffffffu, in);
        int before = __popc(m & ((1u << lane) - 1u));
        if (in && cnt + before < NP) sknn[wl][cnt + before] = p;
        cnt += __popc(m);
    }
    __syncwarp();
    int cc = min(cnt, NP);
    g_knn[gwid * NP + lane] = (lane < cc) ? sknn[wl][lane] : sknn[wl][0];
    if (lane == 0) g_kcnt[gwid] = cc;
}

// ---------- 4) grouped MLP on tensor cores (tf32 mma), 2 groups per block ----------
__device__ __forceinline__ void ln_gelu_sh(float* sH_, const float* __restrict__ g_,
                                           const float* __restrict__ be, int tid)
{
    const int row = tid >> 2, q = tid & 3;
    float x[64];
    #pragma unroll
    for (int j = 0; j < 64; j++) x[j] = sH_[row * SH + q + 4 * j];
    float s = 0.f;
    #pragma unroll
    for (int j = 0; j < 64; j++) s += x[j];
    s += __shfl_xor_sync(0xffffffffu, s, 1);
    s += __shfl_xor_sync(0xffffffffu, s, 2);
    float mu = s * (1.0f / 256.0f);
    float v = 0.f;
    #pragma unroll
    for (int j = 0; j < 64; j++) { float d = x[j] - mu; v += d * d; }
    v += __shfl_xor_sync(0xffffffffu, v, 1);
    v += __shfl_xor_sync(0xffffffffu, v, 2);
    float inv = rsqrtf(v * (1.0f / 256.0f) + LN_EPS);
    #pragma unroll
    for (int j = 0; j < 64; j++) {
        int col = q + 4 * j;
        float t = (x[j] - mu) * inv * __ldg(&g_[col]) + __ldg(&be[col]);
        sH_[row * SH + col] = tf32r(gelu_exact(t));
    }
}

__global__ __launch_bounds__(256, 1) void gmlp_tc_kernel(
    const float* __restrict__ pts,
    const float* __restrict__ w1, const float* __restrict__ b1,
    const float* __restrict__ lg1, const float* __restrict__ lb1,
    const float* __restrict__ w2, const float* __restrict__ b2,
    const float* __restrict__ lg2, const float* __restrict__ lb2,
    const float* __restrict__ w3, const float* __restrict__ b3)
{
    extern __shared__ float sm[];
    float* sA = sm;                        // 64 x SA
    float* sW = sm + 64 * SA;              // 128 x SWS
    float* sH = sm + 64 * SA + 128 * SWS;  // 64 x SH
    __shared__ int idxs[64];
    __shared__ int scnt[2];

    const int tid = threadIdx.x;
    const int blk = blockIdx.x;
    const int w = tid >> 5, lane = tid & 31;
    const int g = lane >> 2, q = lane & 3;
    const int wm = w & 3, wn = w >> 2;
    const int mrow = wm * 16;
    const int b = (blk * 2) >> 10;   // both groups of a block share a batch

    if (tid < 64) idxs[tid] = g_knn[(blk * 2 + (tid >> 5)) * NP + (tid & 31)];
    if (tid < 2) scnt[tid] = g_kcnt[blk * 2 + tid];
    __syncthreads();

    // gather gin into sA (tf32-rounded)
    for (int i = tid; i < 64 * 128; i += 256) {
        int r = i >> 7, c = i & 127;
        sA[r * SA + c] = tf32r(g_gfeat[((size_t)b * NPTS + idxs[r]) * DM + c]);
    }
    if (tid < 64) {
        int grp = blk * 2 + (tid >> 5);
        float cx = g_cent[grp * 2 + 0], cy = g_cent[grp * 2 + 1];
        const float* pp = pts + ((size_t)b * NPTS + idxs[tid]) * 2;
        sA[tid * SA + 128] = tf32r(pp[0] - cx);
        sA[tid * SA + 129] = tf32r(pp[1] - cy);
        #pragma unroll
        for (int c = 130; c < 136; c++) sA[tid * SA + c] = 0.f;
    }
    __syncthreads();

    // ---- GEMM1: (64x136) @ W1^T -> h (64x256), 2 N-passes ----
    for (int pass = 0; pass < 2; pass++) {
        for (int i = tid; i < 128 * 136; i += 256) {
            int n = i / 136, k = i - n * 136;
            sW[n * SWS + k] = (k < 130) ? tf32r(w1[(size_t)(pass * 128 + n) * 130 + k]) : 0.f;
        }
        __syncthreads();
        float c[8][4];
        #pragma unroll
        for (int nt = 0; nt < 8; nt++) { c[nt][0]=c[nt][1]=c[nt][2]=c[nt][3]=0.f; }
        for (int ks = 0; ks < 17; ks++) {
            int k0 = ks * 8;
            unsigned a0 = __float_as_uint(sA[(mrow + g) * SA + k0 + q]);
            unsigned a1 = __float_as_uint(sA[(mrow + g + 8) * SA + k0 + q]);
            unsigned a2 = __float_as_uint(sA[(mrow + g) * SA + k0 + q + 4]);
            unsigned a3 = __float_as_uint(sA[(mrow + g + 8) * SA + k0 + q + 4]);
            #pragma unroll
            for (int nt = 0; nt < 8; nt++) {
                int nb = wn * 64 + nt * 8;
                unsigned bb0 = __float_as_uint(sW[(nb + g) * SWS + k0 + q]);
                unsigned bb1 = __float_as_uint(sW[(nb + g) * SWS + k0 + q + 4]);
                mma_tf32(c[nt], a0, a1, a2, a3, bb0, bb1);
            }
        }
        __syncthreads();   // all warps done with sW before restage
        #pragma unroll
        for (int nt = 0; nt < 8; nt++) {
            int colg = pass * 128 + wn * 64 + nt * 8 + 2 * q;
            float bia = __ldg(&b1[colg]), bib = __ldg(&b1[colg + 1]);
            sH[(mrow + g) * SH + colg]     = c[nt][0] + bia;
            sH[(mrow + g) * SH + colg + 1] = c[nt][1] + bib;
            sH[(mrow + g + 8) * SH + colg]     = c[nt][2] + bia;
            sH[(mrow + g + 8) * SH + colg + 1] = c[nt][3] + bib;
        }
    }
    __syncthreads();
    ln_gelu_sh(sH, lg1, lb1, tid);
    __syncthreads();

    // ---- GEMM2: (64x256) @ W2^T -> (64x256), in-place on sH ----
    {
        float c2[2][8][4];
        #pragma unroll
        for (int p = 0; p < 2; p++)
            #pragma unroll
            for (int nt = 0; nt < 8; nt++) { c2[p][nt][0]=c2[p][nt][1]=c2[p][nt][2]=c2[p][nt][3]=0.f; }
        for (int pass = 0; pass < 2; pass++) {
            for (int kc = 0; kc < 2; kc++) {
                __syncthreads();
                for (int i = tid; i < 128 * 128; i += 256) {
                    int n = i >> 7, k = i & 127;
                    sW[n * SWS + k] = tf32r(w2[(size_t)(pass * 128 + n) * 256 + kc * 128 + k]);
                }
                __syncthreads();
                for (int ks = 0; ks < 16; ks++) {
                    int k0 = ks * 8;
                    int ka = kc * 128 + k0;
                    unsigned a0 = __float_as_uint(sH[(mrow + g) * SH + ka + q]);
                    unsigned a1 = __float_as_uint(sH[(mrow + g + 8) * SH + ka + q]);
                    unsigned a2 = __float_as_uint(sH[(mrow + g) * SH + ka + q + 4]);
                    unsigned a3 = __float_as_uint(sH[(mrow + g + 8) * SH + ka + q + 4]);
                    #pragma unroll
                    for (int nt = 0; nt < 8; nt++) {
                        int nb = wn * 64 + nt * 8;
                        unsigned bb0 = __float_as_uint(sW[(nb + g) * SWS + k0 + q]);
                        unsigned bb1 = __float_as_uint(sW[(nb + g) * SWS + k0 + q + 4]);
                        mma_tf32(c2[pass][nt], a0, a1, a2, a3, bb0, bb1);
                    }
                }
            }
        }
        __syncthreads();   // all reads of sH complete
        #pragma unroll
        for (int pass = 0; pass < 2; pass++)
            #pragma unroll
            for (int nt = 0; nt < 8; nt++) {
                int colg = pass * 128 + wn * 64 + nt * 8 + 2 * q;
                float bia = __ldg(&b2[colg]), bib = __ldg(&b2[colg + 1]);
                sH[(mrow + g) * SH + colg]     = c2[pass][nt][0] + bia;
                sH[(mrow + g) * SH + colg + 1] = c2[pass][nt][1] + bib;
                sH[(mrow + g + 8) * SH + colg]     = c2[pass][nt][2] + bia;
                sH[(mrow + g + 8) * SH + colg + 1] = c2[pass][nt][3] + bib;
            }
    }
    __syncthreads();
    ln_gelu_sh(sH, lg2, lb2, tid);
    __syncthreads();

    // ---- GEMM3: (64x256) @ W3^T -> (64x128) ----
    {
        float c3[8][4];
        #pragma unroll
        for (int nt = 0; nt < 8; nt++) { c3[nt][0]=c3[nt][1]=c3[nt][2]=c3[nt][3]=0.f; }
        for (int kc = 0; kc < 2; kc++) {
            __syncthreads();
            for (int i = tid; i < 128 * 128; i += 256) {
                int n = i >> 7, k = i & 127;
                sW[n * SWS + k] = tf32r(w3[(size_t)n * 256 + kc * 128 + k]);
            }
            __syncthreads();
            for (int ks = 0; ks < 16; ks++) {
                int k0 = ks * 8;
                int ka = kc * 128 + k0;
                unsigned a0 = __float_as_uint(sH[(mrow + g) * SH + ka + q]);
                unsigned a1 = __float_as_uint(sH[(mrow + g + 8) * SH + ka + q]);
                unsigned a2 = __float_as_uint(sH[(mrow + g) * SH + ka + q + 4]);
                unsigned a3 = __float_as_uint(sH[(mrow + g + 8) * SH + ka + q + 4]);
                #pragma unroll
                for (int nt = 0; nt < 8; nt++) {
                    int nb = wn * 64 + nt * 8;
                    unsigned bb0 = __float_as_uint(sW[(nb + g) * SWS + k0 + q]);
                    unsigned bb1 = __float_as_uint(sW[(nb + g) * SWS + k0 + q + 4]);
                    mma_tf32(c3[nt], a0, a1, a2, a3, bb0, bb1);
                }
            }
        }
        __syncthreads();   // sA free now (gather no longer needed)
        #pragma unroll
        for (int nt = 0; nt < 8; nt++) {
            int colg = wn * 64 + nt * 8 + 2 * q;
            float bia = __ldg(&b3[colg]), bib = __ldg(&b3[colg + 1]);
            sA[(mrow + g) * SA + colg]     = c3[nt][0] + bia;
            sA[(mrow + g) * SA + colg + 1] = c3[nt][1] + bib;
            sA[(mrow + g + 8) * SA + colg]     = c3[nt][2] + bia;
            sA[(mrow + g + 8) * SA + colg + 1] = c3[nt][3] + bib;
        }
    }
    __syncthreads();

    // masked max over group rows
    {
        int grp = tid >> 7, col = tid & 127;
        int cnt = scnt[grp];
        float mx = sA[(grp * 32) * SA + col];
        for (int r = 1; r < cnt; r++) mx = fmaxf(mx, sA[(grp * 32 + r) * SA + col]);
        g_local[(size_t)(blk * 2 + grp) * DM + col] = mx;
    }
}

// ---------- 5) tiled SGEMM: C[M,Nc] = A[M,K] @ W[Nc,K]^T + bias ----------
template<int EPI>  // 0 none, 1 gelu
__global__ __launch_bounds__(256) void gemm_kernel(
    const float* __restrict__ A, const float* __restrict__ W,
    const float* __restrict__ bias, float* __restrict__ C,
    int M, int Nc, int K)
{
    __shared__ float As[64 * 17];
    __shared__ float Ws[16 * 68];
    const int tid = threadIdx.x;
    const int tx = tid & 15, ty = tid >> 4;
    const int m0 = blockIdx.y * 64, n0 = blockIdx.x * 64;
    const int lk = tid & 15, lm = tid >> 4;
    float acc[4][4];
    #pragma unroll
    for (int r = 0; r < 4; r++)
        #pragma unroll
        for (int c = 0; c < 4; c++) acc[r][c] = 0.f;

    for (int k0 = 0; k0 < K; k0 += 16) {
        #pragma unroll
        for (int i = 0; i < 4; i++) {
            int m = lm + i * 16;
            As[m * 17 + lk] = A[(size_t)(m0 + m) * K + k0 + lk];
            Ws[lk * 68 + m] = W[(size_t)(n0 + m) * K + k0 + lk];
        }
        __syncthreads();
        #pragma unroll
        for (int k = 0; k < 16; k++) {
            float av[4], wv[4];
            #pragma unroll
            for (int r = 0; r < 4; r++) av[r] = As[(ty * 4 + r) * 17 + k];
            #pragma unroll
            for (int c = 0; c < 4; c++) wv[c] = Ws[k * 68 + tx * 4 + c];
            #pragma unroll
            for (int r = 0; r < 4; r++)
                #pragma unroll
                for (int c = 0; c < 4; c++) acc[r][c] += av[r] * wv[c];
        }
        __syncthreads();
    }
    #pragma unroll
    for (int c = 0; c < 4; c++) {
        int n = n0 + tx * 4 + c;
        float bn = bias[n];
        #pragma unroll
        for (int r = 0; r < 4; r++) {
            float v = acc[r][c] + bn;
            if (EPI == 1) v = gelu_exact(v);
            C[(size_t)(m0 + ty * 4 + r) * Nc + n] = v;
        }
    }
}

// ---------- 6) fused flash attention (fp32) ----------
__global__ __launch_bounds__(128) void flash_kernel(
    const float* __restrict__ Q, const float* __restrict__ KV,
    float* __restrict__ Out, int Sq, int Skv)
{
    __shared__ float Qs[16 * 33];
    __shared__ float Ks[64 * 33];
    __shared__ float Vs[64 * 33];
    __shared__ float Ps[16 * 65];
    const int b = blockIdx.z, h = blockIdx.y, q0 = blockIdx.x * 16;
    const int tid = threadIdx.x;
    const int qr = tid >> 3, dg = tid & 7;
    const int d0 = dg * 4, kb = dg * 8;
    const float scale = 0.17677669529663687f;

    #pragma unroll
    for (int i = 0; i < 4; i++) {
        int e = tid * 4 + i;
        int q = e >> 5, d = e & 31;
        Qs[q * 33 + d] = Q[((size_t)(b * Sq + q0 + q)) * DM + h * DH + d];
    }
    float O[4] = {0.f, 0.f, 0.f, 0.f};
    float mreg = -INFINITY, lreg = 0.f;

    for (int kv0 = 0; kv0 < Skv; kv0 += 64) {
        #pragma unroll
        for (int i = 0; i < 16; i++) {
            int idx = tid + i * 128;
            int r = idx >> 5, d = idx & 31;
            size_t grow = (size_t)(b * Skv + kv0 + r) * 256;
            Ks[r * 33 + d] = KV[grow + h * DH + d];
            Vs[r * 33 + d] = KV[grow + 128 + h * DH + d];
        }
        __syncthreads();
        float s[8];
        #pragma unroll
        for (int j = 0; j < 8; j++) s[j] = 0.f;
        #pragma unroll
        for (int d = 0; d < 32; d++) {
            float qv = Qs[qr * 33 + d];
            #pragma unroll
            for (int j = 0; j < 8; j++) s[j] += Ks[(kb + j) * 33 + d] * qv;
        }
        float rmax = -INFINITY;
        #pragma unroll
        for (int j = 0; j < 8; j++) { s[j] *= scale; rmax = fmaxf(rmax, s[j]); }
        #pragma unroll
        for (int o = 1; o < 8; o <<= 1) rmax = fmaxf(rmax, __shfl_xor_sync(0xffffffffu, rmax, o));
        float mnew = fmaxf(mreg, rmax);
        float corr = expf(mreg - mnew);
        float psum = 0.f;
        #pragma unroll
        for (int j = 0; j < 8; j++) {
            float p = expf(s[j] - mnew);
            Ps[qr * 65 + kb + j] = p;
            psum += p;
        }
        #pragma unroll
        for (int o = 1; o < 8; o <<= 1) psum += __shfl_xor_sync(0xffffffffu, psum, o);
        lreg = lreg * corr + psum;
        mreg = mnew;
        #pragma unroll
        for (int c = 0; c < 4; c++) O[c] *= corr;
        __syncthreads();
        for (int k = 0; k < 64; k++) {
            float pv = Ps[qr * 65 + k];
            #pragma unroll
            for (int c = 0; c < 4; c++) O[c] += pv * Vs[k * 33 + d0 + c];
        }
        __syncthreads();
    }
    float inv = 1.0f / lreg;
    #pragma unroll
    for (int c = 0; c < 4; c++)
        Out[((size_t)(b * Sq + q0 + qr)) * DM + h * DH + d0 + c] = O[c] * inv;
}

// ---------- 7) residual add + layernorm (width 128) ----------
__global__ __launch_bounds__(128) void ln_res_kernel(
    float* __restrict__ out, const float* __restrict__ a, const float* __restrict__ res,
    const float* __restrict__ g, const float* __restrict__ be)
{
    __shared__ float sh1[4], sh2[4];
    const int row = blockIdx.x, t = threadIdx.x;
    const int w = t >> 5, lane = t & 31;
    float x = a[(size_t)row * DM + t] + res[(size_t)row * DM + t];
    float s = x;
    #pragma unroll
    for (int o = 16; o > 0; o >>= 1) s += __shfl_xor_sync(0xffffffffu, s, o);
    if (lane == 0) sh1[w] = s;
    __syncthreads();
    float mu = (sh1[0] + sh1[1] + sh1[2] + sh1[3]) * (1.0f / 128.0f);
    float d = x - mu;
    float q = d * d;
    #pragma unroll
    for (int o = 16; o > 0; o >>= 1) q += __shfl_xor_sync(0xffffffffu, q, o);
    if (lane == 0) sh2[w] = q;
    __syncthreads();
    float var = (sh2[0] + sh2[1] + sh2[2] + sh2[3]) * (1.0f / 128.0f);
    out[(size_t)row * DM + t] = d * rsqrtf(var + LN_EPS) * g[t] + be[t];
}

// ---------- host ----------
extern "C" void kernel_launch(void* const* d_in, const int* in_sizes, int n_in,
                              void* d_out, int out_size)
{
    (void)in_sizes; (void)n_in; (void)out_size;
    const float* pts     = (const float*)d_in[0];
    const float* feat_w  = (const float*)d_in[2];
    const float* feat_b  = (const float*)d_in[3];
    const float* mlp_w1  = (const float*)d_in[4];
    const float* mlp_b1  = (const float*)d_in[5];
    const float* mlp_g1  = (const float*)d_in[6];
    const float* mlp_be1 = (const float*)d_in[7];
    const float* mlp_w2  = (const float*)d_in[8];
    const float* mlp_b2  = (const float*)d_in[9];
    const float* mlp_g2  = (const float*)d_in[10];
    const float* mlp_be2 = (const float*)d_in[11];
    const float* mlp_w3  = (const float*)d_in[12];
    const float* mlp_b3  = (const float*)d_in[13];
    const float* blk_in_w = (const float*)d_in[14];
    const float* blk_in_b = (const float*)d_in[15];
    const float* blk_ow   = (const float*)d_in[16];
    const float* blk_ob   = (const float*)d_in[17];
    const float* blk_g1   = (const float*)d_in[18];
    const float* blk_be1  = (const float*)d_in[19];
    const float* blk_g2   = (const float*)d_in[20];
    const float* blk_be2  = (const float*)d_in[21];
    const float* blk_f1w  = (const float*)d_in[22];
    const float* blk_f1b  = (const float*)d_in[23];
    const float* blk_f2w  = (const float*)d_in[24];
    const float* blk_f2b  = (const float*)d_in[25];
    const float* k_w = (const float*)d_in[26];
    const float* k_b = (const float*)d_in[27];
    const float* v_w = (const float*)d_in[28];
    const float* v_b = (const float*)d_in[29];
    float* out = (float*)d_out;

    float *gfeatp, *localp, *xp, *x2p, *qp, *attp, *tmpp, *kvp, *ffp;
    cudaGetSymbolAddress((void**)&gfeatp, g_gfeat);
    cudaGetSymbolAddress((void**)&localp, g_local);
    cudaGetSymbolAddress((void**)&xp,     g_x);
    cudaGetSymbolAddress((void**)&x2p,    g_x2);
    cudaGetSymbolAddress((void**)&qp,     g_q);
    cudaGetSymbolAddress((void**)&attp,   g_att);
    cudaGetSymbolAddress((void**)&tmpp,   g_tmp);
    cudaGetSymbolAddress((void**)&kvp,    g_kv);
    cudaGetSymbolAddress((void**)&ffp,    g_ff);

    cudaFuncSetAttribute(gmlp_tc_kernel, cudaFuncAttributeMaxDynamicSharedMemorySize, SMEM_TC);

    gfeat_kernel<<<GFROWS / 128, 128>>>(pts, feat_w, feat_b);
    fps_kernel<<<BB, 512>>>(pts);
    bq_kernel<<<(BB * NS) / 8, 256>>>(pts);
    gmlp_tc_kernel<<<BB * NS / 2, 256, SMEM_TC>>>(pts, mlp_w1, mlp_b1, mlp_g1, mlp_be1,
                                                  mlp_w2, mlp_b2, mlp_g2, mlp_be2, mlp_w3, mlp_b3);

    for (int i = 0; i < 4; i++) {
        const float* xcur = (i == 0) ? localp : xp;
        const float* kvsrc = (i < 2) ? gfeatp : xcur;
        int Skv = (i < 2) ? NPTS : NS;
        int Mkv = BB * Skv;
        const float* wq = blk_in_w + (size_t)i * 384 * 128;
        const float* bq = blk_in_b + (size_t)i * 384;

        gemm_kernel<0><<<dim3(2, SQROWS / 64), 256>>>(xcur, wq, bq, qp, SQROWS, 128, 128);
        gemm_kernel<0><<<dim3(4, Mkv / 64), 256>>>(kvsrc, wq + 128 * 128, bq + 128, kvp, Mkv, 256, 128);
        flash_kernel<<<dim3(NS / 16, NH, BB), 128>>>(qp, kvp, attp, NS, Skv);
        gemm_kernel<0><<<dim3(2, SQROWS / 64), 256>>>(attp, blk_ow + (size_t)i * 128 * 128,
                                                      blk_ob + (size_t)i * 128, tmpp, SQROWS, 128, 128);
        ln_res_kernel<<<SQROWS, 128>>>(x2p, tmpp, xcur, blk_g1 + (size_t)i * 128, blk_be1 + (size_t)i * 128);
        gemm_kernel<1><<<dim3(8, SQROWS / 64), 256>>>(x2p, blk_f1w + (size_t)i * 512 * 128,
                                                      blk_f1b + (size_t)i * 512, ffp, SQROWS, 512, 128);
        gemm_kernel<0><<<dim3(2, SQROWS / 64), 256>>>(ffp, blk_f2w + (size_t)i * 128 * 512,
                                                      blk_f2b + (size_t)i * 128, tmpp, SQROWS, 128, 512);
        ln_res_kernel<<<SQROWS, 128>>>(xp, tmpp, x2p, blk_g2 + (size_t)i * 128, blk_be2 + (size_t)i * 128);
    }

    gemm_kernel<0><<<dim3(2, SQROWS / 64), 256>>>(xp, k_w, k_b, out, SQROWS, 128, 128);
    gemm_kernel<0><<<dim3(2, SQROWS / 64), 256>>>(xp, v_w, v_b, out + (size_t)SQROWS * 128, SQROWS, 128, 128);
}

// round 4
// speedup vs baseline: 1.7101x; 1.1830x over previous
#include <cuda_runtime.h>
#include <cuda_bf16.h>
#include <math.h>

#define BB      8
#define NPTS    4096
#define NS      1024
#define NP      32
#define DM      128
#define NH      4
#define DH      32
#define MLPH    256
#define GK      130
#define FFH     512
#define LN_EPS  1e-5f
#define SQROWS  (BB*NS)
#define GFROWS  (BB*NPTS)

// tensor-core gmlp geometry
#define SA  138
#define SWS 138
#define SH  258
#define SMEM_TC ((64*SA + 128*SWS + 64*SH) * 4)

// split-3 gemm geometry: 64x64 tile, K-chunk 16 logical -> 48 physical
#define GSTR 51

__device__ float g_gfeat[GFROWS * DM];
__device__ float g_cent [BB * NS * 2];
__device__ int   g_knn  [BB * NS * NP];
__device__ int   g_kcnt [BB * NS];
__device__ float g_local[SQROWS * DM];
__device__ float g_x    [SQROWS * DM];
__device__ float g_x2   [SQROWS * DM];
__device__ float g_q    [SQROWS * DM];
__device__ float g_att  [SQROWS * DM];
__device__ float g_tmp  [SQROWS * DM];
__device__ float g_kv   [GFROWS * 256];
__device__ float g_ff   [SQROWS * FFH];

__device__ __forceinline__ float gelu_exact(float x) {
    return 0.5f * x * (1.0f + erff(x * 0.70710678118654752440f));
}

__device__ __forceinline__ float tf32r(float x) {
    unsigned u;
    asm("cvt.rna.tf32.f32 %0, %1;" : "=r"(u) : "f"(x));
    return __uint_as_float(u);
}

__device__ __forceinline__ void mma_tf32(float* c, unsigned a0, unsigned a1,
                                         unsigned a2, unsigned a3,
                                         unsigned b0, unsigned b1) {
    asm volatile(
        "mma.sync.aligned.m16n8k8.row.col.f32.tf32.tf32.f32 "
        "{%0,%1,%2,%3},{%4,%5,%6,%7},{%8,%9},{%0,%1,%2,%3};"
        : "+f"(c[0]), "+f"(c[1]), "+f"(c[2]), "+f"(c[3])
        : "r"(a0), "r"(a1), "r"(a2), "r"(a3), "r"(b0), "r"(b1));
}

// ---------- 1) fourier features + 26->128 projection ----------
__global__ __launch_bounds__(128) void gfeat_kernel(
    const float* __restrict__ pts, const float* __restrict__ fw, const float* __restrict__ fb)
{
    __shared__ float fsh[128 * 26];
    const int t = threadIdx.x;
    const int base = blockIdx.x * 128;
    float wreg[26];
    #pragma unroll
    for (int j = 0; j < 26; j++) wreg[j] = fw[t * 26 + j];

    const float FREQ[6] = {3.14159265358979323846f, 6.28318530717958647693f,
        12.5663706143591729539f, 25.1327412287183459077f,
        50.2654824574366918154f, 100.530964914873383631f};
    {
        float x = pts[(size_t)(base + t) * 2 + 0];
        float y = pts[(size_t)(base + t) * 2 + 1];
        fsh[t * 26 + 0] = x; fsh[t * 26 + 1] = y;
        #pragma unroll
        for (int k = 0; k < 6; k++) {
            float sx, cx, sy, cy;
            sincosf(FREQ[k] * x, &sx, &cx);
            sincosf(FREQ[k] * y, &sy, &cy);
            fsh[t*26 + 2 + 4*k + 0] = sx; fsh[t*26 + 2 + 4*k + 1] = sy;
            fsh[t*26 + 2 + 4*k + 2] = cx; fsh[t*26 + 2 + 4*k + 3] = cy;
        }
    }
    float bb = fb[t];
    __syncthreads();
    for (int p = 0; p < 128; p++) {
        float acc = bb;
        #pragma unroll
        for (int j = 0; j < 26; j++) acc += fsh[p * 26 + j] * wreg[j];
        g_gfeat[(size_t)(base + p) * DM + t] = acc;
    }
}

// ---------- 2) farthest point sampling ----------
__global__ __launch_bounds__(512) void fps_kernel(const float* __restrict__ pts)
{
    const int b = blockIdx.x, tid = threadIdx.x;
    const int lane = tid & 31, wid = tid >> 5;
    float px[8], py[8], dd[8];
    #pragma unroll
    for (int j = 0; j < 8; j++) {
        int p = tid + j * 512;
        px[j] = pts[((size_t)b * NPTS + p) * 2 + 0];
        py[j] = pts[((size_t)b * NPTS + p) * 2 + 1];
        dd[j] = INFINITY;
    }
    __shared__ float rv[16]; __shared__ int ri[16];
    __shared__ float rx[16], ry[16];
    __shared__ float sbx, sby;
    float lastx = pts[(size_t)b * NPTS * 2 + 0];
    float lasty = pts[(size_t)b * NPTS * 2 + 1];
    if (tid == 0) {
        g_cent[(size_t)b * NS * 2 + 0] = lastx;
        g_cent[(size_t)b * NS * 2 + 1] = lasty;
    }
    for (int it = 1; it < NS; it++) {
        float bv = -1.0f; int bi = 0x7fffffff; float bx = 0.f, by = 0.f;
        #pragma unroll
        for (int j = 0; j < 8; j++) {
            float dx = __fsub_rn(px[j], lastx);
            float dy = __fsub_rn(py[j], lasty);
            float d2 = __fadd_rn(__fmul_rn(dx, dx), __fmul_rn(dy, dy));
            dd[j] = fminf(dd[j], d2);
            if (dd[j] > bv) { bv = dd[j]; bi = tid + j * 512; bx = px[j]; by = py[j]; }
        }
        #pragma unroll
        for (int off = 16; off > 0; off >>= 1) {
            float ov = __shfl_down_sync(0xffffffffu, bv, off);
            int   oi = __shfl_down_sync(0xffffffffu, bi, off);
            float ox = __shfl_down_sync(0xffffffffu, bx, off);
            float oy = __shfl_down_sync(0xffffffffu, by, off);
            if (ov > bv || (ov == bv && oi < bi)) { bv = ov; bi = oi; bx = ox; by = oy; }
        }
        if (lane == 0) { rv[wid] = bv; ri[wid] = bi; rx[wid] = bx; ry[wid] = by; }
        __syncthreads();
        if (tid < 32) {
            if (tid < 16) { bv = rv[tid]; bi = ri[tid]; bx = rx[tid]; by = ry[tid]; }
            else          { bv = -1.0f; bi = 0x7fffffff; bx = 0.f; by = 0.f; }
            #pragma unroll
            for (int off = 8; off > 0; off >>= 1) {
                float ov = __shfl_down_sync(0xffffffffu, bv, off);
                int   oi = __shfl_down_sync(0xffffffffu, bi, off);
                float ox = __shfl_down_sync(0xffffffffu, bx, off);
                float oy = __shfl_down_sync(0xffffffffu, by, off);
                if (ov > bv || (ov == bv && oi < bi)) { bv = ov; bi = oi; bx = ox; by = oy; }
            }
            if (tid == 0) {
                g_cent[((size_t)b * NS + it) * 2 + 0] = bx;
                g_cent[((size_t)b * NS + it) * 2 + 1] = by;
                sbx = bx; sby = by;
            }
        }
        __syncthreads();
        lastx = sbx; lasty = sby;
    }
}

// ---------- 3) ball query ----------
__global__ __launch_bounds__(256) void bq_kernel(const float* __restrict__ pts)
{
    __shared__ int sknn[8][NP];
    const int gwid = (blockIdx.x * blockDim.x + threadIdx.x) >> 5;
    const int lane = threadIdx.x & 31, wl = threadIdx.x >> 5;
    if (gwid >= BB * NS) return;
    const int b = gwid >> 10;
    const float cx = g_cent[gwid * 2 + 0];
    const float cy = g_cent[gwid * 2 + 1];
    const float R2 = 0.01f;
    int cnt = 0;
    for (int c = 0; c < NPTS / 32 && cnt < NP; c++) {
        int p = c * 32 + lane;
        float dx = __fsub_rn(cx, pts[((size_t)b * NPTS + p) * 2 + 0]);
        float dy = __fsub_rn(cy, pts[((size_t)b * NPTS + p) * 2 + 1]);
        float d2 = __fadd_rn(__fmul_rn(dx, dx), __fmul_rn(dy, dy));
        bool in = d2 < R2;
        unsigned m = __ballot_sync(0xffffffffu, in);
        int before = __popc(m & ((1u << lane) - 1u));
        if (in && cnt + before < NP) sknn[wl][cnt + before] = p;
        cnt += __popc(m);
    }
    __syncwarp();
    int cc = min(cnt, NP);
    g_knn[gwid * NP + lane] = (lane < cc) ? sknn[wl][lane] : sknn[wl][0];
    if (lane == 0) g_kcnt[gwid] = cc;
}

// ---------- 4) grouped MLP on tensor cores (unchanged from R3) ----------
__device__ __forceinline__ void ln_gelu_sh(float* sH_, const float* __restrict__ g_,
                                           const float* __restrict__ be, int tid)
{
    const int row = tid >> 2, q = tid & 3;
    float x[64];
    #pragma unroll
    for (int j = 0; j < 64; j++) x[j] = sH_[row * SH + q + 4 * j];
    float s = 0.f;
    #pragma unroll
    for (int j = 0; j < 64; j++) s += x[j];
    s += __shfl_xor_sync(0xffffffffu, s, 1);
    s += __shfl_xor_sync(0xffffffffu, s, 2);
    float mu = s * (1.0f / 256.0f);
    float v = 0.f;
    #pragma unroll
    for (int j = 0; j < 64; j++) { float d = x[j] - mu; v += d * d; }
    v += __shfl_xor_sync(0xffffffffu, v, 1);
    v += __shfl_xor_sync(0xffffffffu, v, 2);
    float inv = rsqrtf(v * (1.0f / 256.0f) + LN_EPS);
    #pragma unroll
    for (int j = 0; j < 64; j++) {
        int col = q + 4 * j;
        float t = (x[j] - mu) * inv * __ldg(&g_[col]) + __ldg(&be[col]);
        sH_[row * SH + col] = tf32r(gelu_exact(t));
    }
}

__global__ __launch_bounds__(256, 1) void gmlp_tc_kernel(
    const float* __restrict__ pts,
    const float* __restrict__ w1, const float* __restrict__ b1,
    const float* __restrict__ lg1, const float* __restrict__ lb1,
    const float* __restrict__ w2, const float* __restrict__ b2,
    const float* __restrict__ lg2, const float* __restrict__ lb2,
    const float* __restrict__ w3, const float* __restrict__ b3)
{
    extern __shared__ float sm[];
    float* sA = sm;
    float* sW = sm + 64 * SA;
    float* sH = sm + 64 * SA + 128 * SWS;
    __shared__ int idxs[64];
    __shared__ int scnt[2];

    const int tid = threadIdx.x;
    const int blk = blockIdx.x;
    const int w = tid >> 5, lane = tid & 31;
    const int g = lane >> 2, q = lane & 3;
    const int wm = w & 3, wn = w >> 2;
    const int mrow = wm * 16;
    const int b = (blk * 2) >> 10;

    if (tid < 64) idxs[tid] = g_knn[(blk * 2 + (tid >> 5)) * NP + (tid & 31)];
    if (tid < 2) scnt[tid] = g_kcnt[blk * 2 + tid];
    __syncthreads();

    for (int i = tid; i < 64 * 128; i += 256) {
        int r = i >> 7, c = i & 127;
        sA[r * SA + c] = tf32r(g_gfeat[((size_t)b * NPTS + idxs[r]) * DM + c]);
    }
    if (tid < 64) {
        int grp = blk * 2 + (tid >> 5);
        float cx = g_cent[grp * 2 + 0], cy = g_cent[grp * 2 + 1];
        const float* pp = pts + ((size_t)b * NPTS + idxs[tid]) * 2;
        sA[tid * SA + 128] = tf32r(pp[0] - cx);
        sA[tid * SA + 129] = tf32r(pp[1] - cy);
        #pragma unroll
        for (int c = 130; c < 136; c++) sA[tid * SA + c] = 0.f;
    }
    __syncthreads();

    for (int pass = 0; pass < 2; pass++) {
        for (int i = tid; i < 128 * 136; i += 256) {
            int n = i / 136, k = i - n * 136;
            sW[n * SWS + k] = (k < 130) ? tf32r(w1[(size_t)(pass * 128 + n) * 130 + k]) : 0.f;
        }
        __syncthreads();
        float c[8][4];
        #pragma unroll
        for (int nt = 0; nt < 8; nt++) { c[nt][0]=c[nt][1]=c[nt][2]=c[nt][3]=0.f; }
        for (int ks = 0; ks < 17; ks++) {
            int k0 = ks * 8;
            unsigned a0 = __float_as_uint(sA[(mrow + g) * SA + k0 + q]);
            unsigned a1 = __float_as_uint(sA[(mrow + g + 8) * SA + k0 + q]);
            unsigned a2 = __float_as_uint(sA[(mrow + g) * SA + k0 + q + 4]);
            unsigned a3 = __float_as_uint(sA[(mrow + g + 8) * SA + k0 + q + 4]);
            #pragma unroll
            for (int nt = 0; nt < 8; nt++) {
                int nb = wn * 64 + nt * 8;
                unsigned bb0 = __float_as_uint(sW[(nb + g) * SWS + k0 + q]);
                unsigned bb1 = __float_as_uint(sW[(nb + g) * SWS + k0 + q + 4]);
                mma_tf32(c[nt], a0, a1, a2, a3, bb0, bb1);
            }
        }
        __syncthreads();
        #pragma unroll
        for (int nt = 0; nt < 8; nt++) {
            int colg = pass * 128 + wn * 64 + nt * 8 + 2 * q;
            float bia = __ldg(&b1[colg]), bib = __ldg(&b1[colg + 1]);
            sH[(mrow + g) * SH + colg]     = c[nt][0] + bia;
            sH[(mrow + g) * SH + colg + 1] = c[nt][1] + bib;
            sH[(mrow + g + 8) * SH + colg]     = c[nt][2] + bia;
            sH[(mrow + g + 8) * SH + colg + 1] = c[nt][3] + bib;
        }
    }
    __syncthreads();
    ln_gelu_sh(sH, lg1, lb1, tid);
    __syncthreads();

    {
        float c2[2][8][4];
        #pragma unroll
        for (int p = 0; p < 2; p++)
            #pragma unroll
            for (int nt = 0; nt < 8; nt++) { c2[p][nt][0]=c2[p][nt][1]=c2[p][nt][2]=c2[p][nt][3]=0.f; }
        for (int pass = 0; pass < 2; pass++) {
            for (int kc = 0; kc < 2; kc++) {
                __syncthreads();
                for (int i = tid; i < 128 * 128; i += 256) {
                    int n = i >> 7, k = i & 127;
                    sW[n * SWS + k] = tf32r(w2[(size_t)(pass * 128 + n) * 256 + kc * 128 + k]);
                }
                __syncthreads();
                for (int ks = 0; ks < 16; ks++) {
                    int k0 = ks * 8;
                    int ka = kc * 128 + k0;
                    unsigned a0 = __float_as_uint(sH[(mrow + g) * SH + ka + q]);
                    unsigned a1 = __float_as_uint(sH[(mrow + g + 8) * SH + ka + q]);
                    unsigned a2 = __float_as_uint(sH[(mrow + g) * SH + ka + q + 4]);
                    unsigned a3 = __float_as_uint(sH[(mrow + g + 8) * SH + ka + q + 4]);
                    #pragma unroll
                    for (int nt = 0; nt < 8; nt++) {
                        int nb = wn * 64 + nt * 8;
                        unsigned bb0 = __float_as_uint(sW[(nb + g) * SWS + k0 + q]);
                        unsigned bb1 = __float_as_uint(sW[(nb + g) * SWS + k0 + q + 4]);
                        mma_tf32(c2[pass][nt], a0, a1, a2, a3, bb0, bb1);
                    }
                }
            }
        }
        __syncthreads();
        #pragma unroll
        for (int pass = 0; pass < 2; pass++)
            #pragma unroll
            for (int nt = 0; nt < 8; nt++) {
                int colg = pass * 128 + wn * 64 + nt * 8 + 2 * q;
                float bia = __ldg(&b2[colg]), bib = __ldg(&b2[colg + 1]);
                sH[(mrow + g) * SH + colg]     = c2[pass][nt][0] + bia;
                sH[(mrow + g) * SH + colg + 1] = c2[pass][nt][1] + bib;
                sH[(mrow + g + 8) * SH + colg]     = c2[pass][nt][2] + bia;
                sH[(mrow + g + 8) * SH + colg + 1] = c2[pass][nt][3] + bib;
            }
    }
    __syncthreads();
    ln_gelu_sh(sH, lg2, lb2, tid);
    __syncthreads();

    {
        float c3[8][4];
        #pragma unroll
        for (int nt = 0; nt < 8; nt++) { c3[nt][0]=c3[nt][1]=c3[nt][2]=c3[nt][3]=0.f; }
        for (int kc = 0; kc < 2; kc++) {
            __syncthreads();
            for (int i = tid; i < 128 * 128; i += 256) {
                int n = i >> 7, k = i & 127;
                sW[n * SWS + k] = tf32r(w3[(size_t)n * 256 + kc * 128 + k]);
            }
            __syncthreads();
            for (int ks = 0; ks < 16; ks++) {
                int k0 = ks * 8;
                int ka = kc * 128 + k0;
                unsigned a0 = __float_as_uint(sH[(mrow + g) * SH + ka + q]);
                unsigned a1 = __float_as_uint(sH[(mrow + g + 8) * SH + ka + q]);
                unsigned a2 = __float_as_uint(sH[(mrow + g) * SH + ka + q + 4]);
                unsigned a3 = __float_as_uint(sH[(mrow + g + 8) * SH + ka + q + 4]);
                #pragma unroll
                for (int nt = 0; nt < 8; nt++) {
                    int nb = wn * 64 + nt * 8;
                    unsigned bb0 = __float_as_uint(sW[(nb + g) * SWS + k0 + q]);
                    unsigned bb1 = __float_as_uint(sW[(nb + g) * SWS + k0 + q + 4]);
                    mma_tf32(c3[nt], a0, a1, a2, a3, bb0, bb1);
                }
            }
        }
        __syncthreads();
        #pragma unroll
        for (int nt = 0; nt < 8; nt++) {
            int colg = wn * 64 + nt * 8 + 2 * q;
            float bia = __ldg(&b3[colg]), bib = __ldg(&b3[colg + 1]);
            sA[(mrow + g) * SA + colg]     = c3[nt][0] + bia;
            sA[(mrow + g) * SA + colg + 1] = c3[nt][1] + bib;
            sA[(mrow + g + 8) * SA + colg]     = c3[nt][2] + bia;
            sA[(mrow + g + 8) * SA + colg + 1] = c3[nt][3] + bib;
        }
    }
    __syncthreads();

    {
        int grp = tid >> 7, col = tid & 127;
        int cnt = scnt[grp];
        float mx = sA[(grp * 32) * SA + col];
        for (int r = 1; r < cnt; r++) mx = fmaxf(mx, sA[(grp * 32 + r) * SA + col]);
        g_local[(size_t)(blk * 2 + grp) * DM + col] = mx;
    }
}

// ---------- 5) tensor-core GEMM, 3xTF32 split (~fp32 accuracy) ----------
// C[M,Nc] = A[M,K] @ W[Nc,K]^T + bias.  Block tile 64x64, K-chunk 16 logical (48 physical).
template<int EPI>  // 0 none, 1 gelu
__global__ __launch_bounds__(256) void gemm_tc_kernel(
    const float* __restrict__ A, const float* __restrict__ W,
    const float* __restrict__ bias, float* __restrict__ C,
    int M, int Nc, int K)
{
    __shared__ float sA[64 * GSTR];
    __shared__ float sW[64 * GSTR];
    const int tid = threadIdx.x;
    const int w = tid >> 5, lane = tid & 31;
    const int g = lane >> 2, q = lane & 3;
    const int wm = w & 3, wn = w >> 2;
    const int mrow = wm * 16;
    const int m0 = blockIdx.y * 64, n0 = blockIdx.x * 64;

    float acc[4][4];
    #pragma unroll
    for (int nf = 0; nf < 4; nf++) { acc[nf][0]=acc[nf][1]=acc[nf][2]=acc[nf][3]=0.f; }

    for (int k0 = 0; k0 < K; k0 += 16) {
        // stage A: rows of A, pattern [hi,hi,lo]; stage W: pattern [hi,lo,hi]
        #pragma unroll
        for (int j = 0; j < 4; j++) {
            int e = tid + j * 256;           // 1024 elems: 64 rows x 16 k
            int r = e >> 4, kk = e & 15;
            float x = A[(size_t)(m0 + r) * K + k0 + kk];
            float hi = tf32r(x);
            float lo = tf32r(x - hi);
            float* p = &sA[r * GSTR + 3 * kk];
            p[0] = hi; p[1] = hi; p[2] = lo;
            float y = W[(size_t)(n0 + r) * K + k0 + kk];
            float whi = tf32r(y);
            float wlo = tf32r(y - whi);
            float* pw = &sW[r * GSTR + 3 * kk];
            pw[0] = whi; pw[1] = wlo; pw[2] = whi;
        }
        __syncthreads();
        #pragma unroll
        for (int ks = 0; ks < 6; ks++) {
            int kp = ks * 8;
            unsigned a0 = __float_as_uint(sA[(mrow + g) * GSTR + kp + q]);
            unsigned a1 = __float_as_uint(sA[(mrow + g + 8) * GSTR + kp + q]);
            unsigned a2 = __float_as_uint(sA[(mrow + g) * GSTR + kp + q + 4]);
            unsigned a3 = __float_as_uint(sA[(mrow + g + 8) * GSTR + kp + q + 4]);
            #pragma unroll
            for (int nf = 0; nf < 4; nf++) {
                int nb = wn * 32 + nf * 8;
                unsigned b0 = __float_as_uint(sW[(nb + g) * GSTR + kp + q]);
                unsigned b1 = __float_as_uint(sW[(nb + g) * GSTR + kp + q + 4]);
                mma_tf32(acc[nf], a0, a1, a2, a3, b0, b1);
            }
        }
        __syncthreads();
    }

    #pragma unroll
    for (int nf = 0; nf < 4; nf++) {
        int colg = n0 + wn * 32 + nf * 8 + 2 * q;
        float bia = __ldg(&bias[colg]), bib = __ldg(&bias[colg + 1]);
        float v00 = acc[nf][0] + bia, v01 = acc[nf][1] + bib;
        float v10 = acc[nf][2] + bia, v11 = acc[nf][3] + bib;
        if (EPI == 1) {
            v00 = gelu_exact(v00); v01 = gelu_exact(v01);
            v10 = gelu_exact(v10); v11 = gelu_exact(v11);
        }
        C[(size_t)(m0 + mrow + g) * Nc + colg]         = v00;
        C[(size_t)(m0 + mrow + g) * Nc + colg + 1]     = v01;
        C[(size_t)(m0 + mrow + g + 8) * Nc + colg]     = v10;
        C[(size_t)(m0 + mrow + g + 8) * Nc + colg + 1] = v11;
    }
}

// ---------- 6) flash attention v2 (fp32, reg-Q, swizzled K, shfl-P) ----------
__global__ __launch_bounds__(256) void flash2_kernel(
    const float* __restrict__ Q, const float* __restrict__ KV,
    float* __restrict__ Out, int Sq, int Skv)
{
    __shared__ float Ks[64 * 32];
    __shared__ float Vs[64 * 32];
    const int b = blockIdx.z, h = blockIdx.y, q0 = blockIdx.x * 32;
    const int tid = threadIdx.x;
    const int qr = tid >> 3, dg = tid & 7;
    const int d0 = dg * 4, kb = dg * 8;
    const float scale = 0.17677669529663687f;

    float4 q4[8];
    {
        const float* qrow = Q + (size_t)(b * Sq + q0 + qr) * DM + h * DH;
        #pragma unroll
        for (int d4 = 0; d4 < 8; d4++) q4[d4] = *(const float4*)(qrow + d4 * 4);
    }

    float O[4] = {0.f, 0.f, 0.f, 0.f};
    float mreg = -INFINITY, lreg = 0.f;

    for (int kv0 = 0; kv0 < Skv; kv0 += 64) {
        #pragma unroll
        for (int i = 0; i < 2; i++) {
            int e = tid + i * 256;          // 512 float4: 64 rows x 8 groups
            int r = e >> 3, c4 = e & 7;
            const float* base = KV + (size_t)(b * Skv + kv0 + r) * 256 + h * DH + c4 * 4;
            float4 kv_ = *(const float4*)base;
            *(float4*)&Ks[r * 32 + ((c4 ^ (r >> 3)) * 4)] = kv_;
            float4 vv = *(const float4*)(base + 128);
            *(float4*)&Vs[r * 32 + c4 * 4] = vv;
        }
        __syncthreads();

        float s[8];
        #pragma unroll
        for (int j = 0; j < 8; j++) {
            float acc = 0.f;
            const float* krow = &Ks[(kb + j) * 32];
            #pragma unroll
            for (int d4 = 0; d4 < 8; d4++) {
                float4 k4 = *(const float4*)(krow + ((d4 ^ dg) * 4));
                acc += q4[d4].x * k4.x + q4[d4].y * k4.y + q4[d4].z * k4.z + q4[d4].w * k4.w;
            }
            s[j] = acc * scale;
        }
        float rmax = s[0];
        #pragma unroll
        for (int j = 1; j < 8; j++) rmax = fmaxf(rmax, s[j]);
        rmax = fmaxf(rmax, __shfl_xor_sync(0xffffffffu, rmax, 1));
        rmax = fmaxf(rmax, __shfl_xor_sync(0xffffffffu, rmax, 2));
        rmax = fmaxf(rmax, __shfl_xor_sync(0xffffffffu, rmax, 4));

        float mnew = fmaxf(mreg, rmax);
        float corr = expf(mreg - mnew);
        float p[8];
        float psum = 0.f;
        #pragma unroll
        for (int j = 0; j < 8; j++) { p[j] = expf(s[j] - mnew); psum += p[j]; }
        psum += __shfl_xor_sync(0xffffffffu, psum, 1);
        psum += __shfl_xor_sync(0xffffffffu, psum, 2);
        psum += __shfl_xor_sync(0xffffffffu, psum, 4);
        lreg = lreg * corr + psum;
        mreg = mnew;
        #pragma unroll
        for (int c = 0; c < 4; c++) O[c] *= corr;

        #pragma unroll
        for (int sl = 0; sl < 8; sl++) {
            #pragma unroll
            for (int j = 0; j < 8; j++) {
                float pv = __shfl_sync(0xffffffffu, p[j], sl, 8);
                float4 v4 = *(const float4*)&Vs[(sl * 8 + j) * 32 + d0];
                O[0] += pv * v4.x; O[1] += pv * v4.y;
                O[2] += pv * v4.z; O[3] += pv * v4.w;
            }
        }
        __syncthreads();
    }
    float inv = 1.0f / lreg;
    float* orow = Out + (size_t)(b * Sq + q0 + qr) * DM + h * DH + d0;
    orow[0] = O[0] * inv; orow[1] = O[1] * inv;
    orow[2] = O[2] * inv; orow[3] = O[3] * inv;
}

// ---------- 7) residual add + layernorm ----------
__global__ __launch_bounds__(128) void ln_res_kernel(
    float* __restrict__ out, const float* __restrict__ a, const float* __restrict__ res,
    const float* __restrict__ g, const float* __restrict__ be)
{
    __shared__ float sh1[4], sh2[4];
    const int row = blockIdx.x, t = threadIdx.x;
    const int w = t >> 5, lane = t & 31;
    float x = a[(size_t)row * DM + t] + res[(size_t)row * DM + t];
    float s = x;
    #pragma unroll
    for (int o = 16; o > 0; o >>= 1) s += __shfl_xor_sync(0xffffffffu, s, o);
    if (lane == 0) sh1[w] = s;
    __syncthreads();
    float mu = (sh1[0] + sh1[1] + sh1[2] + sh1[3]) * (1.0f / 128.0f);
    float d = x - mu;
    float q = d * d;
    #pragma unroll
    for (int o = 16; o > 0; o >>= 1) q += __shfl_xor_sync(0xffffffffu, q, o);
    if (lane == 0) sh2[w] = q;
    __syncthreads();
    float var = (sh2[0] + sh2[1] + sh2[2] + sh2[3]) * (1.0f / 128.0f);
    out[(size_t)row * DM + t] = d * rsqrtf(var + LN_EPS) * g[t] + be[t];
}

// ---------- host ----------
extern "C" void kernel_launch(void* const* d_in, const int* in_sizes, int n_in,
                              void* d_out, int out_size)
{
    (void)in_sizes; (void)n_in; (void)out_size;
    const float* pts     = (const float*)d_in[0];
    const float* feat_w  = (const float*)d_in[2];
    const float* feat_b  = (const float*)d_in[3];
    const float* mlp_w1  = (const float*)d_in[4];
    const float* mlp_b1  = (const float*)d_in[5];
    const float* mlp_g1  = (const float*)d_in[6];
    const float* mlp_be1 = (const float*)d_in[7];
    const float* mlp_w2  = (const float*)d_in[8];
    const float* mlp_b2  = (const float*)d_in[9];
    const float* mlp_g2  = (const float*)d_in[10];
    const float* mlp_be2 = (const float*)d_in[11];
    const float* mlp_w3  = (const float*)d_in[12];
    const float* mlp_b3  = (const float*)d_in[13];
    const float* blk_in_w = (const float*)d_in[14];
    const float* blk_in_b = (const float*)d_in[15];
    const float* blk_ow   = (const float*)d_in[16];
    const float* blk_ob   = (const float*)d_in[17];
    const float* blk_g1   = (const float*)d_in[18];
    const float* blk_be1  = (const float*)d_in[19];
    const float* blk_g2   = (const float*)d_in[20];
    const float* blk_be2  = (const float*)d_in[21];
    const float* blk_f1w  = (const float*)d_in[22];
    const float* blk_f1b  = (const float*)d_in[23];
    const float* blk_f2w  = (const float*)d_in[24];
    const float* blk_f2b  = (const float*)d_in[25];
    const float* k_w = (const float*)d_in[26];
    const float* k_b = (const float*)d_in[27];
    const float* v_w = (const float*)d_in[28];
    const float* v_b = (const float*)d_in[29];
    float* out = (float*)d_out;

    float *gfeatp, *localp, *xp, *x2p, *qp, *attp, *tmpp, *kvp, *ffp;
    cudaGetSymbolAddress((void**)&gfeatp, g_gfeat);
    cudaGetSymbolAddress((void**)&localp, g_local);
    cudaGetSymbolAddress((void**)&xp,     g_x);
    cudaGetSymbolAddress((void**)&x2p,    g_x2);
    cudaGetSymbolAddress((void**)&qp,     g_q);
    cudaGetSymbolAddress((void**)&attp,   g_att);
    cudaGetSymbolAddress((void**)&tmpp,   g_tmp);
    cudaGetSymbolAddress((void**)&kvp,    g_kv);
    cudaGetSymbolAddress((void**)&ffp,    g_ff);

    cudaFuncSetAttribute(gmlp_tc_kernel, cudaFuncAttributeMaxDynamicSharedMemorySize, SMEM_TC);

    gfeat_kernel<<<GFROWS / 128, 128>>>(pts, feat_w, feat_b);
    fps_kernel<<<BB, 512>>>(pts);
    bq_kernel<<<(BB * NS) / 8, 256>>>(pts);
    gmlp_tc_kernel<<<BB * NS / 2, 256, SMEM_TC>>>(pts, mlp_w1, mlp_b1, mlp_g1, mlp_be1,
                                                  mlp_w2, mlp_b2, mlp_g2, mlp_be2, mlp_w3, mlp_b3);

    for (int i = 0; i < 4; i++) {
        const float* xcur = (i == 0) ? localp : xp;
        const float* kvsrc = (i < 2) ? gfeatp : xcur;
        int Skv = (i < 2) ? NPTS : NS;
        int Mkv = BB * Skv;
        const float* wq = blk_in_w + (size_t)i * 384 * 128;
        const float* bq = blk_in_b + (size_t)i * 384;

        gemm_tc_kernel<0><<<dim3(2, SQROWS / 64), 256>>>(xcur, wq, bq, qp, SQROWS, 128, 128);
        gemm_tc_kernel<0><<<dim3(4, Mkv / 64), 256>>>(kvsrc, wq + 128 * 128, bq + 128, kvp, Mkv, 256, 128);
        flash2_kernel<<<dim3(NS / 32, NH, BB), 256>>>(qp, kvp, attp, NS, Skv);
        gemm_tc_kernel<0><<<dim3(2, SQROWS / 64), 256>>>(attp, blk_ow + (size_t)i * 128 * 128,
                                                         blk_ob + (size_t)i * 128, tmpp, SQROWS, 128, 128);
        ln_res_kernel<<<SQROWS, 128>>>(x2p, tmpp, xcur, blk_g1 + (size_t)i * 128, blk_be1 + (size_t)i * 128);
        gemm_tc_kernel<1><<<dim3(8, SQROWS / 64), 256>>>(x2p, blk_f1w + (size_t)i * 512 * 128,
                                                         blk_f1b + (size_t)i * 512, ffp, SQROWS, 512, 128);
        gemm_tc_kernel<0><<<dim3(2, SQROWS / 64), 256>>>(ffp, blk_f2w + (size_t)i * 128 * 512,
                                                         blk_f2b + (size_t)i * 128, tmpp, SQROWS, 128, 512);
        ln_res_kernel<<<SQROWS, 128>>>(xp, tmpp, x2p, blk_g2 + (size_t)i * 128, blk_be2 + (size_t)i * 128);
    }

    gemm_tc_kernel<0><<<dim3(2, SQROWS / 64), 256>>>(xp, k_w, k_b, out, SQROWS, 128, 128);
    gemm_tc_kernel<0><<<dim3(2, SQROWS / 64), 256>>>(xp, v_w, v_b, out + (size_t)SQROWS * 128, SQROWS, 128, 128);
}

// round 6
// speedup vs baseline: 1.7909x; 1.0473x over previous
#include <cuda_runtime.h>
#include <cuda_bf16.h>
#include <math.h>

#define BB      8
#define NPTS    4096
#define NS      1024
#define NP      32
#define DM      128
#define NH      4
#define DH      32
#define FFH     512
#define LN_EPS  1e-5f
#define SQROWS  (BB*NS)
#define GFROWS  (BB*NPTS)
#define GMROWS  (SQROWS*NP)      // 262144

// 3x-split gemm (transformer linears)
#define GSTR 51
// big 1x gemm (grouped MLP)
#define BSTR 36
#define SM_BIG   (2*128*BSTR*4)
#define SM_BIG2  (SM_BIG + 128*132*4)

__device__ float g_gfeat[GFROWS * DM];
__device__ float g_cent [BB * NS * 2];
__device__ int   g_knn  [BB * NS * NP];
__device__ int   g_kcnt [BB * NS];
__device__ float g_local[SQROWS * DM];
__device__ float g_x    [SQROWS * DM];
__device__ float g_x2   [SQROWS * DM];
__device__ float g_q    [SQROWS * DM];
__device__ float g_att  [SQROWS * DM];
__device__ float g_tmp  [SQROWS * DM];
__device__ float g_kv   [GFROWS * 256];
__device__ float g_ff   [SQROWS * FFH];
__device__ float g_big1 [GMROWS * 256];
__device__ float g_big2 [GMROWS * 256];

__device__ __forceinline__ float gelu_exact(float x) {
    return 0.5f * x * (1.0f + erff(x * 0.70710678118654752440f));
}

__device__ __forceinline__ float tf32r(float x) {
    unsigned u;
    asm("cvt.rna.tf32.f32 %0, %1;" : "=r"(u) : "f"(x));
    return __uint_as_float(u);
}

__device__ __forceinline__ void mma_tf32(float* c, unsigned a0, unsigned a1,
                                         unsigned a2, unsigned a3,
                                         unsigned b0, unsigned b1) {
    asm volatile(
        "mma.sync.aligned.m16n8k8.row.col.f32.tf32.tf32.f32 "
        "{%0,%1,%2,%3},{%4,%5,%6,%7},{%8,%9},{%0,%1,%2,%3};"
        : "+f"(c[0]), "+f"(c[1]), "+f"(c[2]), "+f"(c[3])
        : "r"(a0), "r"(a1), "r"(a2), "r"(a3), "r"(b0), "r"(b1));
}

// ---------- 1) fourier features + 26->128 projection ----------
__global__ __launch_bounds__(128) void gfeat_kernel(
    const float* __restrict__ pts, const float* __restrict__ fw, const float* __restrict__ fb)
{
    __shared__ float fsh[128 * 26];
    const int t = threadIdx.x;
    const int base = blockIdx.x * 128;
    float wreg[26];
    #pragma unroll
    for (int j = 0; j < 26; j++) wreg[j] = fw[t * 26 + j];

    const float FREQ[6] = {3.14159265358979323846f, 6.28318530717958647693f,
        12.5663706143591729539f, 25.1327412287183459077f,
        50.2654824574366918154f, 100.530964914873383631f};
    {
        float x = pts[(size_t)(base + t) * 2 + 0];
        float y = pts[(size_t)(base + t) * 2 + 1];
        fsh[t * 26 + 0] = x; fsh[t * 26 + 1] = y;
        #pragma unroll
        for (int k = 0; k < 6; k++) {
            float sx, cx, sy, cy;
            sincosf(FREQ[k] * x, &sx, &cx);
            sincosf(FREQ[k] * y, &sy, &cy);
            fsh[t*26 + 2 + 4*k + 0] = sx; fsh[t*26 + 2 + 4*k + 1] = sy;
            fsh[t*26 + 2 + 4*k + 2] = cx; fsh[t*26 + 2 + 4*k + 3] = cy;
        }
    }
    float bb = fb[t];
    __syncthreads();
    for (int p = 0; p < 128; p++) {
        float acc = bb;
        #pragma unroll
        for (int j = 0; j < 26; j++) acc += fsh[p * 26 + j] * wreg[j];
        g_gfeat[(size_t)(base + p) * DM + t] = acc;
    }
}

// ---------- 2) farthest point sampling ----------
__global__ __launch_bounds__(512) void fps_kernel(const float* __restrict__ pts)
{
    const int b = blockIdx.x, tid = threadIdx.x;
    const int lane = tid & 31, wid = tid >> 5;
    float px[8], py[8], dd[8];
    #pragma unroll
    for (int j = 0; j < 8; j++) {
        int p = tid + j * 512;
        px[j] = pts[((size_t)b * NPTS + p) * 2 + 0];
        py[j] = pts[((size_t)b * NPTS + p) * 2 + 1];
        dd[j] = INFINITY;
    }
    __shared__ float rv[16]; __shared__ int ri[16];
    __shared__ float rx[16], ry[16];
    __shared__ float sbx, sby;
    float lastx = pts[(size_t)b * NPTS * 2 + 0];
    float lasty = pts[(size_t)b * NPTS * 2 + 1];
    if (tid == 0) {
        g_cent[(size_t)b * NS * 2 + 0] = lastx;
        g_cent[(size_t)b * NS * 2 + 1] = lasty;
    }
    for (int it = 1; it < NS; it++) {
        float bv = -1.0f; int bi = 0x7fffffff; float bx = 0.f, by = 0.f;
        #pragma unroll
        for (int j = 0; j < 8; j++) {
            float dx = __fsub_rn(px[j], lastx);
            float dy = __fsub_rn(py[j], lasty);
            float d2 = __fadd_rn(__fmul_rn(dx, dx), __fmul_rn(dy, dy));
            dd[j] = fminf(dd[j], d2);
            if (dd[j] > bv) { bv = dd[j]; bi = tid + j * 512; bx = px[j]; by = py[j]; }
        }
        #pragma unroll
        for (int off = 16; off > 0; off >>= 1) {
            float ov = __shfl_down_sync(0xffffffffu, bv, off);
            int   oi = __shfl_down_sync(0xffffffffu, bi, off);
            float ox = __shfl_down_sync(0xffffffffu, bx, off);
            float oy = __shfl_down_sync(0xffffffffu, by, off);
            if (ov > bv || (ov == bv && oi < bi)) { bv = ov; bi = oi; bx = ox; by = oy; }
        }
        if (lane == 0) { rv[wid] = bv; ri[wid] = bi; rx[wid] = bx; ry[wid] = by; }
        __syncthreads();
        if (tid < 32) {
            if (tid < 16) { bv = rv[tid]; bi = ri[tid]; bx = rx[tid]; by = ry[tid]; }
            else          { bv = -1.0f; bi = 0x7fffffff; bx = 0.f; by = 0.f; }
            #pragma unroll
            for (int off = 8; off > 0; off >>= 1) {
                float ov = __shfl_down_sync(0xffffffffu, bv, off);
                int   oi = __shfl_down_sync(0xffffffffu, bi, off);
                float ox = __shfl_down_sync(0xffffffffu, bx, off);
                float oy = __shfl_down_sync(0xffffffffu, by, off);
                if (ov > bv || (ov == bv && oi < bi)) { bv = ov; bi = oi; bx = ox; by = oy; }
            }
            if (tid == 0) {
                g_cent[((size_t)b * NS + it) * 2 + 0] = bx;
                g_cent[((size_t)b * NS + it) * 2 + 1] = by;
                sbx = bx; sby = by;
            }
        }
        __syncthreads();
        lastx = sbx; lasty = sby;
    }
}

// ---------- 3) ball query ----------
__global__ __launch_bounds__(256) void bq_kernel(const float* __restrict__ pts)
{
    __shared__ int sknn[8][NP];
    const int gwid = (blockIdx.x * blockDim.x + threadIdx.x) >> 5;
    const int lane = threadIdx.x & 31, wl = threadIdx.x >> 5;
    if (gwid >= BB * NS) return;
    const int b = gwid >> 10;
    const float cx = g_cent[gwid * 2 + 0];
    const float cy = g_cent[gwid * 2 + 1];
    const float R2 = 0.01f;
    int cnt = 0;
    for (int c = 0; c < NPTS / 32 && cnt < NP; c++) {
        int p = c * 32 + lane;
        float dx = __fsub_rn(cx, pts[((size_t)b * NPTS + p) * 2 + 0]);
        float dy = __fsub_rn(cy, pts[((size_t)b * NPTS + p) * 2 + 1]);
        float d2 = __fadd_rn(__fmul_rn(dx, dx), __fmul_rn(dy, dy));
        bool in = d2 < R2;
        unsigned m = __ballot_sync(0xffffffffu, in);
        int before = __popc(m & ((1u << lane) - 1u));
        if (in && cnt + before < NP) sknn[wl][cnt + before] = p;
        cnt += __popc(m);
    }
    __syncwarp();
    int cc = min(cnt, NP);
    g_knn[gwid * NP + lane] = (lane < cc) ? sknn[wl][lane] : sknn[wl][0];
    if (lane == 0) g_kcnt[gwid] = cc;
}

// ---------- 4) big flat GEMM for grouped MLP (single tf32, 128x128 tiles) ----------
// MODE 0: A from global. MODE 1: A gathered via g_knn (gin rows).
// EPI  0: write C=acc+bias.  EPI 2: masked 32-row max-pool into g_local.
template<int MODE, int EPI>
__global__ __launch_bounds__(256) void gemm_big_kernel(
    const float* __restrict__ A, const float* __restrict__ W,
    const float* __restrict__ bias, float* __restrict__ C,
    int N, int K, int KW, const float* __restrict__ pts)
{
    extern __shared__ float sm[];
    float* sA = sm;                 // 128 x BSTR
    float* sW = sm + 128 * BSTR;    // 128 x BSTR
    float* sE = sm + 2 * 128 * BSTR; // EPI==2: 128 x 132
    __shared__ int   sIdx[128];
    __shared__ float sRx[128], sRy[128];
    __shared__ int   sCnt[4];

    const int tid = threadIdx.x;
    const int w = tid >> 5, lane = tid & 31;
    const int g = lane >> 2, q = lane & 3;
    const int wm = w & 3, wn = w >> 2;
    const int m0 = blockIdx.y * 128, n0 = blockIdx.x * 128;
    const int b_batch = m0 >> 15;   // 32768 rows per batch

    if (MODE == 1) {
        if (tid < 128) {
            int m = m0 + tid;
            int grp = m >> 5;
            int idx = g_knn[grp * NP + (m & 31)];
            sIdx[tid] = idx;
            float cx = g_cent[grp * 2 + 0], cy = g_cent[grp * 2 + 1];
            const float* pp = pts + ((size_t)b_batch * NPTS + idx) * 2;
            sRx[tid] = pp[0] - cx;
            sRy[tid] = pp[1] - cy;
        }
    }
    if (EPI == 2) {
        if (tid < 4) sCnt[tid] = g_kcnt[(m0 >> 5) + tid];
    }
    if (MODE == 1 || EPI == 2) __syncthreads();

    float acc[2][8][4];
    #pragma unroll
    for (int mf = 0; mf < 2; mf++)
        #pragma unroll
        for (int nf = 0; nf < 8; nf++) { acc[mf][nf][0]=acc[mf][nf][1]=acc[mf][nf][2]=acc[mf][nf][3]=0.f; }

    for (int k0 = 0; k0 < K; k0 += 32) {
        // stage A (128x32) and W (128x32)
        #pragma unroll
        for (int j = 0; j < 16; j++) {
            int e = j * 256 + tid;
            int r = e >> 5, kk = e & 31;
            int k = k0 + kk;
            float va;
            if (MODE == 1) {
                if (k < 128)      va = g_gfeat[((size_t)b_batch * NPTS + sIdx[r]) * DM + k];
                else if (k == 128) va = sRx[r];
                else if (k == 129) va = sRy[r];
                else               va = 0.f;
            } else {
                va = A[(size_t)(m0 + r) * K + k];
            }
            sA[r * BSTR + kk] = tf32r(va);
            float vw = (k < KW) ? W[(size_t)(n0 + r) * KW + k] : 0.f;
            sW[r * BSTR + kk] = tf32r(vw);
        }
        __syncthreads();
        #pragma unroll
        for (int ks = 0; ks < 4; ks++) {
            int kp = ks * 8;
            unsigned a[2][4];
            #pragma unroll
            for (int mf = 0; mf < 2; mf++) {
                int mb = wm * 32 + mf * 16;
                a[mf][0] = __float_as_uint(sA[(mb + g) * BSTR + kp + q]);
                a[mf][1] = __float_as_uint(sA[(mb + g + 8) * BSTR + kp + q]);
                a[mf][2] = __float_as_uint(sA[(mb + g) * BSTR + kp + q + 4]);
                a[mf][3] = __float_as_uint(sA[(mb + g + 8) * BSTR + kp + q + 4]);
            }
            #pragma unroll
            for (int nf = 0; nf < 8; nf++) {
                int nb = wn * 64 + nf * 8;
                unsigned b0 = __float_as_uint(sW[(nb + g) * BSTR + kp + q]);
                unsigned b1 = __float_as_uint(sW[(nb + g) * BSTR + kp + q + 4]);
                mma_tf32(acc[0][nf], a[0][0], a[0][1], a[0][2], a[0][3], b0, b1);
                mma_tf32(acc[1][nf], a[1][0], a[1][1], a[1][2], a[1][3], b0, b1);
            }
        }
        __syncthreads();
    }

    if (EPI != 2) {
        #pragma unroll
        for (int mf = 0; mf < 2; mf++) {
            int rb = m0 + wm * 32 + mf * 16;
            #pragma unroll
            for (int nf = 0; nf < 8; nf++) {
                int colg = n0 + wn * 64 + nf * 8 + 2 * q;
                float bia = __ldg(&bias[colg]), bib = __ldg(&bias[colg + 1]);
                C[(size_t)(rb + g) * N + colg]         = acc[mf][nf][0] + bia;
                C[(size_t)(rb + g) * N + colg + 1]     = acc[mf][nf][1] + bib;
                C[(size_t)(rb + g + 8) * N + colg]     = acc[mf][nf][2] + bia;
                C[(size_t)(rb + g + 8) * N + colg + 1] = acc[mf][nf][3] + bib;
            }
        }
    } else {
        #pragma unroll
        for (int mf = 0; mf < 2; mf++) {
            int rb = wm * 32 + mf * 16;
            #pragma unroll
            for (int nf = 0; nf < 8; nf++) {
                int colg = wn * 64 + nf * 8 + 2 * q;
                float bia = __ldg(&bias[colg]), bib = __ldg(&bias[colg + 1]);
                sE[(rb + g) * 132 + colg]         = acc[mf][nf][0] + bia;
                sE[(rb + g) * 132 + colg + 1]     = acc[mf][nf][1] + bib;
                sE[(rb + g + 8) * 132 + colg]     = acc[mf][nf][2] + bia;
                sE[(rb + g + 8) * 132 + colg + 1] = acc[mf][nf][3] + bib;
            }
        }
        __syncthreads();
        #pragma unroll
        for (int pass = 0; pass < 2; pass++) {
            int grp = (tid >> 7) + pass * 2;
            int col = tid & 127;
            int cnt = sCnt[grp];
            float mx = sE[(grp * 32) * 132 + col];
            for (int r = 1; r < cnt; r++) mx = fmaxf(mx, sE[(grp * 32 + r) * 132 + col]);
            C[(size_t)((m0 >> 5) + grp) * DM + col] = mx;
        }
    }
}

// ---------- LN + GELU over 256-wide rows (warp per row) ----------
__global__ __launch_bounds__(256) void ln_big_kernel(
    float* __restrict__ H, const float* __restrict__ g, const float* __restrict__ be)
{
    const int row = blockIdx.x * 8 + (threadIdx.x >> 5);
    const int lane = threadIdx.x & 31;
    float4* hp = (float4*)(H + (size_t)row * 256);
    float4 x0 = hp[lane * 2], x1 = hp[lane * 2 + 1];
    float s = x0.x + x0.y + x0.z + x0.w + x1.x + x1.y + x1.z + x1.w;
    #pragma unroll
    for (int o = 16; o > 0; o >>= 1) s += __shfl_xor_sync(0xffffffffu, s, o);
    float mu = s * (1.0f / 256.0f);
    float v = 0.f;
    {
        float d;
        d = x0.x - mu; v += d * d; d = x0.y - mu; v += d * d;
        d = x0.z - mu; v += d * d; d = x0.w - mu; v += d * d;
        d = x1.x - mu; v += d * d; d = x1.y - mu; v += d * d;
        d = x1.z - mu; v += d * d; d = x1.w - mu; v += d * d;
    }
    #pragma unroll
    for (int o = 16; o > 0; o >>= 1) v += __shfl_xor_sync(0xffffffffu, v, o);
    float inv = rsqrtf(v * (1.0f / 256.0f) + LN_EPS);
    int c0 = lane * 8;
    float4 gg0 = *(const float4*)(g + c0),  gg1 = *(const float4*)(g + c0 + 4);
    float4 bb0 = *(const float4*)(be + c0), bb1 = *(const float4*)(be + c0 + 4);
    x0.x = gelu_exact((x0.x - mu) * inv * gg0.x + bb0.x);
    x0.y = gelu_exact((x0.y - mu) * inv * gg0.y + bb0.y);
    x0.z = gelu_exact((x0.z - mu) * inv * gg0.z + bb0.z);
    x0.w = gelu_exact((x0.w - mu) * inv * gg0.w + bb0.w);
    x1.x = gelu_exact((x1.x - mu) * inv * gg1.x + bb1.x);
    x1.y = gelu_exact((x1.y - mu) * inv * gg1.y + bb1.y);
    x1.z = gelu_exact((x1.z - mu) * inv * gg1.z + bb1.z);
    x1.w = gelu_exact((x1.w - mu) * inv * gg1.w + bb1.w);
    hp[lane * 2] = x0; hp[lane * 2 + 1] = x1;
}

// ---------- 5) tensor-core GEMM, 3xTF32 split (transformer linears) ----------
template<int EPI>  // 0 none, 1 gelu
__global__ __launch_bounds__(256) void gemm_tc_kernel(
    const float* __restrict__ A, const float* __restrict__ W,
    const float* __restrict__ bias, float* __restrict__ C,
    int M, int Nc, int K)
{
    __shared__ float sA[64 * GSTR];
    __shared__ float sW[64 * GSTR];
    const int tid = threadIdx.x;
    const int w = tid >> 5, lane = tid & 31;
    const int g = lane >> 2, q = lane & 3;
    const int wm = w & 3, wn = w >> 2;
    const int mrow = wm * 16;
    const int m0 = blockIdx.y * 64, n0 = blockIdx.x * 64;

    float acc[4][4];
    #pragma unroll
    for (int nf = 0; nf < 4; nf++) { acc[nf][0]=acc[nf][1]=acc[nf][2]=acc[nf][3]=0.f; }

    for (int k0 = 0; k0 < K; k0 += 16) {
        #pragma unroll
        for (int j = 0; j < 4; j++) {
            int e = tid + j * 256;
            int r = e >> 4, kk = e & 15;
            float x = A[(size_t)(m0 + r) * K + k0 + kk];
            float hi = tf32r(x);
            float lo = tf32r(x - hi);
            float* p = &sA[r * GSTR + 3 * kk];
            p[0] = hi; p[1] = hi; p[2] = lo;
            float y = W[(size_t)(n0 + r) * K + k0 + kk];
            float whi = tf32r(y);
            float wlo = tf32r(y - whi);
            float* pw = &sW[r * GSTR + 3 * kk];
            pw[0] = whi; pw[1] = wlo; pw[2] = whi;
        }
        __syncthreads();
        #pragma unroll
        for (int ks = 0; ks < 6; ks++) {
            int kp = ks * 8;
            unsigned a0 = __float_as_uint(sA[(mrow + g) * GSTR + kp + q]);
            unsigned a1 = __float_as_uint(sA[(mrow + g + 8) * GSTR + kp + q]);
            unsigned a2 = __float_as_uint(sA[(mrow + g) * GSTR + kp + q + 4]);
            unsigned a3 = __float_as_uint(sA[(mrow + g + 8) * GSTR + kp + q + 4]);
            #pragma unroll
            for (int nf = 0; nf < 4; nf++) {
                int nb = wn * 32 + nf * 8;
                unsigned b0 = __float_as_uint(sW[(nb + g) * GSTR + kp + q]);
                unsigned b1 = __float_as_uint(sW[(nb + g) * GSTR + kp + q + 4]);
                mma_tf32(acc[nf], a0, a1, a2, a3, b0, b1);
            }
        }
        __syncthreads();
    }

    #pragma unroll
    for (int nf = 0; nf < 4; nf++) {
        int colg = n0 + wn * 32 + nf * 8 + 2 * q;
        float bia = __ldg(&bias[colg]), bib = __ldg(&bias[colg + 1]);
        float v00 = acc[nf][0] + bia, v01 = acc[nf][1] + bib;
        float v10 = acc[nf][2] + bia, v11 = acc[nf][3] + bib;
        if (EPI == 1) {
            v00 = gelu_exact(v00); v01 = gelu_exact(v01);
            v10 = gelu_exact(v10); v11 = gelu_exact(v11);
        }
        C[(size_t)(m0 + mrow + g) * Nc + colg]         = v00;
        C[(size_t)(m0 + mrow + g) * Nc + colg + 1]     = v01;
        C[(size_t)(m0 + mrow + g + 8) * Nc + colg]     = v10;
        C[(size_t)(m0 + mrow + g + 8) * Nc + colg + 1] = v11;
    }
}

// ---------- 6) flash attention (fp32, reg-Q, swizzled K, shfl-P) ----------
__global__ __launch_bounds__(256) void flash2_kernel(
    const float* __restrict__ Q, const float* __restrict__ KV,
    float* __restrict__ Out, int Sq, int Skv)
{
    __shared__ float Ks[64 * 32];
    __shared__ float Vs[64 * 32];
    const int b = blockIdx.z, h = blockIdx.y, q0 = blockIdx.x * 32;
    const int tid = threadIdx.x;
    const int qr = tid >> 3, dg = tid & 7;
    const int d0 = dg * 4, kb = dg * 8;
    const float scale = 0.17677669529663687f;

    float4 q4[8];
    {
        const float* qrow = Q + (size_t)(b * Sq + q0 + qr) * DM + h * DH;
        #pragma unroll
        for (int d4 = 0; d4 < 8; d4++) q4[d4] = *(const float4*)(qrow + d4 * 4);
    }

    float O[4] = {0.f, 0.f, 0.f, 0.f};
    float mreg = -INFINITY, lreg = 0.f;

    for (int kv0 = 0; kv0 < Skv; kv0 += 64) {
        #pragma unroll
        for (int i = 0; i < 2; i++) {
            int e = tid + i * 256;
            int r = e >> 3, c4 = e & 7;
            const float* base = KV + (size_t)(b * Skv + kv0 + r) * 256 + h * DH + c4 * 4;
            float4 kv_ = *(const float4*)base;
            *(float4*)&Ks[r * 32 + ((c4 ^ (r >> 3)) * 4)] = kv_;
            float4 vv = *(const float4*)(base + 128);
            *(float4*)&Vs[r * 32 + c4 * 4] = vv;
        }
        __syncthreads();

        float s[8];
        #pragma unroll
        for (int j = 0; j < 8; j++) {
            float acc = 0.f;
            const float* krow = &Ks[(kb + j) * 32];
            #pragma unroll
            for (int d4 = 0; d4 < 8; d4++) {
                float4 k4 = *(const float4*)(krow + ((d4 ^ dg) * 4));
                acc += q4[d4].x * k4.x + q4[d4].y * k4.y + q4[d4].z * k4.z + q4[d4].w * k4.w;
            }
            s[j] = acc * scale;
        }
        float rmax = s[0];
        #pragma unroll
        for (int j = 1; j < 8; j++) rmax = fmaxf(rmax, s[j]);
        rmax = fmaxf(rmax, __shfl_xor_sync(0xffffffffu, rmax, 1));
        rmax = fmaxf(rmax, __shfl_xor_sync(0xffffffffu, rmax, 2));
        rmax = fmaxf(rmax, __shfl_xor_sync(0xffffffffu, rmax, 4));

        float mnew = fmaxf(mreg, rmax);
        float corr = expf(mreg - mnew);
        float p[8];
        float psum = 0.f;
        #pragma unroll
        for (int j = 0; j < 8; j++) { p[j] = expf(s[j] - mnew); psum += p[j]; }
        psum += __shfl_xor_sync(0xffffffffu, psum, 1);
        psum += __shfl_xor_sync(0xffffffffu, psum, 2);
        psum += __shfl_xor_sync(0xffffffffu, psum, 4);
        lreg = lreg * corr + psum;
        mreg = mnew;
        #pragma unroll
        for (int c = 0; c < 4; c++) O[c] *= corr;

        #pragma unroll
        for (int sl = 0; sl < 8; sl++) {
            #pragma unroll
            for (int j = 0; j < 8; j++) {
                float pv = __shfl_sync(0xffffffffu, p[j], sl, 8);
                float4 v4 = *(const float4*)&Vs[(sl * 8 + j) * 32 + d0];
                O[0] += pv * v4.x; O[1] += pv * v4.y;
                O[2] += pv * v4.z; O[3] += pv * v4.w;
            }
        }
        __syncthreads();
    }
    float inv = 1.0f / lreg;
    float* orow = Out + (size_t)(b * Sq + q0 + qr) * DM + h * DH + d0;
    orow[0] = O[0] * inv; orow[1] = O[1] * inv;
    orow[2] = O[2] * inv; orow[3] = O[3] * inv;
}

// ---------- 7) residual add + layernorm (width 128) ----------
__global__ __launch_bounds__(128) void ln_res_kernel(
    float* __restrict__ out, const float* __restrict__ a, const float* __restrict__ res,
    const float* __restrict__ g, const float* __restrict__ be)
{
    __shared__ float sh1[4], sh2[4];
    const int row = blockIdx.x, t = threadIdx.x;
    const int w = t >> 5, lane = t & 31;
    float x = a[(size_t)row * DM + t] + res[(size_t)row * DM + t];
    float s = x;
    #pragma unroll
    for (int o = 16; o > 0; o >>= 1) s += __shfl_xor_sync(0xffffffffu, s, o);
    if (lane == 0) sh1[w] = s;
    __syncthreads();
    float mu = (sh1[0] + sh1[1] + sh1[2] + sh1[3]) * (1.0f / 128.0f);
    float d = x - mu;
    float q = d * d;
    #pragma unroll
    for (int o = 16; o > 0; o >>= 1) q += __shfl_xor_sync(0xffffffffu, q, o);
    if (lane == 0) sh2[w] = q;
    __syncthreads();
    float var = (sh2[0] + sh2[1] + sh2[2] + sh2[3]) * (1.0f / 128.0f);
    out[(size_t)row * DM + t] = d * rsqrtf(var + LN_EPS) * g[t] + be[t];
}

// ---------- host ----------
extern "C" void kernel_launch(void* const* d_in, const int* in_sizes, int n_in,
                              void* d_out, int out_size)
{
    (void)in_sizes; (void)n_in; (void)out_size;
    const float* pts     = (const float*)d_in[0];
    const float* feat_w  = (const float*)d_in[2];
    const float* feat_b  = (const float*)d_in[3];
    const float* mlp_w1  = (const float*)d_in[4];
    const float* mlp_b1  = (const float*)d_in[5];
    const float* mlp_g1  = (const float*)d_in[6];
    const float* mlp_be1 = (const float*)d_in[7];
    const float* mlp_w2  = (const float*)d_in[8];
    const float* mlp_b2  = (const float*)d_in[9];
    const float* mlp_g2  = (const float*)d_in[10];
    const float* mlp_be2 = (const float*)d_in[11];
    const float* mlp_w3  = (const float*)d_in[12];
    const float* mlp_b3  = (const float*)d_in[13];
    const float* blk_in_w = (const float*)d_in[14];
    const float* blk_in_b = (const float*)d_in[15];
    const float* blk_ow   = (const float*)d_in[16];
    const float* blk_ob   = (const float*)d_in[17];
    const float* blk_g1   = (const float*)d_in[18];
    const float* blk_be1  = (const float*)d_in[19];
    const float* blk_g2   = (const float*)d_in[20];
    const float* blk_be2  = (const float*)d_in[21];
    const float* blk_f1w  = (const float*)d_in[22];
    const float* blk_f1b  = (const float*)d_in[23];
    const float* blk_f2w  = (const float*)d_in[24];
    const float* blk_f2b  = (const float*)d_in[25];
    const float* k_w = (const float*)d_in[26];
    const float* k_b = (const float*)d_in[27];
    const float* v_w = (const float*)d_in[28];
    const float* v_b = (const float*)d_in[29];
    float* out = (float*)d_out;

    float *gfeatp, *localp, *xp, *x2p, *qp, *attp, *tmpp, *kvp, *ffp, *big1p, *big2p;
    cudaGetSymbolAddress((void**)&gfeatp, g_gfeat);
    cudaGetSymbolAddress((void**)&localp, g_local);
    cudaGetSymbolAddress((void**)&xp,     g_x);
    cudaGetSymbolAddress((void**)&x2p,    g_x2);
    cudaGetSymbolAddress((void**)&qp,     g_q);
    cudaGetSymbolAddress((void**)&attp,   g_att);
    cudaGetSymbolAddress((void**)&tmpp,   g_tmp);
    cudaGetSymbolAddress((void**)&kvp,    g_kv);
    cudaGetSymbolAddress((void**)&ffp,    g_ff);
    cudaGetSymbolAddress((void**)&big1p,  g_big1);
    cudaGetSymbolAddress((void**)&big2p,  g_big2);

    cudaFuncSetAttribute(gemm_big_kernel<1,0>, cudaFuncAttributeMaxDynamicSharedMemorySize, SM_BIG);
    cudaFuncSetAttribute(gemm_big_kernel<0,0>, cudaFuncAttributeMaxDynamicSharedMemorySize, SM_BIG);
    cudaFuncSetAttribute(gemm_big_kernel<0,2>, cudaFuncAttributeMaxDynamicSharedMemorySize, SM_BIG2);

    gfeat_kernel<<<GFROWS / 128, 128>>>(pts, feat_w, feat_b);
    fps_kernel<<<BB, 512>>>(pts);
    bq_kernel<<<(BB * NS) / 8, 256>>>(pts);

    // grouped MLP as flat GEMMs over 262144 rows
    gemm_big_kernel<1,0><<<dim3(2, GMROWS / 128), 256, SM_BIG>>>(
        nullptr, mlp_w1, mlp_b1, big1p, 256, 160, 130, pts);
    ln_big_kernel<<<GMROWS / 8, 256>>>(big1p, mlp_g1, mlp_be1);
    gemm_big_kernel<0,0><<<dim3(2, GMROWS / 128), 256, SM_BIG>>>(
        big1p, mlp_w2, mlp_b2, big2p, 256, 256, 256, nullptr);
    ln_big_kernel<<<GMROWS / 8, 256>>>(big2p, mlp_g2, mlp_be2);
    gemm_big_kernel<0,2><<<dim3(1, GMROWS / 128), 256, SM_BIG2>>>(
        big2p, mlp_w3, mlp_b3, localp, 128, 256, 256, nullptr);

    for (int i = 0; i < 4; i++) {
        const float* xcur = (i == 0) ? localp : xp;
        const float* kvsrc = (i < 2) ? gfeatp : xcur;
        int Skv = (i < 2) ? NPTS : NS;
        int Mkv = BB * Skv;
        const float* wq = blk_in_w + (size_t)i * 384 * 128;
        const float* bq = blk_in_b + (size_t)i * 384;

        gemm_tc_kernel<0><<<dim3(2, SQROWS / 64), 256>>>(xcur, wq, bq, qp, SQROWS, 128, 128);
        gemm_tc_kernel<0><<<dim3(4, Mkv / 64), 256>>>(kvsrc, wq + 128 * 128, bq + 128, kvp, Mkv, 256, 128);
        flash2_kernel<<<dim3(NS / 32, NH, BB), 256>>>(qp, kvp, attp, NS, Skv);
        gemm_tc_kernel<0><<<dim3(2, SQROWS / 64), 256>>>(attp, blk_ow + (size_t)i * 128 * 128,
                                                         blk_ob + (size_t)i * 128, tmpp, SQROWS, 128, 128);
        ln_res_kernel<<<SQROWS, 128>>>(x2p, tmpp, xcur, blk_g1 + (size_t)i * 128, blk_be1 + (size_t)i * 128);
        gemm_tc_kernel<1><<<dim3(8, SQROWS / 64), 256>>>(x2p, blk_f1w + (size_t)i * 512 * 128,
                                                         blk_f1b + (size_t)i * 512, ffp, SQROWS, 512, 128);
        gemm_tc_kernel<0><<<dim3(2, SQROWS / 64), 256>>>(ffp, blk_f2w + (size_t)i * 128 * 512,
                                                         blk_f2b + (size_t)i * 128, tmpp, SQROWS, 128, 512);
        ln_res_kernel<<<SQROWS, 128>>>(xp, tmpp, x2p, blk_g2 + (size_t)i * 128, blk_be2 + (size_t)i * 128);
    }

    gemm_tc_kernel<0><<<dim3(2, SQROWS / 64), 256>>>(xp, k_w, k_b, out, SQROWS, 128, 128);
    gemm_tc_kernel<0><<<dim3(2, SQROWS / 64), 256>>>(xp, v_w, v_b, out + (size_t)SQROWS * 128, SQROWS, 128, 128);
}

// round 7
// speedup vs baseline: 2.1053x; 1.1755x over previous
#include <cuda_runtime.h>
#include <cuda_bf16.h>
#include <math.h>

#define BB      8
#define NPTS    4096
#define NS      1024
#define NP      32
#define DM      128
#define NH      4
#define DH      32
#define FFH     512
#define LN_EPS  1e-5f
#define SQROWS  (BB*NS)
#define GFROWS  (BB*NPTS)
#define GMROWS  (SQROWS*NP)      // 262144

// 3x-split gemm (transformer linears)
#define GSTR 51
// big 1x gemm (grouped MLP): 128x128 tile, 32-K chunks, 2-stage cp.async
#define BSTR 36
#define SM_BIG (4*128*BSTR*4)    // 2 stages x (A+W) = 73728 B; epilogue pool aliases this

__device__ float g_gfeat  [GFROWS * DM];
__device__ float g_gfeat_t[GFROWS * DM];
__device__ float g_cent [BB * NS * 2];
__device__ int   g_knn  [BB * NS * NP];
__device__ int   g_kcnt [BB * NS];
__device__ float g_local[SQROWS * DM];
__device__ float g_x    [SQROWS * DM];
__device__ float g_x2   [SQROWS * DM];
__device__ float g_q    [SQROWS * DM];
__device__ float g_att  [SQROWS * DM];
__device__ float g_tmp  [SQROWS * DM];
__device__ float g_kv   [GFROWS * 256];
__device__ float g_ff   [SQROWS * FFH];
__device__ float g_big1 [GMROWS * 256];
__device__ float g_big2 [GMROWS * 256];
__device__ float g_w1p  [256 * 160];
__device__ float g_w2p  [256 * 256];
__device__ float g_w3p  [128 * 256];

__device__ __forceinline__ float gelu_exact(float x) {
    return 0.5f * x * (1.0f + erff(x * 0.70710678118654752440f));
}

__device__ __forceinline__ float tf32r(float x) {
    unsigned u;
    asm("cvt.rna.tf32.f32 %0, %1;" : "=r"(u) : "f"(x));
    return __uint_as_float(u);
}

__device__ __forceinline__ void mma_tf32(float* c, unsigned a0, unsigned a1,
                                         unsigned a2, unsigned a3,
                                         unsigned b0, unsigned b1) {
    asm volatile(
        "mma.sync.aligned.m16n8k8.row.col.f32.tf32.tf32.f32 "
        "{%0,%1,%2,%3},{%4,%5,%6,%7},{%8,%9},{%0,%1,%2,%3};"
        : "+f"(c[0]), "+f"(c[1]), "+f"(c[2]), "+f"(c[3])
        : "r"(a0), "r"(a1), "r"(a2), "r"(a3), "r"(b0), "r"(b1));
}

__device__ __forceinline__ unsigned sptr(const void* p) {
    return (unsigned)__cvta_generic_to_shared(p);
}
__device__ __forceinline__ void cpa16(unsigned dst, const void* src) {
    asm volatile("cp.async.cg.shared.global [%0], [%1], 16;" :: "r"(dst), "l"(src));
}

// ---------- 1) fourier features + 26->128 projection ----------
__global__ __launch_bounds__(128) void gfeat_kernel(
    const float* __restrict__ pts, const float* __restrict__ fw, const float* __restrict__ fb)
{
    __shared__ float fsh[128 * 26];
    const int t = threadIdx.x;
    const int base = blockIdx.x * 128;
    float wreg[26];
    #pragma unroll
    for (int j = 0; j < 26; j++) wreg[j] = fw[t * 26 + j];

    const float FREQ[6] = {3.14159265358979323846f, 6.28318530717958647693f,
        12.5663706143591729539f, 25.1327412287183459077f,
        50.2654824574366918154f, 100.530964914873383631f};
    {
        float x = pts[(size_t)(base + t) * 2 + 0];
        float y = pts[(size_t)(base + t) * 2 + 1];
        fsh[t * 26 + 0] = x; fsh[t * 26 + 1] = y;
        #pragma unroll
        for (int k = 0; k < 6; k++) {
            float sx, cx, sy, cy;
            sincosf(FREQ[k] * x, &sx, &cx);
            sincosf(FREQ[k] * y, &sy, &cy);
            fsh[t*26 + 2 + 4*k + 0] = sx; fsh[t*26 + 2 + 4*k + 1] = sy;
            fsh[t*26 + 2 + 4*k + 2] = cx; fsh[t*26 + 2 + 4*k + 3] = cy;
        }
    }
    float bb = fb[t];
    __syncthreads();
    for (int p = 0; p < 128; p++) {
        float acc = bb;
        #pragma unroll
        for (int j = 0; j < 26; j++) acc += fsh[p * 26 + j] * wreg[j];
        g_gfeat  [(size_t)(base + p) * DM + t] = acc;
        g_gfeat_t[(size_t)(base + p) * DM + t] = tf32r(acc);
    }
}

// ---------- weight pre-round (padded, tf32) ----------
__global__ __launch_bounds__(256) void wprep_kernel(
    const float* __restrict__ w1, const float* __restrict__ w2, const float* __restrict__ w3)
{
    int i = blockIdx.x * 256 + threadIdx.x;
    if (i < 256 * 160) {
        int n = i / 160, k = i - n * 160;
        g_w1p[i] = (k < 130) ? tf32r(w1[n * 130 + k]) : 0.f;
    }
    int j = i - 256 * 160;
    if (j >= 0 && j < 256 * 256) g_w2p[j] = tf32r(w2[j]);
    int l = i - 256 * 160 - 256 * 256;
    if (l >= 0 && l < 128 * 256) g_w3p[l] = tf32r(w3[l]);
}

// ---------- 2) farthest point sampling ----------
__global__ __launch_bounds__(512) void fps_kernel(const float* __restrict__ pts)
{
    const int b = blockIdx.x, tid = threadIdx.x;
    const int lane = tid & 31, wid = tid >> 5;
    float px[8], py[8], dd[8];
    #pragma unroll
    for (int j = 0; j < 8; j++) {
        int p = tid + j * 512;
        px[j] = pts[((size_t)b * NPTS + p) * 2 + 0];
        py[j] = pts[((size_t)b * NPTS + p) * 2 + 1];
        dd[j] = INFINITY;
    }
    __shared__ float rv[16]; __shared__ int ri[16];
    __shared__ float rx[16], ry[16];
    __shared__ float sbx, sby;
    float lastx = pts[(size_t)b * NPTS * 2 + 0];
    float lasty = pts[(size_t)b * NPTS * 2 + 1];
    if (tid == 0) {
        g_cent[(size_t)b * NS * 2 + 0] = lastx;
        g_cent[(size_t)b * NS * 2 + 1] = lasty;
    }
    for (int it = 1; it < NS; it++) {
        float bv = -1.0f; int bi = 0x7fffffff; float bx = 0.f, by = 0.f;
        #pragma unroll
        for (int j = 0; j < 8; j++) {
            float dx = __fsub_rn(px[j], lastx);
            float dy = __fsub_rn(py[j], lasty);
            float d2 = __fadd_rn(__fmul_rn(dx, dx), __fmul_rn(dy, dy));
            dd[j] = fminf(dd[j], d2);
            if (dd[j] > bv) { bv = dd[j]; bi = tid + j * 512; bx = px[j]; by = py[j]; }
        }
        #pragma unroll
        for (int off = 16; off > 0; off >>= 1) {
            float ov = __shfl_down_sync(0xffffffffu, bv, off);
            int   oi = __shfl_down_sync(0xffffffffu, bi, off);
            float ox = __shfl_down_sync(0xffffffffu, bx, off);
            float oy = __shfl_down_sync(0xffffffffu, by, off);
            if (ov > bv || (ov == bv && oi < bi)) { bv = ov; bi = oi; bx = ox; by = oy; }
        }
        if (lane == 0) { rv[wid] = bv; ri[wid] = bi; rx[wid] = bx; ry[wid] = by; }
        __syncthreads();
        if (tid < 32) {
            if (tid < 16) { bv = rv[tid]; bi = ri[tid]; bx = rx[tid]; by = ry[tid]; }
            else          { bv = -1.0f; bi = 0x7fffffff; bx = 0.f; by = 0.f; }
            #pragma unroll
            for (int off = 8; off > 0; off >>= 1) {
                float ov = __shfl_down_sync(0xffffffffu, bv, off);
                int   oi = __shfl_down_sync(0xffffffffu, bi, off);
                float ox = __shfl_down_sync(0xffffffffu, bx, off);
                float oy = __shfl_down_sync(0xffffffffu, by, off);
                if (ov > bv || (ov == bv && oi < bi)) { bv = ov; bi = oi; bx = ox; by = oy; }
            }
            if (tid == 0) {
                g_cent[((size_t)b * NS + it) * 2 + 0] = bx;
                g_cent[((size_t)b * NS + it) * 2 + 1] = by;
                sbx = bx; sby = by;
            }
        }
        __syncthreads();
        lastx = sbx; lasty = sby;
    }
}

// ---------- 3) ball query ----------
__global__ __launch_bounds__(256) void bq_kernel(const float* __restrict__ pts)
{
    __shared__ int sknn[8][NP];
    const int gwid = (blockIdx.x * blockDim.x + threadIdx.x) >> 5;
    const int lane = threadIdx.x & 31, wl = threadIdx.x >> 5;
    if (gwid >= BB * NS) return;
    const int b = gwid >> 10;
    const float cx = g_cent[gwid * 2 + 0];
    const float cy = g_cent[gwid * 2 + 1];
    const float R2 = 0.01f;
    int cnt = 0;
    for (int c = 0; c < NPTS / 32 && cnt < NP; c++) {
        int p = c * 32 + lane;
        float dx = __fsub_rn(cx, pts[((size_t)b * NPTS + p) * 2 + 0]);
        float dy = __fsub_rn(cy, pts[((size_t)b * NPTS + p) * 2 + 1]);
        float d2 = __fadd_rn(__fmul_rn(dx, dx), __fmul_rn(dy, dy));
        bool in = d2 < R2;
        unsigned m = __ballot_sync(0xffffffffu, in);
        int before = __popc(m & ((1u << lane) - 1u));
        if (in && cnt + before < NP) sknn[wl][cnt + before] = p;
        cnt += __popc(m);
    }
    __syncwarp();
    int cc = min(cnt, NP);
    g_knn[gwid * NP + lane] = (lane < cc) ? sknn[wl][lane] : sknn[wl][0];
    if (lane == 0) g_kcnt[gwid] = cc;
}

// ---------- 4) big flat GEMM v2: cp.async double-buffered, pre-rounded tf32 inputs ----------
// MODE 0: A from global (already tf32-rounded). MODE 1: A gathered via g_knn from g_gfeat_t.
// EPI  0: C=acc+bias.  EPI 2: masked 32-row max-pool into g_local (pool buffer aliases stages).
template<int MODE, int EPI>
__global__ __launch_bounds__(256, 2) void gemm_big2_kernel(
    const float* __restrict__ A, const float* __restrict__ W,
    const float* __restrict__ bias, float* __restrict__ C,
    int N, int K, const float* __restrict__ pts)
{
    extern __shared__ float sm[];
    float* sA = sm;                     // 2 x 128 x BSTR
    float* sW = sm + 2 * 128 * BSTR;    // 2 x 128 x BSTR
    float* sE = sm;                     // EPI2 pool buffer (aliases stages, used after MMAs)
    __shared__ int   sIdx[128];
    __shared__ float sRx[128], sRy[128];
    __shared__ int   sCnt[4];

    const int tid = threadIdx.x;
    const int w = tid >> 5, lane = tid & 31;
    const int g = lane >> 2, q = lane & 3;
    const int wm = w & 3, wn = w >> 2;
    const int m0 = blockIdx.y * 128, n0 = blockIdx.x * 128;
    const int b_batch = m0 >> 15;
    const int NC = K >> 5;

    if (MODE == 1) {
        if (tid < 128) {
            int m = m0 + tid;
            int grp = m >> 5;
            int idx = g_knn[grp * NP + (m & 31)];
            sIdx[tid] = idx;
            float cx = g_cent[grp * 2 + 0], cy = g_cent[grp * 2 + 1];
            const float* pp = pts + ((size_t)b_batch * NPTS + idx) * 2;
            sRx[tid] = pp[0] - cx;
            sRy[tid] = pp[1] - cy;
        }
    }
    if (EPI == 2) {
        if (tid < 4) sCnt[tid] = g_kcnt[(m0 >> 5) + tid];
    }
    __syncthreads();   // sIdx/sRx/sRy/sCnt ready before any prefetch

    auto prefetch = [&](int c) {
        int bi = c & 1;
        float* dA = sA + bi * 128 * BSTR;
        float* dW = sW + bi * 128 * BSTR;
        int k0 = c * 32;
        if (MODE == 1 && k0 >= 128) {
            // rel-xyz + zero-pad chunk (cols 128..159), plain stores
            #pragma unroll
            for (int j = 0; j < 16; j++) {
                int e = tid + j * 256;
                int r = e >> 5, kk = e & 31;
                float v = (kk == 0) ? tf32r(sRx[r]) : (kk == 1) ? tf32r(sRy[r]) : 0.f;
                dA[r * BSTR + kk] = v;
            }
        } else {
            #pragma unroll
            for (int j = 0; j < 4; j++) {
                int e = tid + j * 256;
                int r = e >> 3, ch = e & 7;
                const float* src;
                if (MODE == 1) src = A + ((size_t)b_batch * NPTS + sIdx[r]) * DM + k0 + ch * 4;
                else           src = A + (size_t)(m0 + r) * K + k0 + ch * 4;
                cpa16(sptr(dA + r * BSTR + ch * 4), src);
            }
        }
        #pragma unroll
        for (int j = 0; j < 4; j++) {
            int e = tid + j * 256;
            int r = e >> 3, ch = e & 7;
            cpa16(sptr(dW + r * BSTR + ch * 4), W + (size_t)(n0 + r) * K + k0 + ch * 4);
        }
        asm volatile("cp.async.commit_group;" ::: "memory");
    };

    float acc[2][8][4];
    #pragma unroll
    for (int mf = 0; mf < 2; mf++)
        #pragma unroll
        for (int nf = 0; nf < 8; nf++) { acc[mf][nf][0]=acc[mf][nf][1]=acc[mf][nf][2]=acc[mf][nf][3]=0.f; }

    prefetch(0);
    prefetch(1);

    for (int c = 0; c < NC; c++) {
        if (c == NC - 1) asm volatile("cp.async.wait_group 0;" ::: "memory");
        else             asm volatile("cp.async.wait_group 1;" ::: "memory");
        __syncthreads();
        int bi = c & 1;
        const float* bA = sA + bi * 128 * BSTR;
        const float* bW = sW + bi * 128 * BSTR;
        #pragma unroll
        for (int ks = 0; ks < 4; ks++) {
            int kp = ks * 8;
            unsigned a[2][4];
            #pragma unroll
            for (int mf = 0; mf < 2; mf++) {
                int mb = wm * 32 + mf * 16;
                a[mf][0] = __float_as_uint(bA[(mb + g) * BSTR + kp + q]);
                a[mf][1] = __float_as_uint(bA[(mb + g + 8) * BSTR + kp + q]);
                a[mf][2] = __float_as_uint(bA[(mb + g) * BSTR + kp + q + 4]);
                a[mf][3] = __float_as_uint(bA[(mb + g + 8) * BSTR + kp + q + 4]);
            }
            #pragma unroll
            for (int nf = 0; nf < 8; nf++) {
                int nb = wn * 64 + nf * 8;
                unsigned b0 = __float_as_uint(bW[(nb + g) * BSTR + kp + q]);
                unsigned b1 = __float_as_uint(bW[(nb + g) * BSTR + kp + q + 4]);
                mma_tf32(acc[0][nf], a[0][0], a[0][1], a[0][2], a[0][3], b0, b1);
                mma_tf32(acc[1][nf], a[1][0], a[1][1], a[1][2], a[1][3], b0, b1);
            }
        }
        __syncthreads();
        if (c + 2 < NC) prefetch(c + 2);
    }

    if (EPI != 2) {
        #pragma unroll
        for (int mf = 0; mf < 2; mf++) {
            int rb = m0 + wm * 32 + mf * 16;
            #pragma unroll
            for (int nf = 0; nf < 8; nf++) {
                int colg = n0 + wn * 64 + nf * 8 + 2 * q;
                float bia = __ldg(&bias[colg]), bib = __ldg(&bias[colg + 1]);
                C[(size_t)(rb + g) * N + colg]         = acc[mf][nf][0] + bia;
                C[(size_t)(rb + g) * N + colg + 1]     = acc[mf][nf][1] + bib;
                C[(size_t)(rb + g + 8) * N + colg]     = acc[mf][nf][2] + bia;
                C[(size_t)(rb + g + 8) * N + colg + 1] = acc[mf][nf][3] + bib;
            }
        }
    } else {
        // pool buffer aliases the stage buffers — all MMA reads are done
        #pragma unroll
        for (int mf = 0; mf < 2; mf++) {
            int rb = wm * 32 + mf * 16;
            #pragma unroll
            for (int nf = 0; nf < 8; nf++) {
                int colg = wn * 64 + nf * 8 + 2 * q;
                float bia = __ldg(&bias[colg]), bib = __ldg(&bias[colg + 1]);
                sE[(rb + g) * 132 + colg]         = acc[mf][nf][0] + bia;
                sE[(rb + g) * 132 + colg + 1]     = acc[mf][nf][1] + bib;
                sE[(rb + g + 8) * 132 + colg]     = acc[mf][nf][2] + bia;
                sE[(rb + g + 8) * 132 + colg + 1] = acc[mf][nf][3] + bib;
            }
        }
        __syncthreads();
        #pragma unroll
        for (int pass = 0; pass < 2; pass++) {
            int grp = (tid >> 7) + pass * 2;
            int col = tid & 127;
            int cnt = sCnt[grp];
            float mx = sE[(grp * 32) * 132 + col];
            for (int r = 1; r < cnt; r++) mx = fmaxf(mx, sE[(grp * 32 + r) * 132 + col]);
            C[(size_t)((m0 >> 5) + grp) * DM + col] = mx;
        }
    }
}

// ---------- LN + GELU over 256-wide rows (warp per row), tf32-rounded output ----------
__global__ __launch_bounds__(256) void ln_big_kernel(
    float* __restrict__ H, const float* __restrict__ g, const float* __restrict__ be)
{
    const int row = blockIdx.x * 8 + (threadIdx.x >> 5);
    const int lane = threadIdx.x & 31;
    float4* hp = (float4*)(H + (size_t)row * 256);
    float4 x0 = hp[lane * 2], x1 = hp[lane * 2 + 1];
    float s = x0.x + x0.y + x0.z + x0.w + x1.x + x1.y + x1.z + x1.w;
    #pragma unroll
    for (int o = 16; o > 0; o >>= 1) s += __shfl_xor_sync(0xffffffffu, s, o);
    float mu = s * (1.0f / 256.0f);
    float v = 0.f;
    {
        float d;
        d = x0.x - mu; v += d * d; d = x0.y - mu; v += d * d;
        d = x0.z - mu; v += d * d; d = x0.w - mu; v += d * d;
        d = x1.x - mu; v += d * d; d = x1.y - mu; v += d * d;
        d = x1.z - mu; v += d * d; d = x1.w - mu; v += d * d;
    }
    #pragma unroll
    for (int o = 16; o > 0; o >>= 1) v += __shfl_xor_sync(0xffffffffu, v, o);
    float inv = rsqrtf(v * (1.0f / 256.0f) + LN_EPS);
    int c0 = lane * 8;
    float4 gg0 = *(const float4*)(g + c0),  gg1 = *(const float4*)(g + c0 + 4);
    float4 bb0 = *(const float4*)(be + c0), bb1 = *(const float4*)(be + c0 + 4);
    x0.x = tf32r(gelu_exact((x0.x - mu) * inv * gg0.x + bb0.x));
    x0.y = tf32r(gelu_exact((x0.y - mu) * inv * gg0.y + bb0.y));
    x0.z = tf32r(gelu_exact((x0.z - mu) * inv * gg0.z + bb0.z));
    x0.w = tf32r(gelu_exact((x0.w - mu) * inv * gg0.w + bb0.w));
    x1.x = tf32r(gelu_exact((x1.x - mu) * inv * gg1.x + bb1.x));
    x1.y = tf32r(gelu_exact((x1.y - mu) * inv * gg1.y + bb1.y));
    x1.z = tf32r(gelu_exact((x1.z - mu) * inv * gg1.z + bb1.z));
    x1.w = tf32r(gelu_exact((x1.w - mu) * inv * gg1.w + bb1.w));
    hp[lane * 2] = x0; hp[lane * 2 + 1] = x1;
}

// ---------- 5) tensor-core GEMM, 3xTF32 split (transformer linears) ----------
template<int EPI>  // 0 none, 1 gelu
__global__ __launch_bounds__(256) void gemm_tc_kernel(
    const float* __restrict__ A, const float* __restrict__ W,
    const float* __restrict__ bias, float* __restrict__ C,
    int M, int Nc, int K)
{
    __shared__ float sA[64 * GSTR];
    __shared__ float sW[64 * GSTR];
    const int tid = threadIdx.x;
    const int w = tid >> 5, lane = tid & 31;
    const int g = lane >> 2, q = lane & 3;
    const int wm = w & 3, wn = w >> 2;
    const int mrow = wm * 16;
    const int m0 = blockIdx.y * 64, n0 = blockIdx.x * 64;

    float acc[4][4];
    #pragma unroll
    for (int nf = 0; nf < 4; nf++) { acc[nf][0]=acc[nf][1]=acc[nf][2]=acc[nf][3]=0.f; }

    for (int k0 = 0; k0 < K; k0 += 16) {
        #pragma unroll
        for (int j = 0; j < 4; j++) {
            int e = tid + j * 256;
            int r = e >> 4, kk = e & 15;
            float x = A[(size_t)(m0 + r) * K + k0 + kk];
            float hi = tf32r(x);
            float lo = tf32r(x - hi);
            float* p = &sA[r * GSTR + 3 * kk];
            p[0] = hi; p[1] = hi; p[2] = lo;
            float y = W[(size_t)(n0 + r) * K + k0 + kk];
            float whi = tf32r(y);
            float wlo = tf32r(y - whi);
            float* pw = &sW[r * GSTR + 3 * kk];
            pw[0] = whi; pw[1] = wlo; pw[2] = whi;
        }
        __syncthreads();
        #pragma unroll
        for (int ks = 0; ks < 6; ks++) {
            int kp = ks * 8;
            unsigned a0 = __float_as_uint(sA[(mrow + g) * GSTR + kp + q]);
            unsigned a1 = __float_as_uint(sA[(mrow + g + 8) * GSTR + kp + q]);
            unsigned a2 = __float_as_uint(sA[(mrow + g) * GSTR + kp + q + 4]);
            unsigned a3 = __float_as_uint(sA[(mrow + g + 8) * GSTR + kp + q + 4]);
            #pragma unroll
            for (int nf = 0; nf < 4; nf++) {
                int nb = wn * 32 + nf * 8;
                unsigned b0 = __float_as_uint(sW[(nb + g) * GSTR + kp + q]);
                unsigned b1 = __float_as_uint(sW[(nb + g) * GSTR + kp + q + 4]);
                mma_tf32(acc[nf], a0, a1, a2, a3, b0, b1);
            }
        }
        __syncthreads();
    }

    #pragma unroll
    for (int nf = 0; nf < 4; nf++) {
        int colg = n0 + wn * 32 + nf * 8 + 2 * q;
        float bia = __ldg(&bias[colg]), bib = __ldg(&bias[colg + 1]);
        float v00 = acc[nf][0] + bia, v01 = acc[nf][1] + bib;
        float v10 = acc[nf][2] + bia, v11 = acc[nf][3] + bib;
        if (EPI == 1) {
            v00 = gelu_exact(v00); v01 = gelu_exact(v01);
            v10 = gelu_exact(v10); v11 = gelu_exact(v11);
        }
        C[(size_t)(m0 + mrow + g) * Nc + colg]         = v00;
        C[(size_t)(m0 + mrow + g) * Nc + colg + 1]     = v01;
        C[(size_t)(m0 + mrow + g + 8) * Nc + colg]     = v10;
        C[(size_t)(m0 + mrow + g + 8) * Nc + colg + 1] = v11;
    }
}

// ---------- 6) flash attention (fp32, reg-Q, swizzled K, shfl-P) ----------
__global__ __launch_bounds__(256) void flash2_kernel(
    const float* __restrict__ Q, const float* __restrict__ KV,
    float* __restrict__ Out, int Sq, int Skv)
{
    __shared__ float Ks[64 * 32];
    __shared__ float Vs[64 * 32];
    const int b = blockIdx.z, h = blockIdx.y, q0 = blockIdx.x * 32;
    const int tid = threadIdx.x;
    const int qr = tid >> 3, dg = tid & 7;
    const int d0 = dg * 4, kb = dg * 8;
    const float scale = 0.17677669529663687f;

    float4 q4[8];
    {
        const float* qrow = Q + (size_t)(b * Sq + q0 + qr) * DM + h * DH;
        #pragma unroll
        for (int d4 = 0; d4 < 8; d4++) q4[d4] = *(const float4*)(qrow + d4 * 4);
    }

    float O[4] = {0.f, 0.f, 0.f, 0.f};
    float mreg = -INFINITY, lreg = 0.f;

    for (int kv0 = 0; kv0 < Skv; kv0 += 64) {
        #pragma unroll
        for (int i = 0; i < 2; i++) {
            int e = tid + i * 256;
            int r = e >> 3, c4 = e & 7;
            const float* base = KV + (size_t)(b * Skv + kv0 + r) * 256 + h * DH + c4 * 4;
            float4 kv_ = *(const float4*)base;
            *(float4*)&Ks[r * 32 + ((c4 ^ (r >> 3)) * 4)] = kv_;
            float4 vv = *(const float4*)(base + 128);
            *(float4*)&Vs[r * 32 + c4 * 4] = vv;
        }
        __syncthreads();

        float s[8];
        #pragma unroll
        for (int j = 0; j < 8; j++) {
            float acc = 0.f;
            const float* krow = &Ks[(kb + j) * 32];
            #pragma unroll
            for (int d4 = 0; d4 < 8; d4++) {
                float4 k4 = *(const float4*)(krow + ((d4 ^ dg) * 4));
                acc += q4[d4].x * k4.x + q4[d4].y * k4.y + q4[d4].z * k4.z + q4[d4].w * k4.w;
            }
            s[j] = acc * scale;
        }
        float rmax = s[0];
        #pragma unroll
        for (int j = 1; j < 8; j++) rmax = fmaxf(rmax, s[j]);
        rmax = fmaxf(rmax, __shfl_xor_sync(0xffffffffu, rmax, 1));
        rmax = fmaxf(rmax, __shfl_xor_sync(0xffffffffu, rmax, 2));
        rmax = fmaxf(rmax, __shfl_xor_sync(0xffffffffu, rmax, 4));

        float mnew = fmaxf(mreg, rmax);
        float corr = expf(mreg - mnew);
        float p[8];
        float psum = 0.f;
        #pragma unroll
        for (int j = 0; j < 8; j++) { p[j] = expf(s[j] - mnew); psum += p[j]; }
        psum += __shfl_xor_sync(0xffffffffu, psum, 1);
        psum += __shfl_xor_sync(0xffffffffu, psum, 2);
        psum += __shfl_xor_sync(0xffffffffu, psum, 4);
        lreg = lreg * corr + psum;
        mreg = mnew;
        #pragma unroll
        for (int c = 0; c < 4; c++) O[c] *= corr;

        #pragma unroll
        for (int sl = 0; sl < 8; sl++) {
            #pragma unroll
            for (int j = 0; j < 8; j++) {
                float pv = __shfl_sync(0xffffffffu, p[j], sl, 8);
                float4 v4 = *(const float4*)&Vs[(sl * 8 + j) * 32 + d0];
                O[0] += pv * v4.x; O[1] += pv * v4.y;
                O[2] += pv * v4.z; O[3] += pv * v4.w;
            }
        }
        __syncthreads();
    }
    float inv = 1.0f / lreg;
    float* orow = Out + (size_t)(b * Sq + q0 + qr) * DM + h * DH + d0;
    orow[0] = O[0] * inv; orow[1] = O[1] * inv;
    orow[2] = O[2] * inv; orow[3] = O[3] * inv;
}

// ---------- 7) residual add + layernorm (width 128) ----------
__global__ __launch_bounds__(128) void ln_res_kernel(
    float* __restrict__ out, const float* __restrict__ a, const float* __restrict__ res,
    const float* __restrict__ g, const float* __restrict__ be)
{
    __shared__ float sh1[4], sh2[4];
    const int row = blockIdx.x, t = threadIdx.x;
    const int w = t >> 5, lane = t & 31;
    float x = a[(size_t)row * DM + t] + res[(size_t)row * DM + t];
    float s = x;
    #pragma unroll
    for (int o = 16; o > 0; o >>= 1) s += __shfl_xor_sync(0xffffffffu, s, o);
    if (lane == 0) sh1[w] = s;
    __syncthreads();
    float mu = (sh1[0] + sh1[1] + sh1[2] + sh1[3]) * (1.0f / 128.0f);
    float d = x - mu;
    float q = d * d;
    #pragma unroll
    for (int o = 16; o > 0; o >>= 1) q += __shfl_xor_sync(0xffffffffu, q, o);
    if (lane == 0) sh2[w] = q;
    __syncthreads();
    float var = (sh2[0] + sh2[1] + sh2[2] + sh2[3]) * (1.0f / 128.0f);
    out[(size_t)row * DM + t] = d * rsqrtf(var + LN_EPS) * g[t] + be[t];
}

// ---------- host ----------
extern "C" void kernel_launch(void* const* d_in, const int* in_sizes, int n_in,
                              void* d_out, int out_size)
{
    (void)in_sizes; (void)n_in; (void)out_size;
    const float* pts     = (const float*)d_in[0];
    const float* feat_w  = (const float*)d_in[2];
    const float* feat_b  = (const float*)d_in[3];
    const float* mlp_w1  = (const float*)d_in[4];
    const float* mlp_b1  = (const float*)d_in[5];
    const float* mlp_g1  = (const float*)d_in[6];
    const float* mlp_be1 = (const float*)d_in[7];
    const float* mlp_w2  = (const float*)d_in[8];
    const float* mlp_b2  = (const float*)d_in[9];
    const float* mlp_g2  = (const float*)d_in[10];
    const float* mlp_be2 = (const float*)d_in[11];
    const float* mlp_w3  = (const float*)d_in[12];
    const float* mlp_b3  = (const float*)d_in[13];
    const float* blk_in_w = (const float*)d_in[14];
    const float* blk_in_b = (const float*)d_in[15];
    const float* blk_ow   = (const float*)d_in[16];
    const float* blk_ob   = (const float*)d_in[17];
    const float* blk_g1   = (const float*)d_in[18];
    const float* blk_be1  = (const float*)d_in[19];
    const float* blk_g2   = (const float*)d_in[20];
    const float* blk_be2  = (const float*)d_in[21];
    const float* blk_f1w  = (const float*)d_in[22];
    const float* blk_f1b  = (const float*)d_in[23];
    const float* blk_f2w  = (const float*)d_in[24];
    const float* blk_f2b  = (const float*)d_in[25];
    const float* k_w = (const float*)d_in[26];
    const float* k_b = (const float*)d_in[27];
    const float* v_w = (const float*)d_in[28];
    const float* v_b = (const float*)d_in[29];
    float* out = (float*)d_out;

    float *gfeatp, *gfeattp, *localp, *xp, *x2p, *qp, *attp, *tmpp, *kvp, *ffp, *big1p, *big2p;
    float *w1pp, *w2pp, *w3pp;
    cudaGetSymbolAddress((void**)&gfeatp,  g_gfeat);
    cudaGetSymbolAddress((void**)&gfeattp, g_gfeat_t);
    cudaGetSymbolAddress((void**)&localp, g_local);
    cudaGetSymbolAddress((void**)&xp,     g_x);
    cudaGetSymbolAddress((void**)&x2p,    g_x2);
    cudaGetSymbolAddress((void**)&qp,     g_q);
    cudaGetSymbolAddress((void**)&attp,   g_att);
    cudaGetSymbolAddress((void**)&tmpp,   g_tmp);
    cudaGetSymbolAddress((void**)&kvp,    g_kv);
    cudaGetSymbolAddress((void**)&ffp,    g_ff);
    cudaGetSymbolAddress((void**)&big1p,  g_big1);
    cudaGetSymbolAddress((void**)&big2p,  g_big2);
    cudaGetSymbolAddress((void**)&w1pp,   g_w1p);
    cudaGetSymbolAddress((void**)&w2pp,   g_w2p);
    cudaGetSymbolAddress((void**)&w3pp,   g_w3p);

    cudaFuncSetAttribute(gemm_big2_kernel<1,0>, cudaFuncAttributeMaxDynamicSharedMemorySize, SM_BIG);
    cudaFuncSetAttribute(gemm_big2_kernel<0,0>, cudaFuncAttributeMaxDynamicSharedMemorySize, SM_BIG);
    cudaFuncSetAttribute(gemm_big2_kernel<0,2>, cudaFuncAttributeMaxDynamicSharedMemorySize, SM_BIG);

    gfeat_kernel<<<GFROWS / 128, 128>>>(pts, feat_w, feat_b);
    wprep_kernel<<<544, 256>>>(mlp_w1, mlp_w2, mlp_w3);
    fps_kernel<<<BB, 512>>>(pts);
    bq_kernel<<<(BB * NS) / 8, 256>>>(pts);

    // grouped MLP as flat pipelined GEMMs over 262144 rows
    gemm_big2_kernel<1,0><<<dim3(2, GMROWS / 128), 256, SM_BIG>>>(
        gfeattp, w1pp, mlp_b1, big1p, 256, 160, pts);
    ln_big_kernel<<<GMROWS / 8, 256>>>(big1p, mlp_g1, mlp_be1);
    gemm_big2_kernel<0,0><<<dim3(2, GMROWS / 128), 256, SM_BIG>>>(
        big1p, w2pp, mlp_b2, big2p, 256, 256, nullptr);
    ln_big_kernel<<<GMROWS / 8, 256>>>(big2p, mlp_g2, mlp_be2);
    gemm_big2_kernel<0,2><<<dim3(1, GMROWS / 128), 256, SM_BIG>>>(
        big2p, w3pp, mlp_b3, localp, 128, 256, nullptr);

    for (int i = 0; i < 4; i++) {
        const float* xcur = (i == 0) ? localp : xp;
        const float* kvsrc = (i < 2) ? gfeatp : xcur;
        int Skv = (i < 2) ? NPTS : NS;
        int Mkv = BB * Skv;
        const float* wq = blk_in_w + (size_t)i * 384 * 128;
        const float* bq = blk_in_b + (size_t)i * 384;

        gemm_tc_kernel<0><<<dim3(2, SQROWS / 64), 256>>>(xcur, wq, bq, qp, SQROWS, 128, 128);
        gemm_tc_kernel<0><<<dim3(4, Mkv / 64), 256>>>(kvsrc, wq + 128 * 128, bq + 128, kvp, Mkv, 256, 128);
        flash2_kernel<<<dim3(NS / 32, NH, BB), 256>>>(qp, kvp, attp, NS, Skv);
        gemm_tc_kernel<0><<<dim3(2, SQROWS / 64), 256>>>(attp, blk_ow + (size_t)i * 128 * 128,
                                                         blk_ob + (size_t)i * 128, tmpp, SQROWS, 128, 128);
        ln_res_kernel<<<SQROWS, 128>>>(x2p, tmpp, xcur, blk_g1 + (size_t)i * 128, blk_be1 + (size_t)i * 128);
        gemm_tc_kernel<1><<<dim3(8, SQROWS / 64), 256>>>(x2p, blk_f1w + (size_t)i * 512 * 128,
                                                         blk_f1b + (size_t)i * 512, ffp, SQROWS, 512, 128);
        gemm_tc_kernel<0><<<dim3(2, SQROWS / 64), 256>>>(ffp, blk_f2w + (size_t)i * 128 * 512,
                                                         blk_f2b + (size_t)i * 128, tmpp, SQROWS, 128, 512);
        ln_res_kernel<<<SQROWS, 128>>>(xp, tmpp, x2p, blk_g2 + (size_t)i * 128, blk_be2 + (size_t)i * 128);
    }

    gemm_tc_kernel<0><<<dim3(2, SQROWS / 64), 256>>>(xp, k_w, k_b, out, SQROWS, 128, 128);
    gemm_tc_kernel<0><<<dim3(2, SQROWS / 64), 256>>>(xp, v_w, v_b, out + (size_t)SQROWS * 128, SQROWS, 128, 128);
}

// round 8
// speedup vs baseline: 2.1513x; 1.0219x over previous
#include <cuda_runtime.h>
#include <cuda_bf16.h>
#include <math.h>

#define BB      8
#define NPTS    4096
#define NS      1024
#define NP      32
#define DM      128
#define NH      4
#define DH      32
#define FFH     512
#define LN_EPS  1e-5f
#define SQROWS  (BB*NS)
#define GFROWS  (BB*NPTS)
#define GMROWS  (SQROWS*NP)      // 262144

// big pipelined gemm: 128x128 tile, 32-K chunks, 2-stage cp.async
#define BSTR 36
#define SM_BIG (4*128*BSTR*4)    // 73728 B; epilogue pool aliases this

__device__ float g_gfeat_t[GFROWS * DM];        // single-tf32 gfeat (MLP gather)
__device__ float g_gfeat3 [GFROWS * 384];       // tripled gfeat (cross-attn KV input)
__device__ float g_cent [BB * NS * 2];
__device__ int   g_knn  [BB * NS * NP];
__device__ int   g_kcnt [BB * NS];
__device__ float g_local [SQROWS * DM];
__device__ float g_local3[SQROWS * 384];
__device__ float g_x    [SQROWS * DM];
__device__ float g_x3   [SQROWS * 384];
__device__ float g_x2   [SQROWS * DM];
__device__ float g_x23  [SQROWS * 384];
__device__ float g_q    [SQROWS * DM];
__device__ float g_att3 [SQROWS * 384];
__device__ float g_tmp  [SQROWS * DM];
__device__ float g_kv   [GFROWS * 256];
__device__ float g_ff3  [SQROWS * 1536];
__device__ float g_big1 [GMROWS * 256];
__device__ float g_big2 [GMROWS * 256];
// pre-rounded / pre-split weights
__device__ float g_w1p  [256 * 160];
__device__ float g_w2p  [256 * 256];
__device__ float g_w3p  [128 * 256];
__device__ float g_inw3 [4 * 384 * 384];
__device__ float g_ow3  [4 * 128 * 384];
__device__ float g_f1w3 [4 * 512 * 384];
__device__ float g_f2w3 [4 * 128 * 1536];
__device__ float g_kvw3 [256 * 384];

__device__ __forceinline__ float gelu_exact(float x) {
    return 0.5f * x * (1.0f + erff(x * 0.70710678118654752440f));
}
__device__ __forceinline__ float tf32r(float x) {
    unsigned u;
    asm("cvt.rna.tf32.f32 %0, %1;" : "=r"(u) : "f"(x));
    return __uint_as_float(u);
}
__device__ __forceinline__ void triA(float* d, float x) {   // A-side [hi,hi,lo]
    float hi = tf32r(x), lo = tf32r(x - hi);
    d[0] = hi; d[1] = hi; d[2] = lo;
}
__device__ __forceinline__ void triB(float* d, float x) {   // B-side [hi,lo,hi]
    float hi = tf32r(x), lo = tf32r(x - hi);
    d[0] = hi; d[1] = lo; d[2] = hi;
}
__device__ __forceinline__ void mma_tf32(float* c, unsigned a0, unsigned a1,
                                         unsigned a2, unsigned a3,
                                         unsigned b0, unsigned b1) {
    asm volatile(
        "mma.sync.aligned.m16n8k8.row.col.f32.tf32.tf32.f32 "
        "{%0,%1,%2,%3},{%4,%5,%6,%7},{%8,%9},{%0,%1,%2,%3};"
        : "+f"(c[0]), "+f"(c[1]), "+f"(c[2]), "+f"(c[3])
        : "r"(a0), "r"(a1), "r"(a2), "r"(a3), "r"(b0), "r"(b1));
}
__device__ __forceinline__ unsigned sptr(const void* p) {
    return (unsigned)__cvta_generic_to_shared(p);
}
__device__ __forceinline__ void cpa16(unsigned dst, const void* src) {
    asm volatile("cp.async.cg.shared.global [%0], [%1], 16;" :: "r"(dst), "l"(src));
}

// ---------- 1) fourier features + 26->128 projection ----------
__global__ __launch_bounds__(128) void gfeat_kernel(
    const float* __restrict__ pts, const float* __restrict__ fw, const float* __restrict__ fb)
{
    __shared__ float fsh[128 * 26];
    const int t = threadIdx.x;
    const int base = blockIdx.x * 128;
    float wreg[26];
    #pragma unroll
    for (int j = 0; j < 26; j++) wreg[j] = fw[t * 26 + j];

    const float FREQ[6] = {3.14159265358979323846f, 6.28318530717958647693f,
        12.5663706143591729539f, 25.1327412287183459077f,
        50.2654824574366918154f, 100.530964914873383631f};
    {
        float x = pts[(size_t)(base + t) * 2 + 0];
        float y = pts[(size_t)(base + t) * 2 + 1];
        fsh[t * 26 + 0] = x; fsh[t * 26 + 1] = y;
        #pragma unroll
        for (int k = 0; k < 6; k++) {
            float sx, cx, sy, cy;
            sincosf(FREQ[k] * x, &sx, &cx);
            sincosf(FREQ[k] * y, &sy, &cy);
            fsh[t*26 + 2 + 4*k + 0] = sx; fsh[t*26 + 2 + 4*k + 1] = sy;
            fsh[t*26 + 2 + 4*k + 2] = cx; fsh[t*26 + 2 + 4*k + 3] = cy;
        }
    }
    float bb = fb[t];
    __syncthreads();
    for (int p = 0; p < 128; p++) {
        float acc = bb;
        #pragma unroll
        for (int j = 0; j < 26; j++) acc += fsh[p * 26 + j] * wreg[j];
        size_t row = (size_t)(base + p);
        g_gfeat_t[row * DM + t] = tf32r(acc);
        triA(&g_gfeat3[row * 384 + 3 * t], acc);
    }
}

// ---------- MLP weight pre-round (padded, tf32) ----------
__global__ __launch_bounds__(256) void wprep_kernel(
    const float* __restrict__ w1, const float* __restrict__ w2, const float* __restrict__ w3)
{
    int i = blockIdx.x * 256 + threadIdx.x;
    if (i < 256 * 160) {
        int n = i / 160, k = i - n * 160;
        g_w1p[i] = (k < 130) ? tf32r(w1[n * 130 + k]) : 0.f;
    }
    int j = i - 256 * 160;
    if (j >= 0 && j < 256 * 256) g_w2p[j] = tf32r(w2[j]);
    int l = i - 256 * 160 - 256 * 256;
    if (l >= 0 && l < 128 * 256) g_w3p[l] = tf32r(w3[l]);
}

// ---------- transformer weight triple-split ----------
__global__ __launch_bounds__(256) void wprep2_kernel(
    const float* __restrict__ inw, const float* __restrict__ ow,
    const float* __restrict__ f1w, const float* __restrict__ f2w,
    const float* __restrict__ kw, const float* __restrict__ vw)
{
    int i = blockIdx.x * 256 + threadIdx.x;
    if (i < 1536 * 128) { int r = i >> 7, k = i & 127; triB(&g_inw3[(size_t)r * 384 + 3 * k], inw[i]); return; }
    i -= 1536 * 128;
    if (i < 512 * 128)  { int r = i >> 7, k = i & 127; triB(&g_ow3 [(size_t)r * 384 + 3 * k], ow[i]);  return; }
    i -= 512 * 128;
    if (i < 2048 * 128) { int r = i >> 7, k = i & 127; triB(&g_f1w3[(size_t)r * 384 + 3 * k], f1w[i]); return; }
    i -= 2048 * 128;
    if (i < 512 * 512)  { int r = i >> 9, k = i & 511; triB(&g_f2w3[(size_t)r * 1536 + 3 * k], f2w[i]); return; }
    i -= 512 * 512;
    if (i < 128 * 128)  { int r = i >> 7, k = i & 127; triB(&g_kvw3[(size_t)r * 384 + 3 * k], kw[i]); return; }
    i -= 128 * 128;
    if (i < 128 * 128)  { int r = i >> 7, k = i & 127; triB(&g_kvw3[(size_t)(128 + r) * 384 + 3 * k], vw[i]); return; }
}

// ---------- 2) farthest point sampling ----------
__global__ __launch_bounds__(512) void fps_kernel(const float* __restrict__ pts)
{
    const int b = blockIdx.x, tid = threadIdx.x;
    const int lane = tid & 31, wid = tid >> 5;
    float px[8], py[8], dd[8];
    #pragma unroll
    for (int j = 0; j < 8; j++) {
        int p = tid + j * 512;
        px[j] = pts[((size_t)b * NPTS + p) * 2 + 0];
        py[j] = pts[((size_t)b * NPTS + p) * 2 + 1];
        dd[j] = INFINITY;
    }
    __shared__ float rv[16]; __shared__ int ri[16];
    __shared__ float rx[16], ry[16];
    __shared__ float sbx, sby;
    float lastx = pts[(size_t)b * NPTS * 2 + 0];
    float lasty = pts[(size_t)b * NPTS * 2 + 1];
    if (tid == 0) {
        g_cent[(size_t)b * NS * 2 + 0] = lastx;
        g_cent[(size_t)b * NS * 2 + 1] = lasty;
    }
    for (int it = 1; it < NS; it++) {
        float bv = -1.0f; int bi = 0x7fffffff; float bx = 0.f, by = 0.f;
        #pragma unroll
        for (int j = 0; j < 8; j++) {
            float dx = __fsub_rn(px[j], lastx);
            float dy = __fsub_rn(py[j], lasty);
            float d2 = __fadd_rn(__fmul_rn(dx, dx), __fmul_rn(dy, dy));
            dd[j] = fminf(dd[j], d2);
            if (dd[j] > bv) { bv = dd[j]; bi = tid + j * 512; bx = px[j]; by = py[j]; }
        }
        #pragma unroll
        for (int off = 16; off > 0; off >>= 1) {
            float ov = __shfl_down_sync(0xffffffffu, bv, off);
            int   oi = __shfl_down_sync(0xffffffffu, bi, off);
            float ox = __shfl_down_sync(0xffffffffu, bx, off);
            float oy = __shfl_down_sync(0xffffffffu, by, off);
            if (ov > bv || (ov == bv && oi < bi)) { bv = ov; bi = oi; bx = ox; by = oy; }
        }
        if (lane == 0) { rv[wid] = bv; ri[wid] = bi; rx[wid] = bx; ry[wid] = by; }
        __syncthreads();
        if (tid < 32) {
            if (tid < 16) { bv = rv[tid]; bi = ri[tid]; bx = rx[tid]; by = ry[tid]; }
            else          { bv = -1.0f; bi = 0x7fffffff; bx = 0.f; by = 0.f; }
            #pragma unroll
            for (int off = 8; off > 0; off >>= 1) {
                float ov = __shfl_down_sync(0xffffffffu, bv, off);
                int   oi = __shfl_down_sync(0xffffffffu, bi, off);
                float ox = __shfl_down_sync(0xffffffffu, bx, off);
                float oy = __shfl_down_sync(0xffffffffu, by, off);
                if (ov > bv || (ov == bv && oi < bi)) { bv = ov; bi = oi; bx = ox; by = oy; }
            }
            if (tid == 0) {
                g_cent[((size_t)b * NS + it) * 2 + 0] = bx;
                g_cent[((size_t)b * NS + it) * 2 + 1] = by;
                sbx = bx; sby = by;
            }
        }
        __syncthreads();
        lastx = sbx; lasty = sby;
    }
}

// ---------- 3) ball query ----------
__global__ __launch_bounds__(256) void bq_kernel(const float* __restrict__ pts)
{
    __shared__ int sknn[8][NP];
    const int gwid = (blockIdx.x * blockDim.x + threadIdx.x) >> 5;
    const int lane = threadIdx.x & 31, wl = threadIdx.x >> 5;
    if (gwid >= BB * NS) return;
    const int b = gwid >> 10;
    const float cx = g_cent[gwid * 2 + 0];
    const float cy = g_cent[gwid * 2 + 1];
    const float R2 = 0.01f;
    int cnt = 0;
    for (int c = 0; c < NPTS / 32 && cnt < NP; c++) {
        int p = c * 32 + lane;
        float dx = __fsub_rn(cx, pts[((size_t)b * NPTS + p) * 2 + 0]);
        float dy = __fsub_rn(cy, pts[((size_t)b * NPTS + p) * 2 + 1]);
        float d2 = __fadd_rn(__fmul_rn(dx, dx), __fmul_rn(dy, dy));
        bool in = d2 < R2;
        unsigned m = __ballot_sync(0xffffffffu, in);
        int before = __popc(m & ((1u << lane) - 1u));
        if (in && cnt + before < NP) sknn[wl][cnt + before] = p;
        cnt += __popc(m);
    }
    __syncwarp();
    int cc = min(cnt, NP);
    g_knn[gwid * NP + lane] = (lane < cc) ? sknn[wl][lane] : sknn[wl][0];
    if (lane == 0) g_kcnt[gwid] = cc;
}

// ---------- 4) pipelined tf32 GEMM, 128x128 tiles, cp.async double-buffered ----------
// MODE 0: A from global. MODE 1: A gathered via g_knn from g_gfeat_t.
// EPI 0: C = acc+bias (stride N).
// EPI 1: C3 = triA(gelu(acc+bias)) (stride 3N).
// EPI 2: masked 32-row max-pool -> C plain (DM) + C2 tripled (384).
template<int MODE, int EPI>
__global__ __launch_bounds__(256, 2) void gemm_big2_kernel(
    const float* __restrict__ A, const float* __restrict__ W,
    const float* __restrict__ bias, float* __restrict__ C,
    float* __restrict__ C2,
    int N, int K, const float* __restrict__ pts)
{
    extern __shared__ float sm[];
    float* sA = sm;
    float* sW = sm + 2 * 128 * BSTR;
    float* sE = sm;                     // EPI2 pool buffer (aliases stages)
    __shared__ int   sIdx[128];
    __shared__ float sRx[128], sRy[128];
    __shared__ int   sCnt[4];

    const int tid = threadIdx.x;
    const int w = tid >> 5, lane = tid & 31;
    const int g = lane >> 2, q = lane & 3;
    const int wm = w & 3, wn = w >> 2;
    const int m0 = blockIdx.y * 128, n0 = blockIdx.x * 128;
    const int b_batch = m0 >> 15;
    const int NC = K >> 5;

    if (MODE == 1) {
        if (tid < 128) {
            int m = m0 + tid;
            int grp = m >> 5;
            int idx = g_knn[grp * NP + (m & 31)];
            sIdx[tid] = idx;
            float cx = g_cent[grp * 2 + 0], cy = g_cent[grp * 2 + 1];
            const float* pp = pts + ((size_t)b_batch * NPTS + idx) * 2;
            sRx[tid] = pp[0] - cx;
            sRy[tid] = pp[1] - cy;
        }
    }
    if (EPI == 2) {
        if (tid < 4) sCnt[tid] = g_kcnt[(m0 >> 5) + tid];
    }
    __syncthreads();

    auto prefetch = [&](int c) {
        int bi = c & 1;
        float* dA = sA + bi * 128 * BSTR;
        float* dW = sW + bi * 128 * BSTR;
        int k0 = c * 32;
        if (MODE == 1 && k0 >= 128) {
            #pragma unroll
            for (int j = 0; j < 16; j++) {
                int e = tid + j * 256;
                int r = e >> 5, kk = e & 31;
                float v = (kk == 0) ? tf32r(sRx[r]) : (kk == 1) ? tf32r(sRy[r]) : 0.f;
                dA[r * BSTR + kk] = v;
            }
        } else {
            #pragma unroll
            for (int j = 0; j < 4; j++) {
                int e = tid + j * 256;
                int r = e >> 3, ch = e & 7;
                const float* src;
                if (MODE == 1) src = A + ((size_t)b_batch * NPTS + sIdx[r]) * DM + k0 + ch * 4;
                else           src = A + (size_t)(m0 + r) * K + k0 + ch * 4;
                cpa16(sptr(dA + r * BSTR + ch * 4), src);
            }
        }
        #pragma unroll
        for (int j = 0; j < 4; j++) {
            int e = tid + j * 256;
            int r = e >> 3, ch = e & 7;
            cpa16(sptr(dW + r * BSTR + ch * 4), W + (size_t)(n0 + r) * K + k0 + ch * 4);
        }
        asm volatile("cp.async.commit_group;" ::: "memory");
    };

    float acc[2][8][4];
    #pragma unroll
    for (int mf = 0; mf < 2; mf++)
        #pragma unroll
        for (int nf = 0; nf < 8; nf++) { acc[mf][nf][0]=acc[mf][nf][1]=acc[mf][nf][2]=acc[mf][nf][3]=0.f; }

    prefetch(0);
    prefetch(1);

    for (int c = 0; c < NC; c++) {
        if (c == NC - 1) asm volatile("cp.async.wait_group 0;" ::: "memory");
        else             asm volatile("cp.async.wait_group 1;" ::: "memory");
        __syncthreads();
        int bi = c & 1;
        const float* bA = sA + bi * 128 * BSTR;
        const float* bW = sW + bi * 128 * BSTR;
        #pragma unroll
        for (int ks = 0; ks < 4; ks++) {
            int kp = ks * 8;
            unsigned a[2][4];
            #pragma unroll
            for (int mf = 0; mf < 2; mf++) {
                int mb = wm * 32 + mf * 16;
                a[mf][0] = __float_as_uint(bA[(mb + g) * BSTR + kp + q]);
                a[mf][1] = __float_as_uint(bA[(mb + g + 8) * BSTR + kp + q]);
                a[mf][2] = __float_as_uint(bA[(mb + g) * BSTR + kp + q + 4]);
                a[mf][3] = __float_as_uint(bA[(mb + g + 8) * BSTR + kp + q + 4]);
            }
            #pragma unroll
            for (int nf = 0; nf < 8; nf++) {
                int nb = wn * 64 + nf * 8;
                unsigned b0 = __float_as_uint(bW[(nb + g) * BSTR + kp + q]);
                unsigned b1 = __float_as_uint(bW[(nb + g) * BSTR + kp + q + 4]);
                mma_tf32(acc[0][nf], a[0][0], a[0][1], a[0][2], a[0][3], b0, b1);
                mma_tf32(acc[1][nf], a[1][0], a[1][1], a[1][2], a[1][3], b0, b1);
            }
        }
        __syncthreads();
        if (c + 2 < NC) prefetch(c + 2);
    }

    if (EPI == 0) {
        #pragma unroll
        for (int mf = 0; mf < 2; mf++) {
            int rb = m0 + wm * 32 + mf * 16;
            #pragma unroll
            for (int nf = 0; nf < 8; nf++) {
                int colg = n0 + wn * 64 + nf * 8 + 2 * q;
                float bia = __ldg(&bias[colg]), bib = __ldg(&bias[colg + 1]);
                C[(size_t)(rb + g) * N + colg]         = acc[mf][nf][0] + bia;
                C[(size_t)(rb + g) * N + colg + 1]     = acc[mf][nf][1] + bib;
                C[(size_t)(rb + g + 8) * N + colg]     = acc[mf][nf][2] + bia;
                C[(size_t)(rb + g + 8) * N + colg + 1] = acc[mf][nf][3] + bib;
            }
        }
    } else if (EPI == 1) {
        const size_t N3 = 3 * (size_t)N;
        #pragma unroll
        for (int mf = 0; mf < 2; mf++) {
            int rb = m0 + wm * 32 + mf * 16;
            #pragma unroll
            for (int nf = 0; nf < 8; nf++) {
                int colg = n0 + wn * 64 + nf * 8 + 2 * q;
                float bia = __ldg(&bias[colg]), bib = __ldg(&bias[colg + 1]);
                triA(&C[(size_t)(rb + g) * N3 + 3 * colg],         gelu_exact(acc[mf][nf][0] + bia));
                triA(&C[(size_t)(rb + g) * N3 + 3 * (colg + 1)],   gelu_exact(acc[mf][nf][1] + bib));
                triA(&C[(size_t)(rb + g + 8) * N3 + 3 * colg],     gelu_exact(acc[mf][nf][2] + bia));
                triA(&C[(size_t)(rb + g + 8) * N3 + 3 * (colg + 1)], gelu_exact(acc[mf][nf][3] + bib));
            }
        }
    } else {
        #pragma unroll
        for (int mf = 0; mf < 2; mf++) {
            int rb = wm * 32 + mf * 16;
            #pragma unroll
            for (int nf = 0; nf < 8; nf++) {
                int colg = wn * 64 + nf * 8 + 2 * q;
                float bia = __ldg(&bias[colg]), bib = __ldg(&bias[colg + 1]);
                sE[(rb + g) * 132 + colg]         = acc[mf][nf][0] + bia;
                sE[(rb + g) * 132 + colg + 1]     = acc[mf][nf][1] + bib;
                sE[(rb + g + 8) * 132 + colg]     = acc[mf][nf][2] + bia;
                sE[(rb + g + 8) * 132 + colg + 1] = acc[mf][nf][3] + bib;
            }
        }
        __syncthreads();
        #pragma unroll
        for (int pass = 0; pass < 2; pass++) {
            int grp = (tid >> 7) + pass * 2;
            int col = tid & 127;
            int cnt = sCnt[grp];
            float mx = sE[(grp * 32) * 132 + col];
            for (int r = 1; r < cnt; r++) mx = fmaxf(mx, sE[(grp * 32 + r) * 132 + col]);
            size_t orow = (size_t)((m0 >> 5) + grp);
            C[orow * DM + col] = mx;
            triA(&C2[orow * 384 + 3 * col], mx);
        }
    }
}

// ---------- LN + GELU over 256-wide rows (warp per row), tf32-rounded output ----------
__global__ __launch_bounds__(256) void ln_big_kernel(
    float* __restrict__ H, const float* __restrict__ g, const float* __restrict__ be)
{
    const int row = blockIdx.x * 8 + (threadIdx.x >> 5);
    const int lane = threadIdx.x & 31;
    float4* hp = (float4*)(H + (size_t)row * 256);
    float4 x0 = hp[lane * 2], x1 = hp[lane * 2 + 1];
    float s = x0.x + x0.y + x0.z + x0.w + x1.x + x1.y + x1.z + x1.w;
    #pragma unroll
    for (int o = 16; o > 0; o >>= 1) s += __shfl_xor_sync(0xffffffffu, s, o);
    float mu = s * (1.0f / 256.0f);
    float v = 0.f;
    {
        float d;
        d = x0.x - mu; v += d * d; d = x0.y - mu; v += d * d;
        d = x0.z - mu; v += d * d; d = x0.w - mu; v += d * d;
        d = x1.x - mu; v += d * d; d = x1.y - mu; v += d * d;
        d = x1.z - mu; v += d * d; d = x1.w - mu; v += d * d;
    }
    #pragma unroll
    for (int o = 16; o > 0; o >>= 1) v += __shfl_xor_sync(0xffffffffu, v, o);
    float inv = rsqrtf(v * (1.0f / 256.0f) + LN_EPS);
    int c0 = lane * 8;
    float4 gg0 = *(const float4*)(g + c0),  gg1 = *(const float4*)(g + c0 + 4);
    float4 bb0 = *(const float4*)(be + c0), bb1 = *(const float4*)(be + c0 + 4);
    x0.x = tf32r(gelu_exact((x0.x - mu) * inv * gg0.x + bb0.x));
    x0.y = tf32r(gelu_exact((x0.y - mu) * inv * gg0.y + bb0.y));
    x0.z = tf32r(gelu_exact((x0.z - mu) * inv * gg0.z + bb0.z));
    x0.w = tf32r(gelu_exact((x0.w - mu) * inv * gg0.w + bb0.w));
    x1.x = tf32r(gelu_exact((x1.x - mu) * inv * gg1.x + bb1.x));
    x1.y = tf32r(gelu_exact((x1.y - mu) * inv * gg1.y + bb1.y));
    x1.z = tf32r(gelu_exact((x1.z - mu) * inv * gg1.z + bb1.z));
    x1.w = tf32r(gelu_exact((x1.w - mu) * inv * gg1.w + bb1.w));
    hp[lane * 2] = x0; hp[lane * 2 + 1] = x1;
}

// ---------- 6) flash attention (fp32) -> tripled output ----------
__global__ __launch_bounds__(256) void flash2_kernel(
    const float* __restrict__ Q, const float* __restrict__ KV,
    float* __restrict__ Out3, int Sq, int Skv)
{
    __shared__ float Ks[64 * 32];
    __shared__ float Vs[64 * 32];
    const int b = blockIdx.z, h = blockIdx.y, q0 = blockIdx.x * 32;
    const int tid = threadIdx.x;
    const int qr = tid >> 3, dg = tid & 7;
    const int d0 = dg * 4, kb = dg * 8;
    const float scale = 0.17677669529663687f;

    float4 q4[8];
    {
        const float* qrow = Q + (size_t)(b * Sq + q0 + qr) * DM + h * DH;
        #pragma unroll
        for (int d4 = 0; d4 < 8; d4++) q4[d4] = *(const float4*)(qrow + d4 * 4);
    }

    float O[4] = {0.f, 0.f, 0.f, 0.f};
    float mreg = -INFINITY, lreg = 0.f;

    for (int kv0 = 0; kv0 < Skv; kv0 += 64) {
        #pragma unroll
        for (int i = 0; i < 2; i++) {
            int e = tid + i * 256;
            int r = e >> 3, c4 = e & 7;
            const float* base = KV + (size_t)(b * Skv + kv0 + r) * 256 + h * DH + c4 * 4;
            float4 kv_ = *(const float4*)base;
            *(float4*)&Ks[r * 32 + ((c4 ^ (r >> 3)) * 4)] = kv_;
            float4 vv = *(const float4*)(base + 128);
            *(float4*)&Vs[r * 32 + c4 * 4] = vv;
        }
        __syncthreads();

        float s[8];
        #pragma unroll
        for (int j = 0; j < 8; j++) {
            float acc = 0.f;
            const float* krow = &Ks[(kb + j) * 32];
            #pragma unroll
            for (int d4 = 0; d4 < 8; d4++) {
                float4 k4 = *(const float4*)(krow + ((d4 ^ dg) * 4));
                acc += q4[d4].x * k4.x + q4[d4].y * k4.y + q4[d4].z * k4.z + q4[d4].w * k4.w;
            }
            s[j] = acc * scale;
        }
        float rmax = s[0];
        #pragma unroll
        for (int j = 1; j < 8; j++) rmax = fmaxf(rmax, s[j]);
        rmax = fmaxf(rmax, __shfl_xor_sync(0xffffffffu, rmax, 1));
        rmax = fmaxf(rmax, __shfl_xor_sync(0xffffffffu, rmax, 2));
        rmax = fmaxf(rmax, __shfl_xor_sync(0xffffffffu, rmax, 4));

        float mnew = fmaxf(mreg, rmax);
        float corr = expf(mreg - mnew);
        float p[8];
        float psum = 0.f;
        #pragma unroll
        for (int j = 0; j < 8; j++) { p[j] = expf(s[j] - mnew); psum += p[j]; }
        psum += __shfl_xor_sync(0xffffffffu, psum, 1);
        psum += __shfl_xor_sync(0xffffffffu, psum, 2);
        psum += __shfl_xor_sync(0xffffffffu, psum, 4);
        lreg = lreg * corr + psum;
        mreg = mnew;
        #pragma unroll
        for (int c = 0; c < 4; c++) O[c] *= corr;

        #pragma unroll
        for (int sl = 0; sl < 8; sl++) {
            #pragma unroll
            for (int j = 0; j < 8; j++) {
                float pv = __shfl_sync(0xffffffffu, p[j], sl, 8);
                float4 v4 = *(const float4*)&Vs[(sl * 8 + j) * 32 + d0];
                O[0] += pv * v4.x; O[1] += pv * v4.y;
                O[2] += pv * v4.z; O[3] += pv * v4.w;
            }
        }
        __syncthreads();
    }
    float inv = 1.0f / lreg;
    float* orow3 = Out3 + (size_t)(b * Sq + q0 + qr) * 384 + 3 * (h * DH + d0);
    #pragma unroll
    for (int c = 0; c < 4; c++) triA(orow3 + 3 * c, O[c] * inv);
}

// ---------- 7) residual add + layernorm -> plain + tripled ----------
__global__ __launch_bounds__(128) void ln_res_kernel(
    float* __restrict__ out, float* __restrict__ out3,
    const float* __restrict__ a, const float* __restrict__ res,
    const float* __restrict__ g, const float* __restrict__ be)
{
    __shared__ float sh1[4], sh2[4];
    const int row = blockIdx.x, t = threadIdx.x;
    const int w = t >> 5, lane = t & 31;
    float x = a[(size_t)row * DM + t] + res[(size_t)row * DM + t];
    float s = x;
    #pragma unroll
    for (int o = 16; o > 0; o >>= 1) s += __shfl_xor_sync(0xffffffffu, s, o);
    if (lane == 0) sh1[w] = s;
    __syncthreads();
    float mu = (sh1[0] + sh1[1] + sh1[2] + sh1[3]) * (1.0f / 128.0f);
    float d = x - mu;
    float q = d * d;
    #pragma unroll
    for (int o = 16; o > 0; o >>= 1) q += __shfl_xor_sync(0xffffffffu, q, o);
    if (lane == 0) sh2[w] = q;
    __syncthreads();
    float var = (sh2[0] + sh2[1] + sh2[2] + sh2[3]) * (1.0f / 128.0f);
    float v = d * rsqrtf(var + LN_EPS) * g[t] + be[t];
    out[(size_t)row * DM + t] = v;
    triA(&out3[(size_t)row * 384 + 3 * t], v);
}

// ---------- host ----------
extern "C" void kernel_launch(void* const* d_in, const int* in_sizes, int n_in,
                              void* d_out, int out_size)
{
    (void)in_sizes; (void)n_in; (void)out_size;
    const float* pts     = (const float*)d_in[0];
    const float* feat_w  = (const float*)d_in[2];
    const float* feat_b  = (const float*)d_in[3];
    const float* mlp_w1  = (const float*)d_in[4];
    const float* mlp_b1  = (const float*)d_in[5];
    const float* mlp_g1  = (const float*)d_in[6];
    const float* mlp_be1 = (const float*)d_in[7];
    const float* mlp_w2  = (const float*)d_in[8];
    const float* mlp_b2  = (const float*)d_in[9];
    const float* mlp_g2  = (const float*)d_in[10];
    const float* mlp_be2 = (const float*)d_in[11];
    const float* mlp_w3  = (const float*)d_in[12];
    const float* mlp_b3  = (const float*)d_in[13];
    const float* blk_in_w = (const float*)d_in[14];
    const float* blk_in_b = (const float*)d_in[15];
    const float* blk_ow   = (const float*)d_in[16];
    const float* blk_ob   = (const float*)d_in[17];
    const float* blk_g1   = (const float*)d_in[18];
    const float* blk_be1  = (const float*)d_in[19];
    const float* blk_g2   = (const float*)d_in[20];
    const float* blk_be2  = (const float*)d_in[21];
    const float* blk_f1w  = (const float*)d_in[22];
    const float* blk_f1b  = (const float*)d_in[23];
    const float* blk_f2w  = (const float*)d_in[24];
    const float* blk_f2b  = (const float*)d_in[25];
    const float* k_w = (const float*)d_in[26];
    const float* k_b = (const float*)d_in[27];
    const float* v_w = (const float*)d_in[28];
    const float* v_b = (const float*)d_in[29];
    float* out = (float*)d_out;

    float *gfeattp, *gfeat3p, *localp, *local3p, *xp, *x3p, *x2p, *x23p;
    float *qp, *att3p, *tmpp, *kvp, *ff3p, *big1p, *big2p;
    float *w1pp, *w2pp, *w3pp, *inw3p, *ow3p, *f1w3p, *f2w3p, *kvw3p;
    cudaGetSymbolAddress((void**)&gfeattp, g_gfeat_t);
    cudaGetSymbolAddress((void**)&gfeat3p, g_gfeat3);
    cudaGetSymbolAddress((void**)&localp,  g_local);
    cudaGetSymbolAddress((void**)&local3p, g_local3);
    cudaGetSymbolAddress((void**)&xp,      g_x);
    cudaGetSymbolAddress((void**)&x3p,     g_x3);
    cudaGetSymbolAddress((void**)&x2p,     g_x2);
    cudaGetSymbolAddress((void**)&x23p,    g_x23);
    cudaGetSymbolAddress((void**)&qp,      g_q);
    cudaGetSymbolAddress((void**)&att3p,   g_att3);
    cudaGetSymbolAddress((void**)&tmpp,    g_tmp);
    cudaGetSymbolAddress((void**)&kvp,     g_kv);
    cudaGetSymbolAddress((void**)&ff3p,    g_ff3);
    cudaGetSymbolAddress((void**)&big1p,   g_big1);
    cudaGetSymbolAddress((void**)&big2p,   g_big2);
    cudaGetSymbolAddress((void**)&w1pp,    g_w1p);
    cudaGetSymbolAddress((void**)&w2pp,    g_w2p);
    cudaGetSymbolAddress((void**)&w3pp,    g_w3p);
    cudaGetSymbolAddress((void**)&inw3p,   g_inw3);
    cudaGetSymbolAddress((void**)&ow3p,    g_ow3);
    cudaGetSymbolAddress((void**)&f1w3p,   g_f1w3);
    cudaGetSymbolAddress((void**)&f2w3p,   g_f2w3);
    cudaGetSymbolAddress((void**)&kvw3p,   g_kvw3);

    cudaFuncSetAttribute(gemm_big2_kernel<1,0>, cudaFuncAttributeMaxDynamicSharedMemorySize, SM_BIG);
    cudaFuncSetAttribute(gemm_big2_kernel<0,0>, cudaFuncAttributeMaxDynamicSharedMemorySize, SM_BIG);
    cudaFuncSetAttribute(gemm_big2_kernel<0,1>, cudaFuncAttributeMaxDynamicSharedMemorySize, SM_BIG);
    cudaFuncSetAttribute(gemm_big2_kernel<0,2>, cudaFuncAttributeMaxDynamicSharedMemorySize, SM_BIG);

    gfeat_kernel<<<GFROWS / 128, 128>>>(pts, feat_w, feat_b);
    wprep_kernel<<<544, 256>>>(mlp_w1, mlp_w2, mlp_w3);
    wprep2_kernel<<<3200, 256>>>(blk_in_w, blk_ow, blk_f1w, blk_f2w, k_w, v_w);
    fps_kernel<<<BB, 512>>>(pts);
    bq_kernel<<<(BB * NS) / 8, 256>>>(pts);

    // grouped MLP (flat pipelined GEMMs, single tf32)
    gemm_big2_kernel<1,0><<<dim3(2, GMROWS / 128), 256, SM_BIG>>>(
        gfeattp, w1pp, mlp_b1, big1p, nullptr, 256, 160, pts);
    ln_big_kernel<<<GMROWS / 8, 256>>>(big1p, mlp_g1, mlp_be1);
    gemm_big2_kernel<0,0><<<dim3(2, GMROWS / 128), 256, SM_BIG>>>(
        big1p, w2pp, mlp_b2, big2p, nullptr, 256, 256, nullptr);
    ln_big_kernel<<<GMROWS / 8, 256>>>(big2p, mlp_g2, mlp_be2);
    gemm_big2_kernel<0,2><<<dim3(1, GMROWS / 128), 256, SM_BIG>>>(
        big2p, w3pp, mlp_b3, localp, local3p, 128, 256, nullptr);

    // transformer: all linears are plain pipelined tf32 GEMMs on tripled operands
    for (int i = 0; i < 4; i++) {
        const float* xcur3 = (i == 0) ? local3p : x3p;
        const float* xcurp = (i == 0) ? localp  : xp;
        const float* kv3   = (i < 2) ? gfeat3p : xcur3;
        int Skv = (i < 2) ? NPTS : NS;
        int Mkv = BB * Skv;
        const float* wq3 = inw3p + (size_t)i * 384 * 384;
        const float* bq  = blk_in_b + (size_t)i * 384;

        gemm_big2_kernel<0,0><<<dim3(1, SQROWS / 128), 256, SM_BIG>>>(
            xcur3, wq3, bq, qp, nullptr, 128, 384, nullptr);
        gemm_big2_kernel<0,0><<<dim3(2, Mkv / 128), 256, SM_BIG>>>(
            kv3, wq3 + 128 * 384, bq + 128, kvp, nullptr, 256, 384, nullptr);
        flash2_kernel<<<dim3(NS / 32, NH, BB), 256>>>(qp, kvp, att3p, NS, Skv);
        gemm_big2_kernel<0,0><<<dim3(1, SQROWS / 128), 256, SM_BIG>>>(
            att3p, ow3p + (size_t)i * 128 * 384, blk_ob + (size_t)i * 128,
            tmpp, nullptr, 128, 384, nullptr);
        ln_res_kernel<<<SQROWS, 128>>>(x2p, x23p, tmpp, xcurp,
                                       blk_g1 + (size_t)i * 128, blk_be1 + (size_t)i * 128);
        gemm_big2_kernel<0,1><<<dim3(4, SQROWS / 128), 256, SM_BIG>>>(
            x23p, f1w3p + (size_t)i * 512 * 384, blk_f1b + (size_t)i * 512,
            ff3p, nullptr, 512, 384, nullptr);
        gemm_big2_kernel<0,0><<<dim3(1, SQROWS / 128), 256, SM_BIG>>>(
            ff3p, f2w3p + (size_t)i * 128 * 1536, blk_f2b + (size_t)i * 128,
            tmpp, nullptr, 128, 1536, nullptr);
        ln_res_kernel<<<SQROWS, 128>>>(xp, x3p, tmpp, x2p,
                                       blk_g2 + (size_t)i * 128, blk_be2 + (size_t)i * 128);
    }

    gemm_big2_kernel<0,0><<<dim3(1, SQROWS / 128), 256, SM_BIG>>>(
        x3p, kvw3p, k_b, out, nullptr, 128, 384, nullptr);
    gemm_big2_kernel<0,0><<<dim3(1, SQROWS / 128), 256, SM_BIG>>>(
        x3p, kvw3p + 128 * 384, v_b, out + (size_t)SQROWS * 128, nullptr, 128, 384, nullptr);
}

// round 10
// speedup vs baseline: 2.3882x; 1.1101x over previous
#include <cuda_runtime.h>
#include <cuda_bf16.h>
#include <math.h>

#define BB      8
#define NPTS    4096
#define NS      1024
#define NP      32
#define DM      128
#define NH      4
#define DH      32
#define FFH     512
#define LN_EPS  1e-5f
#define SQROWS  (BB*NS)
#define GFROWS  (BB*NPTS)
#define GMROWS  (SQROWS*NP)      // 262144

// big pipelined gemm: 128x128 tile, 32-K chunks, 2-stage cp.async
#define BSTR 36
#define SM_BIG (4*128*BSTR*4)    // 73728 B; epilogue pool aliases this

// flash3 smem geometry (floats)
#define QS 100
#define KS 100
#define VS 196
#define PS 196
#define FL_K3 (64*QS)
#define FL_V3 (FL_K3 + 64*KS)
#define FL_P3 (FL_V3 + 32*VS)
#define FL_FLOATS (FL_P3 + 64*PS)
#define FL_SMEM (FL_FLOATS*4)

__device__ float g_gfeat_t[GFROWS * DM];
__device__ float g_gfeat3 [GFROWS * 384];
__device__ float g_cent [BB * NS * 2];
__device__ int   g_knn  [BB * NS * NP];
__device__ int   g_kcnt [BB * NS];
__device__ float g_local [SQROWS * DM];
__device__ float g_local3[SQROWS * 384];
__device__ float g_x    [SQROWS * DM];
__device__ float g_x3   [SQROWS * 384];
__device__ float g_x2   [SQROWS * DM];
__device__ float g_x23  [SQROWS * 384];
__device__ float g_q    [SQROWS * DM];
__device__ float g_att3 [SQROWS * 384];
__device__ float g_tmp  [SQROWS * DM];
__device__ float g_kv   [GFROWS * 256];
__device__ float g_ff3  [SQROWS * 1536];
__device__ float g_big1 [GMROWS * 256];
__device__ float g_big2 [GMROWS * 256];
__device__ float g_w1p  [256 * 160];
__device__ float g_w2p  [256 * 256];
__device__ float g_w3p  [128 * 256];
__device__ float g_inw3 [4 * 384 * 384];
__device__ float g_ow3  [4 * 128 * 384];
__device__ float g_f1w3 [4 * 512 * 384];
__device__ float g_f2w3 [4 * 128 * 1536];
__device__ float g_kvw3 [256 * 384];

__device__ __forceinline__ float gelu_exact(float x) {
    return 0.5f * x * (1.0f + erff(x * 0.70710678118654752440f));
}
__device__ __forceinline__ float tf32r(float x) {
    unsigned u;
    asm("cvt.rna.tf32.f32 %0, %1;" : "=r"(u) : "f"(x));
    return __uint_as_float(u);
}
__device__ __forceinline__ void triA(float* d, float x) {   // A-side [hi,hi,lo]
    float hi = tf32r(x), lo = tf32r(x - hi);
    d[0] = hi; d[1] = hi; d[2] = lo;
}
__device__ __forceinline__ void triB(float* d, float x) {   // B-side [hi,lo,hi]
    float hi = tf32r(x), lo = tf32r(x - hi);
    d[0] = hi; d[1] = lo; d[2] = hi;
}
__device__ __forceinline__ void mma_tf32(float* c, unsigned a0, unsigned a1,
                                         unsigned a2, unsigned a3,
                                         unsigned b0, unsigned b1) {
    asm volatile(
        "mma.sync.aligned.m16n8k8.row.col.f32.tf32.tf32.f32 "
        "{%0,%1,%2,%3},{%4,%5,%6,%7},{%8,%9},{%0,%1,%2,%3};"
        : "+f"(c[0]), "+f"(c[1]), "+f"(c[2]), "+f"(c[3])
        : "r"(a0), "r"(a1), "r"(a2), "r"(a3), "r"(b0), "r"(b1));
}
__device__ __forceinline__ unsigned sptr(const void* p) {
    return (unsigned)__cvta_generic_to_shared(p);
}
__device__ __forceinline__ void cpa16(unsigned dst, const void* src) {
    asm volatile("cp.async.cg.shared.global [%0], [%1], 16;" :: "r"(dst), "l"(src));
}

// ---------- 1) fourier features + 26->128 projection ----------
__global__ __launch_bounds__(128) void gfeat_kernel(
    const float* __restrict__ pts, const float* __restrict__ fw, const float* __restrict__ fb)
{
    __shared__ float fsh[128 * 26];
    const int t = threadIdx.x;
    const int base = blockIdx.x * 128;
    float wreg[26];
    #pragma unroll
    for (int j = 0; j < 26; j++) wreg[j] = fw[t * 26 + j];

    const float FREQ[6] = {3.14159265358979323846f, 6.28318530717958647693f,
        12.5663706143591729539f, 25.1327412287183459077f,
        50.2654824574366918154f, 100.530964914873383631f};
    {
        float x = pts[(size_t)(base + t) * 2 + 0];
        float y = pts[(size_t)(base + t) * 2 + 1];
        fsh[t * 26 + 0] = x; fsh[t * 26 + 1] = y;
        #pragma unroll
        for (int k = 0; k < 6; k++) {
            float sx, cx, sy, cy;
            sincosf(FREQ[k] * x, &sx, &cx);
            sincosf(FREQ[k] * y, &sy, &cy);
            fsh[t*26 + 2 + 4*k + 0] = sx; fsh[t*26 + 2 + 4*k + 1] = sy;
            fsh[t*26 + 2 + 4*k + 2] = cx; fsh[t*26 + 2 + 4*k + 3] = cy;
        }
    }
    float bb = fb[t];
    __syncthreads();
    for (int p = 0; p < 128; p++) {
        float acc = bb;
        #pragma unroll
        for (int j = 0; j < 26; j++) acc += fsh[p * 26 + j] * wreg[j];
        size_t row = (size_t)(base + p);
        g_gfeat_t[row * DM + t] = tf32r(acc);
        triA(&g_gfeat3[row * 384 + 3 * t], acc);
    }
}

// ---------- MLP weight pre-round ----------
__global__ __launch_bounds__(256) void wprep_kernel(
    const float* __restrict__ w1, const float* __restrict__ w2, const float* __restrict__ w3)
{
    int i = blockIdx.x * 256 + threadIdx.x;
    if (i < 256 * 160) {
        int n = i / 160, k = i - n * 160;
        g_w1p[i] = (k < 130) ? tf32r(w1[n * 130 + k]) : 0.f;
    }
    int j = i - 256 * 160;
    if (j >= 0 && j < 256 * 256) g_w2p[j] = tf32r(w2[j]);
    int l = i - 256 * 160 - 256 * 256;
    if (l >= 0 && l < 128 * 256) g_w3p[l] = tf32r(w3[l]);
}

// ---------- transformer weight triple-split ----------
__global__ __launch_bounds__(256) void wprep2_kernel(
    const float* __restrict__ inw, const float* __restrict__ ow,
    const float* __restrict__ f1w, const float* __restrict__ f2w,
    const float* __restrict__ kw, const float* __restrict__ vw)
{
    int i = blockIdx.x * 256 + threadIdx.x;
    if (i < 1536 * 128) { int r = i >> 7, k = i & 127; triB(&g_inw3[(size_t)r * 384 + 3 * k], inw[i]); return; }
    i -= 1536 * 128;
    if (i < 512 * 128)  { int r = i >> 7, k = i & 127; triB(&g_ow3 [(size_t)r * 384 + 3 * k], ow[i]);  return; }
    i -= 512 * 128;
    if (i < 2048 * 128) { int r = i >> 7, k = i & 127; triB(&g_f1w3[(size_t)r * 384 + 3 * k], f1w[i]); return; }
    i -= 2048 * 128;
    if (i < 512 * 512)  { int r = i >> 9, k = i & 511; triB(&g_f2w3[(size_t)r * 1536 + 3 * k], f2w[i]); return; }
    i -= 512 * 512;
    if (i < 128 * 128)  { int r = i >> 7, k = i & 127; triB(&g_kvw3[(size_t)r * 384 + 3 * k], kw[i]); return; }
    i -= 128 * 128;
    if (i < 128 * 128)  { int r = i >> 7, k = i & 127; triB(&g_kvw3[(size_t)(128 + r) * 384 + 3 * k], vw[i]); return; }
}

// ---------- 2) farthest point sampling (1 barrier/iter, parity buffers) ----------
__global__ __launch_bounds__(512) void fps_kernel(const float* __restrict__ pts)
{
    const int b = blockIdx.x, tid = threadIdx.x;
    const int lane = tid & 31, wid = tid >> 5;
    float px[8], py[8], dd[8];
    #pragma unroll
    for (int j = 0; j < 8; j++) {
        int p = tid + j * 512;
        px[j] = pts[((size_t)b * NPTS + p) * 2 + 0];
        py[j] = pts[((size_t)b * NPTS + p) * 2 + 1];
        dd[j] = INFINITY;
    }
    __shared__ float rv[2][16]; __shared__ int ri[2][16];
    __shared__ float rx[2][16], ry[2][16];
    float lastx = pts[(size_t)b * NPTS * 2 + 0];
    float lasty = pts[(size_t)b * NPTS * 2 + 1];
    if (tid == 0) {
        g_cent[(size_t)b * NS * 2 + 0] = lastx;
        g_cent[(size_t)b * NS * 2 + 1] = lasty;
    }
    for (int it = 1; it < NS; it++) {
        const int pb = it & 1;
        float bv = -1.0f; int bi = 0x7fffffff; float bx = 0.f, by = 0.f;
        #pragma unroll
        for (int j = 0; j < 8; j++) {
            float dx = __fsub_rn(px[j], lastx);
            float dy = __fsub_rn(py[j], lasty);
            float d2 = __fadd_rn(__fmul_rn(dx, dx), __fmul_rn(dy, dy));
            dd[j] = fminf(dd[j], d2);
            if (dd[j] > bv) { bv = dd[j]; bi = tid + j * 512; bx = px[j]; by = py[j]; }
        }
        #pragma unroll
        for (int off = 16; off > 0; off >>= 1) {
            float ov = __shfl_down_sync(0xffffffffu, bv, off);
            int   oi = __shfl_down_sync(0xffffffffu, bi, off);
            float ox = __shfl_down_sync(0xffffffffu, bx, off);
            float oy = __shfl_down_sync(0xffffffffu, by, off);
            if (ov > bv || (ov == bv && oi < bi)) { bv = ov; bi = oi; bx = ox; by = oy; }
        }
        if (lane == 0) { rv[pb][wid] = bv; ri[pb][wid] = bi; rx[pb][wid] = bx; ry[pb][wid] = by; }
        __syncthreads();
        bv = -1.0f; bi = 0x7fffffff; bx = 0.f; by = 0.f;
        #pragma unroll
        for (int k = 0; k < 16; k++) {
            float ov = rv[pb][k]; int oi = ri[pb][k];
            if (ov > bv || (ov == bv && oi < bi)) { bv = ov; bi = oi; bx = rx[pb][k]; by = ry[pb][k]; }
        }
        lastx = bx; lasty = by;
        if (tid == 0) {
            g_cent[((size_t)b * NS + it) * 2 + 0] = bx;
            g_cent[((size_t)b * NS + it) * 2 + 1] = by;
        }
    }
}

// ---------- 3) ball query ----------
__global__ __launch_bounds__(256) void bq_kernel(const float* __restrict__ pts)
{
    __shared__ int sknn[8][NP];
    const int gwid = (blockIdx.x * blockDim.x + threadIdx.x) >> 5;
    const int lane = threadIdx.x & 31, wl = threadIdx.x >> 5;
    if (gwid >= BB * NS) return;
    const int b = gwid >> 10;
    const float cx = g_cent[gwid * 2 + 0];
    const float cy = g_cent[gwid * 2 + 1];
    const float R2 = 0.01f;
    int cnt = 0;
    for (int c = 0; c < NPTS / 32 && cnt < NP; c++) {
        int p = c * 32 + lane;
        float dx = __fsub_rn(cx, pts[((size_t)b * NPTS + p) * 2 + 0]);
        float dy = __fsub_rn(cy, pts[((size_t)b * NPTS + p) * 2 + 1]);
        float d2 = __fadd_rn(__fmul_rn(dx, dx), __fmul_rn(dy, dy));
        bool in = d2 < R2;
        unsigned m = __ballot_sync(0xffffffffu, in);
        int before = __popc(m & ((1u << lane) - 1u));
        if (in && cnt + before < NP) sknn[wl][cnt + before] = p;
        cnt += __popc(m);
    }
    __syncwarp();
    int cc = min(cnt, NP);
    g_knn[gwid * NP + lane] = (lane < cc) ? sknn[wl][lane] : sknn[wl][0];
    if (lane == 0) g_kcnt[gwid] = cc;
}

// ---------- 4) pipelined tf32 GEMM, 128x128 tiles, cp.async double-buffered ----------
template<int MODE, int EPI>
__global__ __launch_bounds__(256, 2) void gemm_big2_kernel(
    const float* __restrict__ A, const float* __restrict__ W,
    const float* __restrict__ bias, float* __restrict__ C,
    float* __restrict__ C2,
    int N, int K, const float* __restrict__ pts)
{
    extern __shared__ float sm[];
    float* sA = sm;
    float* sW = sm + 2 * 128 * BSTR;
    float* sE = sm;
    __shared__ int   sIdx[128];
    __shared__ float sRx[128], sRy[128];
    __shared__ int   sCnt[4];

    const int tid = threadIdx.x;
    const int w = tid >> 5, lane = tid & 31;
    const int g = lane >> 2, q = lane & 3;
    const int wm = w & 3, wn = w >> 2;
    const int m0 = blockIdx.y * 128, n0 = blockIdx.x * 128;
    const int b_batch = m0 >> 15;
    const int NC = K >> 5;

    if (MODE == 1) {
        if (tid < 128) {
            int m = m0 + tid;
            int grp = m >> 5;
            int idx = g_knn[grp * NP + (m & 31)];
            sIdx[tid] = idx;
            float cx = g_cent[grp * 2 + 0], cy = g_cent[grp * 2 + 1];
            const float* pp = pts + ((size_t)b_batch * NPTS + idx) * 2;
            sRx[tid] = pp[0] - cx;
            sRy[tid] = pp[1] - cy;
        }
    }
    if (EPI == 2) {
        if (tid < 4) sCnt[tid] = g_kcnt[(m0 >> 5) + tid];
    }
    __syncthreads();

    auto prefetch = [&](int c) {
        int bi = c & 1;
        float* dA = sA + bi * 128 * BSTR;
        float* dW = sW + bi * 128 * BSTR;
        int k0 = c * 32;
        if (MODE == 1 && k0 >= 128) {
            #pragma unroll
            for (int j = 0; j < 16; j++) {
                int e = tid + j * 256;
                int r = e >> 5, kk = e & 31;
                float v = (kk == 0) ? tf32r(sRx[r]) : (kk == 1) ? tf32r(sRy[r]) : 0.f;
                dA[r * BSTR + kk] = v;
            }
        } else {
            #pragma unroll
            for (int j = 0; j < 4; j++) {
                int e = tid + j * 256;
                int r = e >> 3, ch = e & 7;
                const float* src;
                if (MODE == 1) src = A + ((size_t)b_batch * NPTS + sIdx[r]) * DM + k0 + ch * 4;
                else           src = A + (size_t)(m0 + r) * K + k0 + ch * 4;
                cpa16(sptr(dA + r * BSTR + ch * 4), src);
            }
        }
        #pragma unroll
        for (int j = 0; j < 4; j++) {
            int e = tid + j * 256;
            int r = e >> 3, ch = e & 7;
            cpa16(sptr(dW + r * BSTR + ch * 4), W + (size_t)(n0 + r) * K + k0 + ch * 4);
        }
        asm volatile("cp.async.commit_group;" ::: "memory");
    };

    float acc[2][8][4];
    #pragma unroll
    for (int mf = 0; mf < 2; mf++)
        #pragma unroll
        for (int nf = 0; nf < 8; nf++) { acc[mf][nf][0]=acc[mf][nf][1]=acc[mf][nf][2]=acc[mf][nf][3]=0.f; }

    prefetch(0);
    prefetch(1);

    for (int c = 0; c < NC; c++) {
        if (c == NC - 1) asm volatile("cp.async.wait_group 0;" ::: "memory");
        else             asm volatile("cp.async.wait_group 1;" ::: "memory");
        __syncthreads();
        int bi = c & 1;
        const float* bA = sA + bi * 128 * BSTR;
        const float* bW = sW + bi * 128 * BSTR;
        #pragma unroll
        for (int ks = 0; ks < 4; ks++) {
            int kp = ks * 8;
            unsigned a[2][4];
            #pragma unroll
            for (int mf = 0; mf < 2; mf++) {
                int mb = wm * 32 + mf * 16;
                a[mf][0] = __float_as_uint(bA[(mb + g) * BSTR + kp + q]);
                a[mf][1] = __float_as_uint(bA[(mb + g + 8) * BSTR + kp + q]);
                a[mf][2] = __float_as_uint(bA[(mb + g) * BSTR + kp + q + 4]);
                a[mf][3] = __float_as_uint(bA[(mb + g + 8) * BSTR + kp + q + 4]);
            }
            #pragma unroll
            for (int nf = 0; nf < 8; nf++) {
                int nb = wn * 64 + nf * 8;
                unsigned b0 = __float_as_uint(bW[(nb + g) * BSTR + kp + q]);
                unsigned b1 = __float_as_uint(bW[(nb + g) * BSTR + kp + q + 4]);
                mma_tf32(acc[0][nf], a[0][0], a[0][1], a[0][2], a[0][3], b0, b1);
                mma_tf32(acc[1][nf], a[1][0], a[1][1], a[1][2], a[1][3], b0, b1);
            }
        }
        __syncthreads();
        if (c + 2 < NC) prefetch(c + 2);
    }

    if (EPI == 0) {
        #pragma unroll
        for (int mf = 0; mf < 2; mf++) {
            int rb = m0 + wm * 32 + mf * 16;
            #pragma unroll
            for (int nf = 0; nf < 8; nf++) {
                int colg = n0 + wn * 64 + nf * 8 + 2 * q;
                float bia = __ldg(&bias[colg]), bib = __ldg(&bias[colg + 1]);
                C[(size_t)(rb + g) * N + colg]         = acc[mf][nf][0] + bia;
                C[(size_t)(rb + g) * N + colg + 1]     = acc[mf][nf][1] + bib;
                C[(size_t)(rb + g + 8) * N + colg]     = acc[mf][nf][2] + bia;
                C[(size_t)(rb + g + 8) * N + colg + 1] = acc[mf][nf][3] + bib;
            }
        }
    } else if (EPI == 1) {
        const size_t N3 = 3 * (size_t)N;
        #pragma unroll
        for (int mf = 0; mf < 2; mf++) {
            int rb = m0 + wm * 32 + mf * 16;
            #pragma unroll
            for (int nf = 0; nf < 8; nf++) {
                int colg = n0 + wn * 64 + nf * 8 + 2 * q;
                float bia = __ldg(&bias[colg]), bib = __ldg(&bias[colg + 1]);
                triA(&C[(size_t)(rb + g) * N3 + 3 * colg],           gelu_exact(acc[mf][nf][0] + bia));
                triA(&C[(size_t)(rb + g) * N3 + 3 * (colg + 1)],     gelu_exact(acc[mf][nf][1] + bib));
                triA(&C[(size_t)(rb + g + 8) * N3 + 3 * colg],       gelu_exact(acc[mf][nf][2] + bia));
                triA(&C[(size_t)(rb + g + 8) * N3 + 3 * (colg + 1)], gelu_exact(acc[mf][nf][3] + bib));
            }
        }
    } else {
        #pragma unroll
        for (int mf = 0; mf < 2; mf++) {
            int rb = wm * 32 + mf * 16;
            #pragma unroll
            for (int nf = 0; nf < 8; nf++) {
                int colg = wn * 64 + nf * 8 + 2 * q;
                float bia = __ldg(&bias[colg]), bib = __ldg(&bias[colg + 1]);
                sE[(rb + g) * 132 + colg]         = acc[mf][nf][0] + bia;
                sE[(rb + g) * 132 + colg + 1]     = acc[mf][nf][1] + bib;
                sE[(rb + g + 8) * 132 + colg]     = acc[mf][nf][2] + bia;
                sE[(rb + g + 8) * 132 + colg + 1] = acc[mf][nf][3] + bib;
            }
        }
        __syncthreads();
        #pragma unroll
        for (int pass = 0; pass < 2; pass++) {
            int grp = (tid >> 7) + pass * 2;
            int col = tid & 127;
            int cnt = sCnt[grp];
            float mx = sE[(grp * 32) * 132 + col];
            for (int r = 1; r < cnt; r++) mx = fmaxf(mx, sE[(grp * 32 + r) * 132 + col]);
            size_t orow = (size_t)((m0 >> 5) + grp);
            C[orow * DM + col] = mx;
            triA(&C2[orow * 384 + 3 * col], mx);
        }
    }
}

// ---------- LN + GELU over 256-wide rows, tf32-rounded output ----------
__global__ __launch_bounds__(256) void ln_big_kernel(
    float* __restrict__ H, const float* __restrict__ g, const float* __restrict__ be)
{
    const int row = blockIdx.x * 8 + (threadIdx.x >> 5);
    const int lane = threadIdx.x & 31;
    float4* hp = (float4*)(H + (size_t)row * 256);
    float4 x0 = hp[lane * 2], x1 = hp[lane * 2 + 1];
    float s = x0.x + x0.y + x0.z + x0.w + x1.x + x1.y + x1.z + x1.w;
    #pragma unroll
    for (int o = 16; o > 0; o >>= 1) s += __shfl_xor_sync(0xffffffffu, s, o);
    float mu = s * (1.0f / 256.0f);
    float v = 0.f;
    {
        float d;
        d = x0.x - mu; v += d * d; d = x0.y - mu; v += d * d;
        d = x0.z - mu; v += d * d; d = x0.w - mu; v += d * d;
        d = x1.x - mu; v += d * d; d = x1.y - mu; v += d * d;
        d = x1.z - mu; v += d * d; d = x1.w - mu; v += d * d;
    }
    #pragma unroll
    for (int o = 16; o > 0; o >>= 1) v += __shfl_xor_sync(0xffffffffu, v, o);
    float inv = rsqrtf(v * (1.0f / 256.0f) + LN_EPS);
    int c0 = lane * 8;
    float4 gg0 = *(const float4*)(g + c0),  gg1 = *(const float4*)(g + c0 + 4);
    float4 bb0 = *(const float4*)(be + c0), bb1 = *(const float4*)(be + c0 + 4);
    x0.x = tf32r(gelu_exact((x0.x - mu) * inv * gg0.x + bb0.x));
    x0.y = tf32r(gelu_exact((x0.y - mu) * inv * gg0.y + bb0.y));
    x0.z = tf32r(gelu_exact((x0.z - mu) * inv * gg0.z + bb0.z));
    x0.w = tf32r(gelu_exact((x0.w - mu) * inv * gg0.w + bb0.w));
    x1.x = tf32r(gelu_exact((x1.x - mu) * inv * gg1.x + bb1.x));
    x1.y = tf32r(gelu_exact((x1.y - mu) * inv * gg1.y + bb1.y));
    x1.z = tf32r(gelu_exact((x1.z - mu) * inv * gg1.z + bb1.z));
    x1.w = tf32r(gelu_exact((x1.w - mu) * inv * gg1.w + bb1.w));
    hp[lane * 2] = x0; hp[lane * 2 + 1] = x1;
}

// ---------- 6) flash attention on tensor cores, 3xTF32 ----------
__global__ __launch_bounds__(256) void flash3_kernel(
    const float* __restrict__ Q, const float* __restrict__ KV,
    float* __restrict__ Out3, int Sq, int Skv)
{
    extern __shared__ float fs[];
    float* Q3  = fs;
    float* K3  = fs + FL_K3;
    float* V3T = fs + FL_V3;
    float* P3  = fs + FL_P3;
    __shared__ float sred[2][64], ssum[2][64], m_s[64], l_s[64];

    const int b = blockIdx.z, h = blockIdx.y, q0 = blockIdx.x * 64;
    const int tid = threadIdx.x;
    const int w = tid >> 5, lane = tid & 31;
    const int g = lane >> 2, q = lane & 3;
    const int wm = w & 3, wn = w >> 2;
    const int mrow = wm * 16;
    const int r0 = mrow + g, r1 = r0 + 8;
    const float scale = 0.17677669529663687f;

    if (tid < 64) { m_s[tid] = -INFINITY; l_s[tid] = 0.f; }

    #pragma unroll
    for (int i = 0; i < 2; i++) {
        int e = tid + i * 256;
        int r = e >> 3, c4 = e & 7;
        float4 qv = *(const float4*)(Q + (size_t)(b * Sq + q0 + r) * DM + h * DH + c4 * 4);
        triA(&Q3[r * QS + 3 * (c4 * 4 + 0)], qv.x * scale);
        triA(&Q3[r * QS + 3 * (c4 * 4 + 1)], qv.y * scale);
        triA(&Q3[r * QS + 3 * (c4 * 4 + 2)], qv.z * scale);
        triA(&Q3[r * QS + 3 * (c4 * 4 + 3)], qv.w * scale);
    }
    float o[2][4];
    #pragma unroll
    for (int nf = 0; nf < 2; nf++) { o[nf][0]=o[nf][1]=o[nf][2]=o[nf][3]=0.f; }
    __syncthreads();

    for (int kv0 = 0; kv0 < Skv; kv0 += 64) {
        #pragma unroll
        for (int i = 0; i < 2; i++) {
            int e = tid + i * 256;
            int r = e >> 3, c4 = e & 7;
            const float* base = KV + (size_t)(b * Skv + kv0 + r) * 256 + h * DH + c4 * 4;
            float4 kv4 = *(const float4*)base;
            triB(&K3[r * KS + 3 * (c4 * 4 + 0)], kv4.x);
            triB(&K3[r * KS + 3 * (c4 * 4 + 1)], kv4.y);
            triB(&K3[r * KS + 3 * (c4 * 4 + 2)], kv4.z);
            triB(&K3[r * KS + 3 * (c4 * 4 + 3)], kv4.w);
            float4 vv = *(const float4*)(base + 128);
            triB(&V3T[(c4 * 4 + 0) * VS + 3 * r], vv.x);
            triB(&V3T[(c4 * 4 + 1) * VS + 3 * r], vv.y);
            triB(&V3T[(c4 * 4 + 2) * VS + 3 * r], vv.z);
            triB(&V3T[(c4 * 4 + 3) * VS + 3 * r], vv.w);
        }
        __syncthreads();

        float s[4][4];
        #pragma unroll
        for (int nf = 0; nf < 4; nf++) { s[nf][0]=s[nf][1]=s[nf][2]=s[nf][3]=0.f; }
        #pragma unroll
        for (int ks = 0; ks < 12; ks++) {
            int kp = ks * 8;
            unsigned a0 = __float_as_uint(Q3[r0 * QS + kp + q]);
            unsigned a1 = __float_as_uint(Q3[r1 * QS + kp + q]);
            unsigned a2 = __float_as_uint(Q3[r0 * QS + kp + q + 4]);
            unsigned a3 = __float_as_uint(Q3[r1 * QS + kp + q + 4]);
            #pragma unroll
            for (int nf = 0; nf < 4; nf++) {
                int nb = wn * 32 + nf * 8;
                unsigned b0 = __float_as_uint(K3[(nb + g) * KS + kp + q]);
                unsigned b1 = __float_as_uint(K3[(nb + g) * KS + kp + q + 4]);
                mma_tf32(s[nf], a0, a1, a2, a3, b0, b1);
            }
        }
        float mx0 = -INFINITY, mx1 = -INFINITY;
        #pragma unroll
        for (int nf = 0; nf < 4; nf++) {
            mx0 = fmaxf(mx0, fmaxf(s[nf][0], s[nf][1]));
            mx1 = fmaxf(mx1, fmaxf(s[nf][2], s[nf][3]));
        }
        mx0 = fmaxf(mx0, __shfl_xor_sync(0xffffffffu, mx0, 1));
        mx0 = fmaxf(mx0, __shfl_xor_sync(0xffffffffu, mx0, 2));
        mx1 = fmaxf(mx1, __shfl_xor_sync(0xffffffffu, mx1, 1));
        mx1 = fmaxf(mx1, __shfl_xor_sync(0xffffffffu, mx1, 2));
        if (q == 0) { sred[wn][r0] = mx0; sred[wn][r1] = mx1; }
        __syncthreads();

        float mold0 = m_s[r0], mold1 = m_s[r1];
        float mnew0 = fmaxf(mold0, fmaxf(sred[0][r0], sred[1][r0]));
        float mnew1 = fmaxf(mold1, fmaxf(sred[0][r1], sred[1][r1]));
        float corr0 = expf(mold0 - mnew0);
        float corr1 = expf(mold1 - mnew1);
        float ps0 = 0.f, ps1 = 0.f;
        float p[4][4];
        #pragma unroll
        for (int nf = 0; nf < 4; nf++) {
            p[nf][0] = expf(s[nf][0] - mnew0);
            p[nf][1] = expf(s[nf][1] - mnew0);
            p[nf][2] = expf(s[nf][2] - mnew1);
            p[nf][3] = expf(s[nf][3] - mnew1);
            ps0 += p[nf][0] + p[nf][1];
            ps1 += p[nf][2] + p[nf][3];
        }
        ps0 += __shfl_xor_sync(0xffffffffu, ps0, 1);
        ps0 += __shfl_xor_sync(0xffffffffu, ps0, 2);
        ps1 += __shfl_xor_sync(0xffffffffu, ps1, 1);
        ps1 += __shfl_xor_sync(0xffffffffu, ps1, 2);
        if (q == 0) { ssum[wn][r0] = ps0; ssum[wn][r1] = ps1; }
        #pragma unroll
        for (int nf = 0; nf < 4; nf++) {
            int c = wn * 32 + nf * 8 + 2 * q;
            triA(&P3[r0 * PS + 3 * c],       p[nf][0]);
            triA(&P3[r0 * PS + 3 * (c + 1)], p[nf][1]);
            triA(&P3[r1 * PS + 3 * c],       p[nf][2]);
            triA(&P3[r1 * PS + 3 * (c + 1)], p[nf][3]);
        }
        __syncthreads();

        if (wn == 0 && q == 0) {
            l_s[r0] = l_s[r0] * corr0 + ssum[0][r0] + ssum[1][r0];
            l_s[r1] = l_s[r1] * corr1 + ssum[0][r1] + ssum[1][r1];
            m_s[r0] = mnew0; m_s[r1] = mnew1;
        }
        #pragma unroll
        for (int nf = 0; nf < 2; nf++) {
            o[nf][0] *= corr0; o[nf][1] *= corr0;
            o[nf][2] *= corr1; o[nf][3] *= corr1;
        }
        #pragma unroll
        for (int ks = 0; ks < 24; ks++) {
            int kp = ks * 8;
            unsigned a0 = __float_as_uint(P3[r0 * PS + kp + q]);
            unsigned a1 = __float_as_uint(P3[r1 * PS + kp + q]);
            unsigned a2 = __float_as_uint(P3[r0 * PS + kp + q + 4]);
            unsigned a3 = __float_as_uint(P3[r1 * PS + kp + q + 4]);
            #pragma unroll
            for (int nf = 0; nf < 2; nf++) {
                int nb = wn * 16 + nf * 8;
                unsigned b0 = __float_as_uint(V3T[(nb + g) * VS + kp + q]);
                unsigned b1 = __float_as_uint(V3T[(nb + g) * VS + kp + q + 4]);
                mma_tf32(o[nf], a0, a1, a2, a3, b0, b1);
            }
        }
        __syncthreads();
    }

    float inv0 = 1.0f / l_s[r0];
    float inv1 = 1.0f / l_s[r1];
    #pragma unroll
    for (int nf = 0; nf < 2; nf++) {
        int c = wn * 16 + nf * 8 + 2 * q;
        int col = h * DH + c;
        triA(&Out3[(size_t)(b * Sq + q0 + r0) * 384 + 3 * col],       o[nf][0] * inv0);
        triA(&Out3[(size_t)(b * Sq + q0 + r0) * 384 + 3 * (col + 1)], o[nf][1] * inv0);
        triA(&Out3[(size_t)(b * Sq + q0 + r1) * 384 + 3 * col],       o[nf][2] * inv1);
        triA(&Out3[(size_t)(b * Sq + q0 + r1) * 384 + 3 * (col + 1)], o[nf][3] * inv1);
    }
}

// ---------- 7) residual add + layernorm -> plain + tripled ----------
__global__ __launch_bounds__(128) void ln_res_kernel(
    float* __restrict__ out, float* __restrict__ out3,
    const float* __restrict__ a, const float* __restrict__ res,
    const float* __restrict__ g, const float* __restrict__ be)
{
    __shared__ float sh1[4], sh2[4];
    const int row = blockIdx.x, t = threadIdx.x;
    const int w = t >> 5, lane = t & 31;
    float x = a[(size_t)row * DM + t] + res[(size_t)row * DM + t];
    float s = x;
    #pragma unroll
    for (int o = 16; o > 0; o >>= 1) s += __shfl_xor_sync(0xffffffffu, s, o);
    if (lane == 0) sh1[w] = s;
    __syncthreads();
    float mu = (sh1[0] + sh1[1] + sh1[2] + sh1[3]) * (1.0f / 128.0f);
    float d = x - mu;
    float q = d * d;
    #pragma unroll
    for (int o = 16; o > 0; o >>= 1) q += __shfl_xor_sync(0xffffffffu, q, o);
    if (lane == 0) sh2[w] = q;
    __syncthreads();
    float var = (sh2[0] + sh2[1] + sh2[2] + sh2[3]) * (1.0f / 128.0f);
    float v = d * rsqrtf(var + LN_EPS) * g[t] + be[t];
    out[(size_t)row * DM + t] = v;
    triA(&out3[(size_t)row * 384 + 3 * t], v);
}

// ---------- host ----------
extern "C" void kernel_launch(void* const* d_in, const int* in_sizes, int n_in,
                              void* d_out, int out_size)
{
    (void)in_sizes; (void)n_in; (void)out_size;
    const float* pts     = (const float*)d_in[0];
    const float* feat_w  = (const float*)d_in[2];
    const float* feat_b  = (const float*)d_in[3];
    const float* mlp_w1  = (const float*)d_in[4];
    const float* mlp_b1  = (const float*)d_in[5];
    const float* mlp_g1  = (const float*)d_in[6];
    const float* mlp_be1 = (const float*)d_in[7];
    const float* mlp_w2  = (const float*)d_in[8];
    const float* mlp_b2  = (const float*)d_in[9];
    const float* mlp_g2  = (const float*)d_in[10];
    const float* mlp_be2 = (const float*)d_in[11];
    const float* mlp_w3  = (const float*)d_in[12];
    const float* mlp_b3  = (const float*)d_in[13];
    const float* blk_in_w = (const float*)d_in[14];
    const float* blk_in_b = (const float*)d_in[15];
    const float* blk_ow   = (const float*)d_in[16];
    const float* blk_ob   = (const float*)d_in[17];
    const float* blk_g1   = (const float*)d_in[18];
    const float* blk_be1  = (const float*)d_in[19];
    const float* blk_g2   = (const float*)d_in[20];
    const float* blk_be2  = (const float*)d_in[21];
    const float* blk_f1w  = (const float*)d_in[22];
    const float* blk_f1b  = (const float*)d_in[23];
    const float* blk_f2w  = (const float*)d_in[24];
    const float* blk_f2b  = (const float*)d_in[25];
    const float* k_w = (const float*)d_in[26];
    const float* k_b = (const float*)d_in[27];
    const float* v_w = (const float*)d_in[28];
    const float* v_b = (const float*)d_in[29];
    float* out = (float*)d_out;

    float *gfeattp, *gfeat3p, *localp, *local3p, *xp, *x3p, *x2p, *x23p;
    float *qp, *att3p, *tmpp, *kvp, *ff3p, *big1p, *big2p;
    float *w1pp, *w2pp, *w3pp, *inw3p, *ow3p, *f1w3p, *f2w3p, *kvw3p;
    cudaGetSymbolAddress((void**)&gfeattp, g_gfeat_t);
    cudaGetSymbolAddress((void**)&gfeat3p, g_gfeat3);
    cudaGetSymbolAddress((void**)&localp,  g_local);
    cudaGetSymbolAddress((void**)&local3p, g_local3);
    cudaGetSymbolAddress((void**)&xp,      g_x);
    cudaGetSymbolAddress((void**)&x3p,     g_x3);
    cudaGetSymbolAddress((void**)&x2p,     g_x2);
    cudaGetSymbolAddress((void**)&x23p,    g_x23);
    cudaGetSymbolAddress((void**)&qp,      g_q);
    cudaGetSymbolAddress((void**)&att3p,   g_att3);
    cudaGetSymbolAddress((void**)&tmpp,    g_tmp);
    cudaGetSymbolAddress((void**)&kvp,     g_kv);
    cudaGetSymbolAddress((void**)&ff3p,    g_ff3);
    cudaGetSymbolAddress((void**)&big1p,   g_big1);
    cudaGetSymbolAddress((void**)&big2p,   g_big2);
    cudaGetSymbolAddress((void**)&w1pp,    g_w1p);
    cudaGetSymbolAddress((void**)&w2pp,    g_w2p);
    cudaGetSymbolAddress((void**)&w3pp,    g_w3p);
    cudaGetSymbolAddress((void**)&inw3p,   g_inw3);
    cudaGetSymbolAddress((void**)&ow3p,    g_ow3);
    cudaGetSymbolAddress((void**)&f1w3p,   g_f1w3);
    cudaGetSymbolAddress((void**)&f2w3p,   g_f2w3);
    cudaGetSymbolAddress((void**)&kvw3p,   g_kvw3);

    cudaFuncSetAttribute(gemm_big2_kernel<1,0>, cudaFuncAttributeMaxDynamicSharedMemorySize, SM_BIG);
    cudaFuncSetAttribute(gemm_big2_kernel<0,0>, cudaFuncAttributeMaxDynamicSharedMemorySize, SM_BIG);
    cudaFuncSetAttribute(gemm_big2_kernel<0,1>, cudaFuncAttributeMaxDynamicSharedMemorySize, SM_BIG);
    cudaFuncSetAttribute(gemm_big2_kernel<0,2>, cudaFuncAttributeMaxDynamicSharedMemorySize, SM_BIG);
    cudaFuncSetAttribute(flash3_kernel, cudaFuncAttributeMaxDynamicSharedMemorySize, FL_SMEM);

    gfeat_kernel<<<GFROWS / 128, 128>>>(pts, feat_w, feat_b);
    wprep_kernel<<<544, 256>>>(mlp_w1, mlp_w2, mlp_w3);
    wprep2_kernel<<<3200, 256>>>(blk_in_w, blk_ow, blk_f1w, blk_f2w, k_w, v_w);
    fps_kernel<<<BB, 512>>>(pts);
    bq_kernel<<<(BB * NS) / 8, 256>>>(pts);

    gemm_big2_kernel<1,0><<<dim3(2, GMROWS / 128), 256, SM_BIG>>>(
        gfeattp, w1pp, mlp_b1, big1p, nullptr, 256, 160, pts);
    ln_big_kernel<<<GMROWS / 8, 256>>>(big1p, mlp_g1, mlp_be1);
    gemm_big2_kernel<0,0><<<dim3(2, GMROWS / 128), 256, SM_BIG>>>(
        big1p, w2pp, mlp_b2, big2p, nullptr, 256, 256, nullptr);
    ln_big_kernel<<<GMROWS / 8, 256>>>(big2p, mlp_g2, mlp_be2);
    gemm_big2_kernel<0,2><<<dim3(1, GMROWS / 128), 256, SM_BIG>>>(
        big2p, w3pp, mlp_b3, localp, local3p, 128, 256, nullptr);

    for (int i = 0; i < 4; i++) {
        const float* xcur3 = (i == 0) ? local3p : x3p;
        const float* xcurp = (i == 0) ? localp  : xp;
        const float* kv3   = (i < 2) ? gfeat3p : xcur3;
        int Skv = (i < 2) ? NPTS : NS;
        int Mkv = BB * Skv;
        const float* wq3 = inw3p + (size_t)i * 384 * 384;
        const float* bq  = blk_in_b + (size_t)i * 384;

        gemm_big2_kernel<0,0><<<dim3(1, SQROWS / 128), 256, SM_BIG>>>(
            xcur3, wq3, bq, qp, nullptr, 128, 384, nullptr);
        gemm_big2_kernel<0,0><<<dim3(2, Mkv / 128), 256, SM_BIG>>>(
            kv3, wq3 + 128 * 384, bq + 128, kvp, nullptr, 256, 384, nullptr);
        flash3_kernel<<<dim3(NS / 64, NH, BB), 256, FL_SMEM>>>(qp, kvp, att3p, NS, Skv);
        gemm_big2_kernel<0,0><<<dim3(1, SQROWS / 128), 256, SM_BIG>>>(
            att3p, ow3p + (size_t)i * 128 * 384, blk_ob + (size_t)i * 128,
            tmpp, nullptr, 128, 384, nullptr);
        ln_res_kernel<<<SQROWS, 128>>>(x2p, x23p, tmpp, xcurp,
                                       blk_g1 + (size_t)i * 128, blk_be1 + (size_t)i * 128);
        gemm_big2_kernel<0,1><<<dim3(4, SQROWS / 128), 256, SM_BIG>>>(
            x23p, f1w3p + (size_t)i * 512 * 384, blk_f1b + (size_t)i * 512,
            ff3p, nullptr, 512, 384, nullptr);
        gemm_big2_kernel<0,0><<<dim3(1, SQROWS / 128), 256, SM_BIG>>>(
            ff3p, f2w3p + (size_t)i * 128 * 1536, blk_f2b + (size_t)i * 128,
            tmpp, nullptr, 128, 1536, nullptr);
        ln_res_kernel<<<SQROWS, 128>>>(xp, x3p, tmpp, x2p,
                                       blk_g2 + (size_t)i * 128, blk_be2 + (size_t)i * 128);
    }

    gemm_big2_kernel<0,0><<<dim3(1, SQROWS / 128), 256, SM_BIG>>>(
        x3p, kvw3p, k_b, out, nullptr, 128, 384, nullptr);
    gemm_big2_kernel<0,0><<<dim3(1, SQROWS / 128), 256, SM_BIG>>>(
        x3p, kvw3p + 128 * 384, v_b, out + (size_t)SQROWS * 128, nullptr, 128, 384, nullptr);
}